// round 1
// baseline (speedup 1.0000x reference)
#include <cuda_runtime.h>
#include <math.h>

#define Bc 4
#define Sc 1024
#define Dc 1024
#define NHc 16
#define DHc 64
#define FFc 4096
#define NEc 8
#define Tc (Bc*Sc)
#define BHc (Bc*NHc)

// ---------------- scratch (static device memory, allocation-free) ----------------
__device__ float g_pe[Sc*Dc];
__device__ float g_qkv[(size_t)Tc*3*Dc];
__device__ float g_r[Sc*Dc];
__device__ float g_sc[(size_t)BHc*Sc*Sc];   // ac scores, then probs (in place)
__device__ float g_bd[(size_t)BHc*Sc*Sc];   // raw bd term (pre rel-shift)
__device__ float g_ctx[(size_t)Tc*Dc];
__device__ float g_ao[(size_t)Tc*Dc];
__device__ float g_h1[(size_t)Tc*Dc];
__device__ float g_ffh[(size_t)Tc*FFc];     // FF hidden, reused as MoE hidden
__device__ float g_ff[(size_t)Tc*Dc];
__device__ float g_h2[(size_t)Tc*Dc];
__device__ float g_moe[(size_t)Tc*Dc];
__device__ float g_h3[(size_t)Tc*Dc];
__device__ float g_gate[Tc];
__device__ int   g_cnt[NEc];
__device__ int   g_idx[NEc*Tc];

// ---------------- positional embedding ----------------
__global__ void pe_kernel(float* __restrict__ pe) {
    int i = blockIdx.x;                       // row, pos = S-1-i
    float pos = (float)(Sc - 1 - i);
    #pragma unroll
    for (int l = 0; l < 4; l++) {
        int c = threadIdx.x + l * 256;
        int j = (c < Dc/2) ? c : (c - Dc/2);
        float invf = expf(-logf(10000.f) * ((float)(2*j) / (float)Dc));
        float a = pos * invf;
        pe[(size_t)i*Dc + c] = (c < Dc/2) ? sinf(a) : cosf(a);
    }
}

// ---------------- generic SGEMM: C[M,N] = A[M,K] @ B[K,N] ----------------
// EPI: 0=none, 1=+bias, 2=relu(+bias), 3=(+bias)*rowScale[row]
// gather: optional row index list (A rows and C rows both remapped through it)
// cntPtr: optional device row count (rows >= *cntPtr skipped)
template<int EPI>
__global__ __launch_bounds__(256)
void sgemm_k(const float* __restrict__ A, const float* __restrict__ Bm,
             float* __restrict__ C, int M, int N, int K,
             const float* __restrict__ bias, const float* __restrict__ rowScale,
             const int* __restrict__ gather, const int* __restrict__ cntPtr)
{
    int limit = cntPtr ? cntPtr[0] : M;
    int m0 = blockIdx.y * 128;
    if (m0 >= limit) return;
    int n0 = blockIdx.x * 128;

    __shared__ float As[8][128];
    __shared__ float Bs[8][128];

    int tid = threadIdx.x;
    int arow_l = tid >> 1;              // 0..127
    int aseg   = (tid & 1) * 4;         // k offset 0 or 4
    int gr = m0 + arow_l;
    long long arow = -1;
    if (gr < limit) arow = gather ? gather[gr] : gr;

    int brow = tid >> 5;                // 0..7
    int bcol = (tid & 31) * 4;

    int tm = tid >> 4, tn = tid & 15;

    float acc[8][8];
    #pragma unroll
    for (int i = 0; i < 8; i++)
        #pragma unroll
        for (int j = 0; j < 8; j++) acc[i][j] = 0.f;

    for (int k0 = 0; k0 < K; k0 += 8) {
        float4 av = make_float4(0.f, 0.f, 0.f, 0.f);
        if (arow >= 0) av = *(const float4*)(A + (size_t)arow * K + k0 + aseg);
        float4 bv = *(const float4*)(Bm + (size_t)(k0 + brow) * N + n0 + bcol);
        __syncthreads();
        As[aseg+0][arow_l] = av.x; As[aseg+1][arow_l] = av.y;
        As[aseg+2][arow_l] = av.z; As[aseg+3][arow_l] = av.w;
        *(float4*)(&Bs[brow][bcol]) = bv;
        __syncthreads();
        #pragma unroll
        for (int kk = 0; kk < 8; kk++) {
            float ra[8], rb[8];
            *(float4*)(ra)   = *(const float4*)(&As[kk][tm*8]);
            *(float4*)(ra+4) = *(const float4*)(&As[kk][tm*8+4]);
            *(float4*)(rb)   = *(const float4*)(&Bs[kk][tn*8]);
            *(float4*)(rb+4) = *(const float4*)(&Bs[kk][tn*8+4]);
            #pragma unroll
            for (int i = 0; i < 8; i++)
                #pragma unroll
                for (int j = 0; j < 8; j++)
                    acc[i][j] += ra[i] * rb[j];
        }
    }

    #pragma unroll
    for (int i = 0; i < 8; i++) {
        int grI = m0 + tm*8 + i;
        if (grI >= limit) continue;
        int crow = gather ? gather[grI] : grI;
        float rs = 1.f;
        if (EPI == 3) rs = rowScale[crow];
        #pragma unroll
        for (int j = 0; j < 8; j += 4) {
            int col = n0 + tn*8 + j;
            float4 v;
            v.x = acc[i][j+0]; v.y = acc[i][j+1]; v.z = acc[i][j+2]; v.w = acc[i][j+3];
            if (EPI >= 1) {
                v.x += bias[col+0]; v.y += bias[col+1]; v.z += bias[col+2]; v.w += bias[col+3];
            }
            if (EPI == 2) {
                v.x = fmaxf(v.x, 0.f); v.y = fmaxf(v.y, 0.f);
                v.z = fmaxf(v.z, 0.f); v.w = fmaxf(v.w, 0.f);
            }
            if (EPI == 3) { v.x *= rs; v.y *= rs; v.z *= rs; v.w *= rs; }
            *(float4*)(C + (size_t)crow * N + col) = v;
        }
    }
}

// ---------------- attention QK^T-style scores (64x64 tile per block) ----------------
// isBD=0: out[bh,q,k] = sum_d (q[b,q,h,d]+bias[h,d]) * k[b,k,h,d]
// isBD=1: out[bh,q,j] = sum_d (q[b,q,h,d]+bias[h,d]) * r[j,h,d]
__global__ __launch_bounds__(256)
void attn_qk(const float* __restrict__ qkv, const float* __restrict__ bias2,
             const float* __restrict__ rmat, int isBD, float* __restrict__ out)
{
    int kt = blockIdx.x, qt = blockIdx.y, bh = blockIdx.z;
    if (!isBD && kt > qt) return;
    if (isBD && (qt*64 + 63 + kt*64 + 63) < (Sc - 1)) return;
    int b = bh >> 4, h = bh & 15;
    int q0 = qt * 64, k0 = kt * 64;

    __shared__ float Qs[64][68];
    __shared__ float Ks[64][68];

    int tid = threadIdx.x;
    #pragma unroll
    for (int l = 0; l < 4; l++) {
        int slot = tid * 4 + l;
        int row  = slot >> 4;
        int dseg = (slot & 15) * 4;
        float4 qv = *(const float4*)(qkv + ((size_t)(b*Sc + q0 + row))*3072 + h*64 + dseg);
        float4 ub = *(const float4*)(bias2 + h*64 + dseg);
        qv.x += ub.x; qv.y += ub.y; qv.z += ub.z; qv.w += ub.w;
        *(float4*)(&Qs[row][dseg]) = qv;
        float4 kv;
        if (isBD) kv = *(const float4*)(rmat + ((size_t)(k0 + row))*Dc + h*64 + dseg);
        else      kv = *(const float4*)(qkv + ((size_t)(b*Sc + k0 + row))*3072 + 1024 + h*64 + dseg);
        *(float4*)(&Ks[row][dseg]) = kv;
    }
    __syncthreads();

    int tm = tid >> 4, tn = tid & 15;
    float acc[4][4] = {};
    #pragma unroll 8
    for (int kk = 0; kk < 64; kk++) {
        float ra[4], rb[4];
        #pragma unroll
        for (int i = 0; i < 4; i++) ra[i] = Qs[tm*4+i][kk];
        #pragma unroll
        for (int j = 0; j < 4; j++) rb[j] = Ks[tn*4+j][kk];
        #pragma unroll
        for (int i = 0; i < 4; i++)
            #pragma unroll
            for (int j = 0; j < 4; j++)
                acc[i][j] += ra[i] * rb[j];
    }

    #pragma unroll
    for (int i = 0; i < 4; i++) {
        int q = q0 + tm*4 + i;
        float4 v; v.x = acc[i][0]; v.y = acc[i][1]; v.z = acc[i][2]; v.w = acc[i][3];
        *(float4*)(out + ((size_t)bh*Sc + q)*Sc + k0 + tn*4) = v;
    }
}

// ---------------- assemble scores + rel_shift + causal softmax (in place on sc) ----------------
__global__ __launch_bounds__(256)
void softmax_k(float* __restrict__ sc, const float* __restrict__ bd)
{
    int q = blockIdx.x, bh = blockIdx.y;
    size_t base = ((size_t)bh*Sc + q)*Sc;
    int tid = threadIdx.x;
    __shared__ float red[256];

    float v[4];
    float mx = -1e30f;
    #pragma unroll
    for (int l = 0; l < 4; l++) {
        int k = tid + l*256;
        float val = -1e30f;
        if (k <= q) {
            int j = k - q + Sc - 1;                 // rel_shift index
            val = (sc[base + k] + bd[base - q + j /* same row, col j */ - k + k]) * 0.125f;
            // note: bd row base identical to sc row base; index col j:
            val = (sc[base + k] + bd[((size_t)bh*Sc + q)*Sc + j]) * 0.125f;
        }
        v[l] = val;
        mx = fmaxf(mx, val);
    }
    red[tid] = mx; __syncthreads();
    for (int s = 128; s > 0; s >>= 1) { if (tid < s) red[tid] = fmaxf(red[tid], red[tid+s]); __syncthreads(); }
    float m = red[0]; __syncthreads();

    float sum = 0.f;
    #pragma unroll
    for (int l = 0; l < 4; l++) {
        int k = tid + l*256;
        float e = (k <= q) ? expf(v[l] - m) : 0.f;
        v[l] = e; sum += e;
    }
    red[tid] = sum; __syncthreads();
    for (int s = 128; s > 0; s >>= 1) { if (tid < s) red[tid] += red[tid+s]; __syncthreads(); }
    float inv = 1.f / red[0];

    #pragma unroll
    for (int l = 0; l < 4; l++) {
        int k = tid + l*256;
        sc[base + k] = v[l] * inv;
    }
}

// ---------------- ctx = probs @ V (64 q-rows x 64 d-cols per block) ----------------
__global__ __launch_bounds__(256)
void attn_av(const float* __restrict__ probs, const float* __restrict__ qkv,
             float* __restrict__ ctx)
{
    int qt = blockIdx.x, bh = blockIdx.y;
    int b = bh >> 4, h = bh & 15;
    int q0 = qt * 64;

    __shared__ float Ps[64][36];
    __shared__ float Vs[32][68];

    int tid = threadIdx.x;
    int tm = tid >> 4, tn = tid & 15;
    float acc[4][4] = {};
    int kmax = (qt + 1) * 64;           // probs zero beyond each row's q

    for (int k0 = 0; k0 < kmax; k0 += 32) {
        __syncthreads();
        #pragma unroll
        for (int l = 0; l < 2; l++) {
            int slot = tid * 2 + l;     // 512 float4 slots: 64 rows x 8 segs
            int row  = slot >> 3;
            int cseg = (slot & 7) * 4;
            float4 pv = *(const float4*)(probs + ((size_t)bh*Sc + q0 + row)*Sc + k0 + cseg);
            *(float4*)(&Ps[row][cseg]) = pv;
            int vrow = slot >> 4;       // 32 rows x 16 segs
            int vseg = (slot & 15) * 4;
            float4 vv = *(const float4*)(qkv + ((size_t)(b*Sc + k0 + vrow))*3072 + 2048 + h*64 + vseg);
            *(float4*)(&Vs[vrow][vseg]) = vv;
        }
        __syncthreads();
        #pragma unroll 4
        for (int kk = 0; kk < 32; kk++) {
            float ra[4], rb[4];
            #pragma unroll
            for (int i = 0; i < 4; i++) ra[i] = Ps[tm*4+i][kk];
            #pragma unroll
            for (int j = 0; j < 4; j++) rb[j] = Vs[kk][tn*4+j];
            #pragma unroll
            for (int i = 0; i < 4; i++)
                #pragma unroll
                for (int j = 0; j < 4; j++)
                    acc[i][j] += ra[i] * rb[j];
        }
    }

    #pragma unroll
    for (int i = 0; i < 4; i++) {
        float4 v; v.x = acc[i][0]; v.y = acc[i][1]; v.z = acc[i][2]; v.w = acc[i][3];
        *(float4*)(ctx + ((size_t)(b*Sc + q0 + tm*4 + i))*Dc + h*64 + tn*4) = v;
    }
}

// ---------------- residual + layernorm: out = LN(x + y) ----------------
__global__ __launch_bounds__(256)
void rln_k(const float* __restrict__ x, const float* __restrict__ y,
           const float* __restrict__ g, const float* __restrict__ bta,
           float* __restrict__ out)
{
    int row = blockIdx.x;
    int tid = threadIdx.x;
    __shared__ float red[256];
    float v[4];
    float s = 0.f, ss = 0.f;
    #pragma unroll
    for (int l = 0; l < 4; l++) {
        size_t idx = (size_t)row*Dc + tid + l*256;
        float val = x[idx] + y[idx];
        v[l] = val; s += val; ss += val*val;
    }
    red[tid] = s; __syncthreads();
    for (int st = 128; st > 0; st >>= 1) { if (tid < st) red[tid] += red[tid+st]; __syncthreads(); }
    float mean = red[0] * (1.f/Dc); __syncthreads();
    red[tid] = ss; __syncthreads();
    for (int st = 128; st > 0; st >>= 1) { if (tid < st) red[tid] += red[tid+st]; __syncthreads(); }
    float var = red[0] * (1.f/Dc) - mean*mean;
    float inv = rsqrtf(var + 1e-5f);
    #pragma unroll
    for (int l = 0; l < 4; l++) {
        int c = tid + l*256;
        out[(size_t)row*Dc + c] = (v[l] - mean) * inv * g[c] + bta[c];
    }
}

// ---------------- router: top-1 softmax gate + expert compaction ----------------
__global__ void zero_cnt(int* cnt) { if (threadIdx.x < NEc) cnt[threadIdx.x] = 0; }

__global__ __launch_bounds__(256)
void router_k(const float* __restrict__ h2, const float* __restrict__ Wg,
              float* __restrict__ gate, int* __restrict__ cnt, int* __restrict__ idxlist)
{
    int warp = (blockIdx.x * blockDim.x + threadIdx.x) >> 5;
    int lane = threadIdx.x & 31;
    if (warp >= Tc) return;
    const float* hrow = h2 + (size_t)warp * Dc;
    float logit[NEc];
    #pragma unroll
    for (int e = 0; e < NEc; e++) {
        float p = 0.f;
        for (int d = lane; d < Dc; d += 32) p += hrow[d] * Wg[d*NEc + e];
        #pragma unroll
        for (int off = 16; off > 0; off >>= 1) p += __shfl_xor_sync(0xFFFFFFFFu, p, off);
        logit[e] = p;
    }
    float m = logit[0]; int am = 0;
    #pragma unroll
    for (int e = 1; e < NEc; e++) if (logit[e] > m) { m = logit[e]; am = e; }
    float sum = 0.f;
    #pragma unroll
    for (int e = 0; e < NEc; e++) sum += expf(logit[e] - m);
    if (lane == 0) {
        gate[warp] = 1.f / sum;                     // = max prob
        int pos = atomicAdd(&cnt[am], 1);
        idxlist[am*Tc + pos] = warp;
    }
}

// ---------------- launch ----------------
extern "C" void kernel_launch(void* const* d_in, const int* in_sizes, int n_in,
                              void* d_out, int out_size)
{
    const float* x    = (const float*)d_in[0];
    const float* Wqkv = (const float*)d_in[1];
    const float* Wo   = (const float*)d_in[2];
    const float* Wr   = (const float*)d_in[3];
    const float* u_b  = (const float*)d_in[4];
    const float* v_b  = (const float*)d_in[5];
    const float* ln1g = (const float*)d_in[6];
    const float* ln1b = (const float*)d_in[7];
    const float* Wff1 = (const float*)d_in[8];
    const float* bff1 = (const float*)d_in[9];
    const float* Wff2 = (const float*)d_in[10];
    const float* bff2 = (const float*)d_in[11];
    const float* ln2g = (const float*)d_in[12];
    const float* ln2b = (const float*)d_in[13];
    const float* Wg   = (const float*)d_in[14];
    const float* We1  = (const float*)d_in[15];
    const float* be1  = (const float*)d_in[16];
    const float* We2  = (const float*)d_in[17];
    const float* be2  = (const float*)d_in[18];
    const float* ln3g = (const float*)d_in[19];
    const float* ln3b = (const float*)d_in[20];
    const float* Wout = (const float*)d_in[21];
    float* out = (float*)d_out;

    float *pe, *qkv, *r, *sc, *bd, *ctx, *ao, *h1, *ffh, *ff, *h2, *moe, *h3, *gate;
    int *cnt, *idx;
    cudaGetSymbolAddress((void**)&pe,  g_pe);
    cudaGetSymbolAddress((void**)&qkv, g_qkv);
    cudaGetSymbolAddress((void**)&r,   g_r);
    cudaGetSymbolAddress((void**)&sc,  g_sc);
    cudaGetSymbolAddress((void**)&bd,  g_bd);
    cudaGetSymbolAddress((void**)&ctx, g_ctx);
    cudaGetSymbolAddress((void**)&ao,  g_ao);
    cudaGetSymbolAddress((void**)&h1,  g_h1);
    cudaGetSymbolAddress((void**)&ffh, g_ffh);
    cudaGetSymbolAddress((void**)&ff,  g_ff);
    cudaGetSymbolAddress((void**)&h2,  g_h2);
    cudaGetSymbolAddress((void**)&moe, g_moe);
    cudaGetSymbolAddress((void**)&h3,  g_h3);
    cudaGetSymbolAddress((void**)&gate,g_gate);
    cudaGetSymbolAddress((void**)&cnt, g_cnt);
    cudaGetSymbolAddress((void**)&idx, g_idx);

    // positional embedding + projections
    pe_kernel<<<Sc, 256>>>(pe);
    sgemm_k<0><<<dim3(3072/128, Tc/128), 256>>>(x, Wqkv, qkv, Tc, 3072, Dc, nullptr, nullptr, nullptr, nullptr);
    sgemm_k<0><<<dim3(Dc/128, Sc/128), 256>>>(pe, Wr, r, Sc, Dc, Dc, nullptr, nullptr, nullptr, nullptr);

    // attention
    attn_qk<<<dim3(16, 16, BHc), 256>>>(qkv, u_b, r, 0, sc);
    attn_qk<<<dim3(16, 16, BHc), 256>>>(qkv, v_b, r, 1, bd);
    softmax_k<<<dim3(Sc, BHc), 256>>>(sc, bd);
    attn_av<<<dim3(16, BHc), 256>>>(sc, qkv, ctx);
    sgemm_k<0><<<dim3(Dc/128, Tc/128), 256>>>(ctx, Wo, ao, Tc, Dc, Dc, nullptr, nullptr, nullptr, nullptr);
    rln_k<<<Tc, 256>>>(x, ao, ln1g, ln1b, h1);

    // FFN
    sgemm_k<2><<<dim3(FFc/128, Tc/128), 256>>>(h1, Wff1, ffh, Tc, FFc, Dc, bff1, nullptr, nullptr, nullptr);
    sgemm_k<1><<<dim3(Dc/128, Tc/128), 256>>>(ffh, Wff2, ff, Tc, Dc, FFc, bff2, nullptr, nullptr, nullptr);
    rln_k<<<Tc, 256>>>(h1, ff, ln2g, ln2b, h2);

    // MoE: router + per-expert gathered GEMMs (top-1 sparse)
    zero_cnt<<<1, 32>>>(cnt);
    router_k<<<Tc/8, 256>>>(h2, Wg, gate, cnt, idx);
    for (int e = 0; e < NEc; e++) {
        sgemm_k<2><<<dim3(FFc/128, Tc/128), 256>>>(
            h2, We1 + (size_t)e*Dc*FFc, ffh, Tc, FFc, Dc,
            be1 + (size_t)e*FFc, nullptr, idx + e*Tc, cnt + e);
        sgemm_k<3><<<dim3(Dc/128, Tc/128), 256>>>(
            ffh, We2 + (size_t)e*FFc*Dc, moe, Tc, Dc, FFc,
            be2 + (size_t)e*Dc, gate, idx + e*Tc, cnt + e);
    }
    rln_k<<<Tc, 256>>>(h2, moe, ln3g, ln3b, h3);

    // output projection
    sgemm_k<0><<<dim3(Dc/128, Tc/128), 256>>>(h3, Wout, out, Tc, Dc, Dc, nullptr, nullptr, nullptr, nullptr);
}

// round 3
// speedup vs baseline: 3.7282x; 3.7282x over previous
#include <cuda_runtime.h>
#include <cuda_bf16.h>
#include <math.h>
#include <stdint.h>

#define Bc 4
#define Sc 1024
#define Dc 1024
#define NHc 16
#define DHc 64
#define FFc 4096
#define NEc 8
#define Tc (Bc*Sc)
#define BHc (Bc*NHc)

// ---------------- scratch (static device memory, allocation-free) ----------------
__device__ float g_pe[Sc*Dc];
__device__ float g_qkv[(size_t)Tc*3*Dc];
__device__ float g_r[Sc*Dc];
__device__ float g_sc[(size_t)BHc*Sc*Sc];   // ac scores, then probs (in place)
__device__ float g_bd[(size_t)BHc*Sc*Sc];   // raw bd term (pre rel-shift)
__device__ float g_ctx[(size_t)Tc*Dc];
__device__ float g_ao[(size_t)Tc*Dc];
__device__ float g_h1[(size_t)Tc*Dc];
__device__ float g_ffh[(size_t)Tc*FFc];
__device__ float g_ff[(size_t)Tc*Dc];
__device__ float g_h2[(size_t)Tc*Dc];
__device__ float g_moe[(size_t)Tc*Dc];
__device__ float g_h3[(size_t)Tc*Dc];
__device__ float g_gate[Tc];
__device__ int   g_cnt[NEc];
__device__ int   g_idx[NEc*Tc];

// transposed split-bf16 weights: [N,K] layout, hi + lo
#define OFF_QKV  0
#define OFF_WR   3145728
#define OFF_WO   4194304
#define OFF_FF1  5242880
#define OFF_FF2  9437184
#define OFF_WE1  13631488
#define OFF_WE2  47185920
#define OFF_WOUT 80740352
#define WTOT     81788928
__device__ __nv_bfloat16 g_whi[WTOT];
__device__ __nv_bfloat16 g_wlo[WTOT];

// ---------------- PTX helpers ----------------
__device__ __forceinline__ uint32_t smem_u32(const void* p) {
    uint32_t a;
    asm("{ .reg .u64 t; cvta.to.shared.u64 t, %1; cvt.u32.u64 %0, t; }" : "=r"(a) : "l"(p));
    return a;
}
__device__ __forceinline__ void ldm4(uint32_t* r, uint32_t a) {
    asm volatile("ldmatrix.sync.aligned.m8n8.x4.shared.b16 {%0,%1,%2,%3}, [%4];"
        : "=r"(r[0]), "=r"(r[1]), "=r"(r[2]), "=r"(r[3]) : "r"(a));
}
__device__ __forceinline__ void mma_bf16(float* c, const uint32_t* a, uint32_t b0, uint32_t b1) {
    asm volatile("mma.sync.aligned.m16n8k16.row.col.f32.bf16.bf16.f32 "
        "{%0,%1,%2,%3}, {%4,%5,%6,%7}, {%8,%9}, {%0,%1,%2,%3};"
        : "+f"(c[0]), "+f"(c[1]), "+f"(c[2]), "+f"(c[3])
        : "r"(a[0]), "r"(a[1]), "r"(a[2]), "r"(a[3]), "r"(b0), "r"(b1));
}

// ---------------- weight transpose + fp32 -> bf16 hi/lo split ----------------
// W[K,N] -> hi/lo [N,K]
__global__ __launch_bounds__(256)
void wconv(const float* __restrict__ W, __nv_bfloat16* __restrict__ hi,
           __nv_bfloat16* __restrict__ lo, int K, int N)
{
    __shared__ float t[32][33];
    int tx = threadIdx.x & 31, ty = threadIdx.x >> 5;   // 32 x 8
    int kb = blockIdx.y * 32, nb = blockIdx.x * 32;
    #pragma unroll
    for (int j = 0; j < 4; j++)
        t[ty + j*8][tx] = W[(size_t)(kb + ty + j*8) * N + nb + tx];
    __syncthreads();
    #pragma unroll
    for (int j = 0; j < 4; j++) {
        int n = nb + ty + j*8, k = kb + tx;
        float v = t[tx][ty + j*8];
        __nv_bfloat16 h = __float2bfloat16_rn(v);
        hi[(size_t)n*K + k] = h;
        lo[(size_t)n*K + k] = __float2bfloat16_rn(v - __bfloat162float(h));
    }
}

// ---------------- HMMA split-bf16 GEMM: C[M,N] = A[M,K] @ B^T, B as [N,K] ----------------
// CTA tile 128x128, BK=32, 8 warps (warp tile 32x64), 3 MMAs per product (hi/lo split).
// EPI: 0=none 1=+bias 2=relu(+bias) 3=(+bias)*rowScale[row]
template<int EPI>
__global__ __launch_bounds__(256)
void tgemm(const float* __restrict__ A, const __nv_bfloat16* __restrict__ Bhi,
           const __nv_bfloat16* __restrict__ Blo, float* __restrict__ C,
           int M, int N, int K,
           const float* __restrict__ bias, const float* __restrict__ rowScale,
           const int* __restrict__ gather, const int* __restrict__ cntPtr)
{
    __shared__ __nv_bfloat16 AsH[128][40];
    __shared__ __nv_bfloat16 AsL[128][40];
    __shared__ __nv_bfloat16 BsH[128][40];
    __shared__ __nv_bfloat16 BsL[128][40];

    int limit = cntPtr ? cntPtr[0] : M;
    int m0 = blockIdx.y * 128;
    if (m0 >= limit) return;
    int n0 = blockIdx.x * 128;

    int tid = threadIdx.x, wid = tid >> 5, lane = tid & 31;
    int wm = (wid & 3) * 32, wn = (wid >> 2) * 64;

    // A staging: 1024 float4 slots (row 0..127, seg 0..7 covering 4 floats)
    const float* ap[4];
    int arow[4], aseg[4];
    #pragma unroll
    for (int l = 0; l < 4; l++) {
        int slot = tid + 256*l;
        arow[l] = slot >> 3; aseg[l] = slot & 7;
        int gr = m0 + arow[l];
        ap[l] = nullptr;
        if (gr < limit) {
            int sr = gather ? gather[gr] : gr;
            ap[l] = A + (size_t)sr * K + aseg[l] * 4;
        }
    }
    // B staging: 512 uint4 slots each for hi and lo (row 0..127, seg 0..3 covering 8 bf16)
    const __nv_bfloat16 *bph[2], *bpl[2];
    int brow[2], bseg[2];
    #pragma unroll
    for (int l = 0; l < 2; l++) {
        int slot = tid + 256*l;
        brow[l] = slot >> 2; bseg[l] = slot & 3;
        size_t off = (size_t)(n0 + brow[l]) * K + bseg[l] * 8;
        bph[l] = Bhi + off; bpl[l] = Blo + off;
    }

    // ldmatrix per-lane offsets
    int t4 = lane >> 3;
    int rr = (lane & 7) + (t4 & 1) * 8;
    int cc = (t4 >> 1) * 8;
    uint32_t baAH = smem_u32(AsH), baAL = smem_u32(AsL);
    uint32_t baBH = smem_u32(BsH), baBL = smem_u32(BsL);

    float acc[2][8][4];
    #pragma unroll
    for (int i = 0; i < 2; i++)
        #pragma unroll
        for (int j = 0; j < 8; j++)
            #pragma unroll
            for (int q = 0; q < 4; q++) acc[i][j][q] = 0.f;

    float4 av[4]; uint4 bvh[2], bvl[2];
    int Kc = K >> 5;

    // prologue: load chunk 0
    #pragma unroll
    for (int l = 0; l < 4; l++)
        av[l] = ap[l] ? *(const float4*)(ap[l]) : make_float4(0.f,0.f,0.f,0.f);
    #pragma unroll
    for (int l = 0; l < 2; l++) {
        bvh[l] = *(const uint4*)(bph[l]);
        bvl[l] = *(const uint4*)(bpl[l]);
    }

    for (int c = 0; c < Kc; c++) {
        // store staged regs to smem
        #pragma unroll
        for (int l = 0; l < 4; l++) {
            float4 v = av[l];
            __nv_bfloat162 h01 = __floats2bfloat162_rn(v.x, v.y);
            __nv_bfloat162 h23 = __floats2bfloat162_rn(v.z, v.w);
            float2 f01 = __bfloat1622float2(h01);
            float2 f23 = __bfloat1622float2(h23);
            __nv_bfloat162 l01 = __floats2bfloat162_rn(v.x - f01.x, v.y - f01.y);
            __nv_bfloat162 l23 = __floats2bfloat162_rn(v.z - f23.x, v.w - f23.y);
            *(uint2*)&AsH[arow[l]][aseg[l]*4] = make_uint2(*(uint32_t*)&h01, *(uint32_t*)&h23);
            *(uint2*)&AsL[arow[l]][aseg[l]*4] = make_uint2(*(uint32_t*)&l01, *(uint32_t*)&l23);
        }
        #pragma unroll
        for (int l = 0; l < 2; l++) {
            *(uint4*)&BsH[brow[l]][bseg[l]*8] = bvh[l];
            *(uint4*)&BsL[brow[l]][bseg[l]*8] = bvl[l];
        }
        __syncthreads();

        // prefetch next chunk
        if (c + 1 < Kc) {
            int ko = (c + 1) * 32;
            #pragma unroll
            for (int l = 0; l < 4; l++)
                av[l] = ap[l] ? *(const float4*)(ap[l] + ko) : make_float4(0.f,0.f,0.f,0.f);
            #pragma unroll
            for (int l = 0; l < 2; l++) {
                bvh[l] = *(const uint4*)(bph[l] + ko);
                bvl[l] = *(const uint4*)(bpl[l] + ko);
            }
        }

        // compute from smem
        #pragma unroll
        for (int k16 = 0; k16 < 32; k16 += 16) {
            uint32_t aH[2][4], aL[2][4];
            #pragma unroll
            for (int mi = 0; mi < 2; mi++) {
                uint32_t off = ((uint32_t)(wm + mi*16 + rr) * 40u + (uint32_t)(k16 + cc)) * 2u;
                ldm4(aH[mi], baAH + off);
                ldm4(aL[mi], baAL + off);
            }
            uint32_t bH[4][4], bL[4][4];
            #pragma unroll
            for (int ni = 0; ni < 4; ni++) {
                uint32_t off = ((uint32_t)(wn + ni*16 + rr) * 40u + (uint32_t)(k16 + cc)) * 2u;
                ldm4(bH[ni], baBH + off);
                ldm4(bL[ni], baBL + off);
            }
            #pragma unroll
            for (int mi = 0; mi < 2; mi++)
                #pragma unroll
                for (int ni = 0; ni < 4; ni++)
                    #pragma unroll
                    for (int h = 0; h < 2; h++) {
                        int j = ni*2 + h;
                        mma_bf16(acc[mi][j], aH[mi], bH[ni][h], bH[ni][h+2]);
                        mma_bf16(acc[mi][j], aH[mi], bL[ni][h], bL[ni][h+2]);
                        mma_bf16(acc[mi][j], aL[mi], bH[ni][h], bH[ni][h+2]);
                    }
        }
        __syncthreads();
    }

    // epilogue
    #pragma unroll
    for (int mi = 0; mi < 2; mi++) {
        #pragma unroll
        for (int half = 0; half < 2; half++) {
            int gr = m0 + wm + mi*16 + (lane >> 2) + half*8;
            if (gr >= limit) continue;
            int crow = gather ? gather[gr] : gr;
            float rs = 1.f;
            if (EPI == 3) rs = rowScale[crow];
            #pragma unroll
            for (int j = 0; j < 8; j++) {
                int col = n0 + wn + j*8 + (lane & 3)*2;
                float2 v;
                v.x = acc[mi][j][half*2 + 0];
                v.y = acc[mi][j][half*2 + 1];
                if (EPI >= 1) { v.x += bias[col]; v.y += bias[col+1]; }
                if (EPI == 2) { v.x = fmaxf(v.x, 0.f); v.y = fmaxf(v.y, 0.f); }
                if (EPI == 3) { v.x *= rs; v.y *= rs; }
                *(float2*)(C + (size_t)crow * N + col) = v;
            }
        }
    }
}

// ---------------- positional embedding ----------------
__global__ void pe_kernel(float* __restrict__ pe) {
    int i = blockIdx.x;
    float pos = (float)(Sc - 1 - i);
    #pragma unroll
    for (int l = 0; l < 4; l++) {
        int c = threadIdx.x + l * 256;
        int j = (c < Dc/2) ? c : (c - Dc/2);
        float invf = expf(-logf(10000.f) * ((float)(2*j) / (float)Dc));
        float a = pos * invf;
        pe[(size_t)i*Dc + c] = (c < Dc/2) ? sinf(a) : cosf(a);
    }
}

// ---------------- attention QK^T-style scores (64x64 tile per block) ----------------
__global__ __launch_bounds__(256)
void attn_qk(const float* __restrict__ qkv, const float* __restrict__ bias2,
             const float* __restrict__ rmat, int isBD, float* __restrict__ out)
{
    int kt = blockIdx.x, qt = blockIdx.y, bh = blockIdx.z;
    if (!isBD && kt > qt) return;
    if (isBD && (qt*64 + 63 + kt*64 + 63) < (Sc - 1)) return;
    int b = bh >> 4, h = bh & 15;
    int q0 = qt * 64, k0 = kt * 64;

    __shared__ float Qs[64][68];
    __shared__ float Ks[64][68];

    int tid = threadIdx.x;
    #pragma unroll
    for (int l = 0; l < 4; l++) {
        int slot = tid * 4 + l;
        int row  = slot >> 4;
        int dseg = (slot & 15) * 4;
        float4 qv = *(const float4*)(qkv + ((size_t)(b*Sc + q0 + row))*3072 + h*64 + dseg);
        float4 ub = *(const float4*)(bias2 + h*64 + dseg);
        qv.x += ub.x; qv.y += ub.y; qv.z += ub.z; qv.w += ub.w;
        *(float4*)(&Qs[row][dseg]) = qv;
        float4 kv;
        if (isBD) kv = *(const float4*)(rmat + ((size_t)(k0 + row))*Dc + h*64 + dseg);
        else      kv = *(const float4*)(qkv + ((size_t)(b*Sc + k0 + row))*3072 + 1024 + h*64 + dseg);
        *(float4*)(&Ks[row][dseg]) = kv;
    }
    __syncthreads();

    int tm = tid >> 4, tn = tid & 15;
    float acc[4][4] = {};
    #pragma unroll 8
    for (int kk = 0; kk < 64; kk++) {
        float ra[4], rb[4];
        #pragma unroll
        for (int i = 0; i < 4; i++) ra[i] = Qs[tm*4+i][kk];
        #pragma unroll
        for (int j = 0; j < 4; j++) rb[j] = Ks[tn*4+j][kk];
        #pragma unroll
        for (int i = 0; i < 4; i++)
            #pragma unroll
            for (int j = 0; j < 4; j++)
                acc[i][j] += ra[i] * rb[j];
    }

    #pragma unroll
    for (int i = 0; i < 4; i++) {
        int q = q0 + tm*4 + i;
        float4 v; v.x = acc[i][0]; v.y = acc[i][1]; v.z = acc[i][2]; v.w = acc[i][3];
        *(float4*)(out + ((size_t)bh*Sc + q)*Sc + k0 + tn*4) = v;
    }
}

// ---------------- rel_shift + causal softmax (in place on sc) ----------------
__global__ __launch_bounds__(256)
void softmax_k(float* __restrict__ sc, const float* __restrict__ bd)
{
    int q = blockIdx.x, bh = blockIdx.y;
    size_t base = ((size_t)bh*Sc + q)*Sc;
    int tid = threadIdx.x;
    __shared__ float red[256];

    float v[4];
    float mx = -1e30f;
    #pragma unroll
    for (int l = 0; l < 4; l++) {
        int k = tid + l*256;
        float val = -1e30f;
        if (k <= q) {
            int j = k - q + Sc - 1;
            val = (sc[base + k] + bd[base + j]) * 0.125f;
        }
        v[l] = val;
        mx = fmaxf(mx, val);
    }
    red[tid] = mx; __syncthreads();
    for (int s = 128; s > 0; s >>= 1) { if (tid < s) red[tid] = fmaxf(red[tid], red[tid+s]); __syncthreads(); }
    float m = red[0]; __syncthreads();

    float sum = 0.f;
    #pragma unroll
    for (int l = 0; l < 4; l++) {
        int k = tid + l*256;
        float e = (k <= q) ? expf(v[l] - m) : 0.f;
        v[l] = e; sum += e;
    }
    red[tid] = sum; __syncthreads();
    for (int s = 128; s > 0; s >>= 1) { if (tid < s) red[tid] += red[tid+s]; __syncthreads(); }
    float inv = 1.f / red[0];

    #pragma unroll
    for (int l = 0; l < 4; l++) {
        int k = tid + l*256;
        sc[base + k] = v[l] * inv;
    }
}

// ---------------- ctx = probs @ V ----------------
__global__ __launch_bounds__(256)
void attn_av(const float* __restrict__ probs, const float* __restrict__ qkv,
             float* __restrict__ ctx)
{
    int qt = blockIdx.x, bh = blockIdx.y;
    int b = bh >> 4, h = bh & 15;
    int q0 = qt * 64;

    __shared__ float Ps[64][36];
    __shared__ float Vs[32][68];

    int tid = threadIdx.x;
    int tm = tid >> 4, tn = tid & 15;
    float acc[4][4] = {};
    int kmax = (qt + 1) * 64;

    for (int k0 = 0; k0 < kmax; k0 += 32) {
        __syncthreads();
        #pragma unroll
        for (int l = 0; l < 2; l++) {
            int slot = tid * 2 + l;
            int row  = slot >> 3;
            int cseg = (slot & 7) * 4;
            float4 pv = *(const float4*)(probs + ((size_t)bh*Sc + q0 + row)*Sc + k0 + cseg);
            *(float4*)(&Ps[row][cseg]) = pv;
            int vrow = slot >> 4;
            int vseg = (slot & 15) * 4;
            float4 vv = *(const float4*)(qkv + ((size_t)(b*Sc + k0 + vrow))*3072 + 2048 + h*64 + vseg);
            *(float4*)(&Vs[vrow][vseg]) = vv;
        }
        __syncthreads();
        #pragma unroll 4
        for (int kk = 0; kk < 32; kk++) {
            float ra[4], rb[4];
            #pragma unroll
            for (int i = 0; i < 4; i++) ra[i] = Ps[tm*4+i][kk];
            #pragma unroll
            for (int j = 0; j < 4; j++) rb[j] = Vs[kk][tn*4+j];
            #pragma unroll
            for (int i = 0; i < 4; i++)
                #pragma unroll
                for (int j = 0; j < 4; j++)
                    acc[i][j] += ra[i] * rb[j];
        }
    }

    #pragma unroll
    for (int i = 0; i < 4; i++) {
        float4 v; v.x = acc[i][0]; v.y = acc[i][1]; v.z = acc[i][2]; v.w = acc[i][3];
        *(float4*)(ctx + ((size_t)(b*Sc + q0 + tm*4 + i))*Dc + h*64 + tn*4) = v;
    }
}

// ---------------- residual + layernorm ----------------
__global__ __launch_bounds__(256)
void rln_k(const float* __restrict__ x, const float* __restrict__ y,
           const float* __restrict__ g, const float* __restrict__ bta,
           float* __restrict__ out)
{
    int row = blockIdx.x;
    int tid = threadIdx.x;
    __shared__ float red[256];
    float v[4];
    float s = 0.f, ss = 0.f;
    #pragma unroll
    for (int l = 0; l < 4; l++) {
        size_t idx = (size_t)row*Dc + tid + l*256;
        float val = x[idx] + y[idx];
        v[l] = val; s += val; ss += val*val;
    }
    red[tid] = s; __syncthreads();
    for (int st = 128; st > 0; st >>= 1) { if (tid < st) red[tid] += red[tid+st]; __syncthreads(); }
    float mean = red[0] * (1.f/Dc); __syncthreads();
    red[tid] = ss; __syncthreads();
    for (int st = 128; st > 0; st >>= 1) { if (tid < st) red[tid] += red[tid+st]; __syncthreads(); }
    float var = red[0] * (1.f/Dc) - mean*mean;
    float inv = rsqrtf(var + 1e-5f);
    #pragma unroll
    for (int l = 0; l < 4; l++) {
        int c = tid + l*256;
        out[(size_t)row*Dc + c] = (v[l] - mean) * inv * g[c] + bta[c];
    }
}

// ---------------- router ----------------
__global__ void zero_cnt(int* cnt) { if (threadIdx.x < NEc) cnt[threadIdx.x] = 0; }

__global__ __launch_bounds__(256)
void router_k(const float* __restrict__ h2, const float* __restrict__ Wg,
              float* __restrict__ gate, int* __restrict__ cnt, int* __restrict__ idxlist)
{
    int warp = (blockIdx.x * blockDim.x + threadIdx.x) >> 5;
    int lane = threadIdx.x & 31;
    if (warp >= Tc) return;
    const float* hrow = h2 + (size_t)warp * Dc;
    float logit[NEc];
    #pragma unroll
    for (int e = 0; e < NEc; e++) {
        float p = 0.f;
        for (int d = lane; d < Dc; d += 32) p += hrow[d] * Wg[d*NEc + e];
        #pragma unroll
        for (int off = 16; off > 0; off >>= 1) p += __shfl_xor_sync(0xFFFFFFFFu, p, off);
        logit[e] = p;
    }
    float m = logit[0]; int am = 0;
    #pragma unroll
    for (int e = 1; e < NEc; e++) if (logit[e] > m) { m = logit[e]; am = e; }
    float sum = 0.f;
    #pragma unroll
    for (int e = 0; e < NEc; e++) sum += expf(logit[e] - m);
    if (lane == 0) {
        gate[warp] = 1.f / sum;
        int pos = atomicAdd(&cnt[am], 1);
        idxlist[am*Tc + pos] = warp;
    }
}

// ---------------- launch ----------------
extern "C" void kernel_launch(void* const* d_in, const int* in_sizes, int n_in,
                              void* d_out, int out_size)
{
    const float* x    = (const float*)d_in[0];
    const float* Wqkv = (const float*)d_in[1];
    const float* Wo   = (const float*)d_in[2];
    const float* Wr   = (const float*)d_in[3];
    const float* u_b  = (const float*)d_in[4];
    const float* v_b  = (const float*)d_in[5];
    const float* ln1g = (const float*)d_in[6];
    const float* ln1b = (const float*)d_in[7];
    const float* Wff1 = (const float*)d_in[8];
    const float* bff1 = (const float*)d_in[9];
    const float* Wff2 = (const float*)d_in[10];
    const float* bff2 = (const float*)d_in[11];
    const float* ln2g = (const float*)d_in[12];
    const float* ln2b = (const float*)d_in[13];
    const float* Wg   = (const float*)d_in[14];
    const float* We1  = (const float*)d_in[15];
    const float* be1  = (const float*)d_in[16];
    const float* We2  = (const float*)d_in[17];
    const float* be2  = (const float*)d_in[18];
    const float* ln3g = (const float*)d_in[19];
    const float* ln3b = (const float*)d_in[20];
    const float* Wout = (const float*)d_in[21];
    float* out = (float*)d_out;

    float *pe, *qkv, *r, *sc, *bd, *ctx, *ao, *h1, *ffh, *ff, *h2, *moe, *h3, *gate;
    int *cnt, *idx;
    __nv_bfloat16 *whi, *wlo;
    cudaGetSymbolAddress((void**)&pe,  g_pe);
    cudaGetSymbolAddress((void**)&qkv, g_qkv);
    cudaGetSymbolAddress((void**)&r,   g_r);
    cudaGetSymbolAddress((void**)&sc,  g_sc);
    cudaGetSymbolAddress((void**)&bd,  g_bd);
    cudaGetSymbolAddress((void**)&ctx, g_ctx);
    cudaGetSymbolAddress((void**)&ao,  g_ao);
    cudaGetSymbolAddress((void**)&h1,  g_h1);
    cudaGetSymbolAddress((void**)&ffh, g_ffh);
    cudaGetSymbolAddress((void**)&ff,  g_ff);
    cudaGetSymbolAddress((void**)&h2,  g_h2);
    cudaGetSymbolAddress((void**)&moe, g_moe);
    cudaGetSymbolAddress((void**)&h3,  g_h3);
    cudaGetSymbolAddress((void**)&gate,g_gate);
    cudaGetSymbolAddress((void**)&cnt, g_cnt);
    cudaGetSymbolAddress((void**)&idx, g_idx);
    cudaGetSymbolAddress((void**)&whi, g_whi);
    cudaGetSymbolAddress((void**)&wlo, g_wlo);

    // weight transpose + split (every call; deterministic)
    wconv<<<dim3(3072/32, 1024/32), 256>>>(Wqkv, whi+OFF_QKV,  wlo+OFF_QKV,  1024, 3072);
    wconv<<<dim3(1024/32, 1024/32), 256>>>(Wr,   whi+OFF_WR,   wlo+OFF_WR,   1024, 1024);
    wconv<<<dim3(1024/32, 1024/32), 256>>>(Wo,   whi+OFF_WO,   wlo+OFF_WO,   1024, 1024);
    wconv<<<dim3(4096/32, 1024/32), 256>>>(Wff1, whi+OFF_FF1,  wlo+OFF_FF1,  1024, 4096);
    wconv<<<dim3(1024/32, 4096/32), 256>>>(Wff2, whi+OFF_FF2,  wlo+OFF_FF2,  4096, 1024);
    wconv<<<dim3(1024/32, 1024/32), 256>>>(Wout, whi+OFF_WOUT, wlo+OFF_WOUT, 1024, 1024);
    for (int e = 0; e < NEc; e++) {
        wconv<<<dim3(4096/32, 1024/32), 256>>>(We1 + (size_t)e*Dc*FFc,
            whi+OFF_WE1 + (size_t)e*FFc*Dc, wlo+OFF_WE1 + (size_t)e*FFc*Dc, 1024, 4096);
        wconv<<<dim3(1024/32, 4096/32), 256>>>(We2 + (size_t)e*FFc*Dc,
            whi+OFF_WE2 + (size_t)e*Dc*FFc, wlo+OFF_WE2 + (size_t)e*Dc*FFc, 4096, 1024);
    }

    // projections
    pe_kernel<<<Sc, 256>>>(pe);
    tgemm<0><<<dim3(3072/128, Tc/128), 256>>>(x,  whi+OFF_QKV, wlo+OFF_QKV, qkv, Tc, 3072, 1024, nullptr, nullptr, nullptr, nullptr);
    tgemm<0><<<dim3(1024/128, Sc/128), 256>>>(pe, whi+OFF_WR,  wlo+OFF_WR,  r,   Sc, 1024, 1024, nullptr, nullptr, nullptr, nullptr);

    // attention (fp32)
    attn_qk<<<dim3(16, 16, BHc), 256>>>(qkv, u_b, r, 0, sc);
    attn_qk<<<dim3(16, 16, BHc), 256>>>(qkv, v_b, r, 1, bd);
    softmax_k<<<dim3(Sc, BHc), 256>>>(sc, bd);
    attn_av<<<dim3(16, BHc), 256>>>(sc, qkv, ctx);
    tgemm<0><<<dim3(1024/128, Tc/128), 256>>>(ctx, whi+OFF_WO, wlo+OFF_WO, ao, Tc, 1024, 1024, nullptr, nullptr, nullptr, nullptr);
    rln_k<<<Tc, 256>>>(x, ao, ln1g, ln1b, h1);

    // FFN
    tgemm<2><<<dim3(4096/128, Tc/128), 256>>>(h1,  whi+OFF_FF1, wlo+OFF_FF1, ffh, Tc, 4096, 1024, bff1, nullptr, nullptr, nullptr);
    tgemm<1><<<dim3(1024/128, Tc/128), 256>>>(ffh, whi+OFF_FF2, wlo+OFF_FF2, ff,  Tc, 1024, 4096, bff2, nullptr, nullptr, nullptr);
    rln_k<<<Tc, 256>>>(h1, ff, ln2g, ln2b, h2);

    // MoE
    zero_cnt<<<1, 32>>>(cnt);
    router_k<<<Tc/8, 256>>>(h2, Wg, gate, cnt, idx);
    for (int e = 0; e < NEc; e++) {
        tgemm<2><<<dim3(4096/128, Tc/128), 256>>>(
            h2,  whi+OFF_WE1 + (size_t)e*FFc*Dc, wlo+OFF_WE1 + (size_t)e*FFc*Dc, ffh,
            Tc, 4096, 1024, be1 + (size_t)e*FFc, nullptr, idx + e*Tc, cnt + e);
        tgemm<3><<<dim3(1024/128, Tc/128), 256>>>(
            ffh, whi+OFF_WE2 + (size_t)e*Dc*FFc, wlo+OFF_WE2 + (size_t)e*Dc*FFc, moe,
            Tc, 1024, 4096, be2 + (size_t)e*Dc, gate, idx + e*Tc, cnt + e);
    }
    rln_k<<<Tc, 256>>>(h2, moe, ln3g, ln3b, h3);

    // output projection
    tgemm<0><<<dim3(1024/128, Tc/128), 256>>>(h3, whi+OFF_WOUT, wlo+OFF_WOUT, out, Tc, 1024, 1024, nullptr, nullptr, nullptr, nullptr);
}

// round 4
// speedup vs baseline: 4.3907x; 1.1777x over previous
#include <cuda_runtime.h>
#include <cuda_bf16.h>
#include <math.h>
#include <stdint.h>

#define Bc 4
#define Sc 1024
#define Dc 1024
#define NHc 16
#define DHc 64
#define FFc 4096
#define NEc 8
#define Tc (Bc*Sc)
#define BHc (Bc*NHc)

typedef __nv_bfloat16 bf16;
typedef __nv_bfloat162 bf162;

// ---------------- fp32 scratch ----------------
__device__ float g_qkv[(size_t)Tc*3*Dc];
__device__ float g_r[Sc*Dc];
__device__ float g_sc[(size_t)BHc*Sc*Sc];   // ac scores, then probs (in place)
__device__ float g_bd[(size_t)BHc*Sc*Sc];   // raw bd term (pre rel-shift)
__device__ float g_ao[(size_t)Tc*Dc];
__device__ float g_ff[(size_t)Tc*Dc];
__device__ float g_h1[(size_t)Tc*Dc];
__device__ float g_h2[(size_t)Tc*Dc];
__device__ float g_h3[(size_t)Tc*Dc];
__device__ float g_moe[(size_t)Tc*Dc];
__device__ float g_gate[Tc];
__device__ int   g_cnt[NEc];
__device__ int   g_idx[NEc*Tc];

// ---------------- bf16 hi/lo scratch ----------------
__device__ bf16 g_peh[Sc*Dc],  g_pel[Sc*Dc];
__device__ bf16 g_xh[(size_t)Tc*Dc],  g_xl[(size_t)Tc*Dc];
__device__ bf16 g_quh[(size_t)Tc*Dc], g_qul[(size_t)Tc*Dc];   // [bh][s][64]
__device__ bf16 g_qvh[(size_t)Tc*Dc], g_qvl[(size_t)Tc*Dc];
__device__ bf16 g_kh[(size_t)Tc*Dc],  g_kl[(size_t)Tc*Dc];
__device__ bf16 g_vth[(size_t)Tc*Dc], g_vtl[(size_t)Tc*Dc];   // [bh][d][s]
__device__ bf16 g_rh[NHc*Sc*DHc],     g_rl[NHc*Sc*DHc];       // [h][s][64]
__device__ bf16 g_ctxh[(size_t)Tc*Dc], g_ctxl[(size_t)Tc*Dc];
__device__ bf16 g_h1h[(size_t)Tc*Dc], g_h1l[(size_t)Tc*Dc];
__device__ bf16 g_h2h[(size_t)Tc*Dc], g_h2l[(size_t)Tc*Dc];
__device__ bf16 g_h3h[(size_t)Tc*Dc], g_h3l[(size_t)Tc*Dc];
__device__ bf16 g_ffhh[(size_t)Tc*FFc], g_ffhl[(size_t)Tc*FFc];

// transposed split-bf16 weights: [N,K] layout, hi + lo
#define OFF_QKV  0
#define OFF_WR   3145728
#define OFF_WO   4194304
#define OFF_FF1  5242880
#define OFF_FF2  9437184
#define OFF_WE1  13631488
#define OFF_WE2  47185920
#define OFF_WOUT 80740352
#define WTOT     81788928
__device__ bf16 g_whi[WTOT];
__device__ bf16 g_wlo[WTOT];

// ---------------- helpers ----------------
__device__ __forceinline__ uint32_t smem_u32(const void* p) {
    uint32_t a;
    asm("{ .reg .u64 t; cvta.to.shared.u64 t, %1; cvt.u32.u64 %0, t; }" : "=r"(a) : "l"(p));
    return a;
}
__device__ __forceinline__ void ldm4(uint32_t* r, uint32_t a) {
    asm volatile("ldmatrix.sync.aligned.m8n8.x4.shared.b16 {%0,%1,%2,%3}, [%4];"
        : "=r"(r[0]), "=r"(r[1]), "=r"(r[2]), "=r"(r[3]) : "r"(a));
}
__device__ __forceinline__ void mma_bf16(float* c, const uint32_t* a, uint32_t b0, uint32_t b1) {
    asm volatile("mma.sync.aligned.m16n8k16.row.col.f32.bf16.bf16.f32 "
        "{%0,%1,%2,%3}, {%4,%5,%6,%7}, {%8,%9}, {%0,%1,%2,%3};"
        : "+f"(c[0]), "+f"(c[1]), "+f"(c[2]), "+f"(c[3])
        : "r"(a[0]), "r"(a[1]), "r"(a[2]), "r"(a[3]), "r"(b0), "r"(b1));
}
__device__ __forceinline__ void split1(float v, bf16& h, bf16& l) {
    h = __float2bfloat16_rn(v);
    l = __float2bfloat16_rn(v - __bfloat162float(h));
}
__device__ __forceinline__ void split2(float x, float y, bf162& h, bf162& l) {
    h = __floats2bfloat162_rn(x, y);
    float2 hf = __bfloat1622float2(h);
    l = __floats2bfloat162_rn(x - hf.x, y - hf.y);
}

// ---------------- weight transpose + split: W[K,N] -> hi/lo [N,K] ----------------
__global__ __launch_bounds__(256)
void wconv(const float* __restrict__ W, bf16* __restrict__ hi,
           bf16* __restrict__ lo, int K, int N)
{
    __shared__ float t[32][33];
    int tx = threadIdx.x & 31, ty = threadIdx.x >> 5;
    int kb = blockIdx.y * 32, nb = blockIdx.x * 32;
    #pragma unroll
    for (int j = 0; j < 4; j++)
        t[ty + j*8][tx] = W[(size_t)(kb + ty + j*8) * N + nb + tx];
    __syncthreads();
    #pragma unroll
    for (int j = 0; j < 4; j++) {
        int n = nb + ty + j*8, k = kb + tx;
        float v = t[tx][ty + j*8];
        bf16 h, l; split1(v, h, l);
        hi[(size_t)n*K + k] = h;
        lo[(size_t)n*K + k] = l;
    }
}

// ---------------- elementwise fp32 -> bf16 hi/lo ----------------
__global__ __launch_bounds__(256)
void econv(const float* __restrict__ src, bf16* __restrict__ hi, bf16* __restrict__ lo)
{
    size_t i = (size_t)blockIdx.x * 1024 + threadIdx.x;
    #pragma unroll
    for (int l = 0; l < 4; l++) {
        float v = src[i + l*256];
        bf16 h, lo_;
        split1(v, h, lo_);
        hi[i + l*256] = h; lo[i + l*256] = lo_;
    }
}

// ---------------- positional embedding (bf16 hi/lo) ----------------
__global__ void pe_kernel(bf16* __restrict__ peh, bf16* __restrict__ pel) {
    int i = blockIdx.x;
    float pos = (float)(Sc - 1 - i);
    #pragma unroll
    for (int l = 0; l < 4; l++) {
        int c = threadIdx.x + l * 256;
        int j = (c < Dc/2) ? c : (c - Dc/2);
        float invf = expf(-logf(10000.f) * ((float)(2*j) / (float)Dc));
        float a = pos * invf;
        float v = (c < Dc/2) ? sinf(a) : cosf(a);
        bf16 h, lo; split1(v, h, lo);
        peh[(size_t)i*Dc + c] = h; pel[(size_t)i*Dc + c] = lo;
    }
}

// ---------------- attention operand prep ----------------
// qu = q + u_bias, qv = q + v_bias, k -> [bh][s][64] bf16 hi/lo
__global__ __launch_bounds__(256)
void qprep(const float* __restrict__ qkv, const float* __restrict__ ub, const float* __restrict__ vb,
           bf16* quh, bf16* qul, bf16* qvh, bf16* qvl, bf16* kh, bf16* kl)
{
    int tok = blockIdx.x;
    int b = tok >> 10, s = tok & 1023;
    #pragma unroll
    for (int l = 0; l < 4; l++) {
        int c = threadIdx.x + l*256;
        int h = c >> 6, d = c & 63;
        size_t src = (size_t)tok*3072 + c;
        float qf = qkv[src], kf = qkv[src + 1024];
        size_t dst = ((size_t)(b*NHc + h)*Sc + s)*64 + d;
        bf16 hh, ll;
        split1(qf + ub[c], hh, ll); quh[dst] = hh; qul[dst] = ll;
        split1(qf + vb[c], hh, ll); qvh[dst] = hh; qvl[dst] = ll;
        split1(kf, hh, ll);         kh[dst] = hh;  kl[dst] = ll;
    }
}
// v -> transposed [bh][d][s] bf16 hi/lo
__global__ __launch_bounds__(256)
void vtprep(const float* __restrict__ qkv, bf16* vth, bf16* vtl)
{
    __shared__ float t[32][33];
    int tx = threadIdx.x & 31, ty = threadIdx.x >> 5;
    int s0 = blockIdx.x * 32, d0 = blockIdx.y * 32, bh = blockIdx.z;
    int b = bh >> 4, h = bh & 15;
    #pragma unroll
    for (int j = 0; j < 4; j++) {
        int sl = ty + j*8;
        t[sl][tx] = qkv[((size_t)(b*Sc + s0 + sl))*3072 + 2048 + h*64 + d0 + tx];
    }
    __syncthreads();
    #pragma unroll
    for (int j = 0; j < 4; j++) {
        int dl = ty + j*8;
        float v = t[tx][dl];
        bf16 hh, ll; split1(v, hh, ll);
        size_t dst = ((size_t)bh*64 + d0 + dl)*Sc + s0 + tx;
        vth[dst] = hh; vtl[dst] = ll;
    }
}
// r[s][h*64+d] -> [h][s][64]
__global__ __launch_bounds__(256)
void rprep(const float* __restrict__ r, bf16* rh, bf16* rl)
{
    int s = blockIdx.x;
    #pragma unroll
    for (int l = 0; l < 4; l++) {
        int c = threadIdx.x + l*256;
        int h = c >> 6, d = c & 63;
        float v = r[(size_t)s*Dc + c];
        bf16 hh, ll; split1(v, hh, ll);
        size_t dst = ((size_t)h*Sc + s)*64 + d;
        rh[dst] = hh; rl[dst] = ll;
    }
}

// ---------------- HMMA split-bf16 GEMM: C[M,N] = A[M,K] @ B^T ----------------
// A bf16 hi/lo [M,K]; B bf16 hi/lo [N,K]. CTA 128x128, BK=32, 8 warps (32x64).
// EPI: 0=none 1=+bias 2=relu(+bias) 3=(+bias)*rowScale ; OBF: 0=fp32 C, 1=bf16 hi/lo C
template<int EPI, int OBF>
__global__ __launch_bounds__(256)
void tgemm(const bf16* __restrict__ Ahi, const bf16* __restrict__ Alo,
           const bf16* __restrict__ Bhi, const bf16* __restrict__ Blo,
           float* __restrict__ C, bf16* __restrict__ Chi, bf16* __restrict__ Clo,
           int M, int N, int K,
           const float* __restrict__ bias, const float* __restrict__ rowScale,
           const int* __restrict__ gather, const int* __restrict__ cntPtr)
{
    __shared__ bf16 AsH[128][40];
    __shared__ bf16 AsL[128][40];
    __shared__ bf16 BsH[128][40];
    __shared__ bf16 BsL[128][40];

    int limit = cntPtr ? cntPtr[0] : M;
    int m0 = blockIdx.y * 128;
    if (m0 >= limit) return;
    int n0 = blockIdx.x * 128;

    int tid = threadIdx.x, wid = tid >> 5, lane = tid & 31;
    int wm = (wid & 3) * 32, wn = (wid >> 2) * 64;

    // staging pointers: 512 uint4 slots (128 rows x 4 segs of 8 bf16) per buffer
    const bf16 *aph[2], *apl[2], *bph[2], *bpl[2];
    int arow[2], aseg[2], brow[2], bseg[2];
    #pragma unroll
    for (int l = 0; l < 2; l++) {
        int slot = tid + 256*l;
        arow[l] = slot >> 2; aseg[l] = slot & 3;
        int gr = m0 + arow[l];
        aph[l] = nullptr; apl[l] = nullptr;
        if (gr < limit) {
            int sr = gather ? gather[gr] : gr;
            aph[l] = Ahi + (size_t)sr * K + aseg[l] * 8;
            apl[l] = Alo + (size_t)sr * K + aseg[l] * 8;
        }
        brow[l] = slot >> 2; bseg[l] = slot & 3;
        size_t off = (size_t)(n0 + brow[l]) * K + bseg[l] * 8;
        bph[l] = Bhi + off; bpl[l] = Blo + off;
    }

    int t4 = lane >> 3;
    int rr = (lane & 7) + (t4 & 1) * 8;
    int cc = (t4 >> 1) * 8;
    uint32_t baAH = smem_u32(AsH), baAL = smem_u32(AsL);
    uint32_t baBH = smem_u32(BsH), baBL = smem_u32(BsL);

    float acc[2][8][4];
    #pragma unroll
    for (int i = 0; i < 2; i++)
        #pragma unroll
        for (int j = 0; j < 8; j++)
            #pragma unroll
            for (int q = 0; q < 4; q++) acc[i][j][q] = 0.f;

    uint4 avh[2], avl[2], bvh[2], bvl[2];
    const uint4 z4 = make_uint4(0,0,0,0);
    int Kc = K >> 5;

    #pragma unroll
    for (int l = 0; l < 2; l++) {
        avh[l] = aph[l] ? *(const uint4*)(aph[l]) : z4;
        avl[l] = apl[l] ? *(const uint4*)(apl[l]) : z4;
        bvh[l] = *(const uint4*)(bph[l]);
        bvl[l] = *(const uint4*)(bpl[l]);
    }

    for (int c = 0; c < Kc; c++) {
        #pragma unroll
        for (int l = 0; l < 2; l++) {
            *(uint4*)&AsH[arow[l]][aseg[l]*8] = avh[l];
            *(uint4*)&AsL[arow[l]][aseg[l]*8] = avl[l];
            *(uint4*)&BsH[brow[l]][bseg[l]*8] = bvh[l];
            *(uint4*)&BsL[brow[l]][bseg[l]*8] = bvl[l];
        }
        __syncthreads();

        if (c + 1 < Kc) {
            int ko = (c + 1) * 32;
            #pragma unroll
            for (int l = 0; l < 2; l++) {
                avh[l] = aph[l] ? *(const uint4*)(aph[l] + ko) : z4;
                avl[l] = apl[l] ? *(const uint4*)(apl[l] + ko) : z4;
                bvh[l] = *(const uint4*)(bph[l] + ko);
                bvl[l] = *(const uint4*)(bpl[l] + ko);
            }
        }

        #pragma unroll
        for (int k16 = 0; k16 < 32; k16 += 16) {
            uint32_t aH[2][4], aL[2][4];
            #pragma unroll
            for (int mi = 0; mi < 2; mi++) {
                uint32_t off = ((uint32_t)(wm + mi*16 + rr) * 40u + (uint32_t)(k16 + cc)) * 2u;
                ldm4(aH[mi], baAH + off);
                ldm4(aL[mi], baAL + off);
            }
            uint32_t bH[4][4], bL[4][4];
            #pragma unroll
            for (int ni = 0; ni < 4; ni++) {
                uint32_t off = ((uint32_t)(wn + ni*16 + rr) * 40u + (uint32_t)(k16 + cc)) * 2u;
                ldm4(bH[ni], baBH + off);
                ldm4(bL[ni], baBL + off);
            }
            #pragma unroll
            for (int mi = 0; mi < 2; mi++)
                #pragma unroll
                for (int ni = 0; ni < 4; ni++)
                    #pragma unroll
                    for (int h = 0; h < 2; h++) {
                        int j = ni*2 + h;
                        mma_bf16(acc[mi][j], aH[mi], bH[ni][h], bH[ni][h+2]);
                        mma_bf16(acc[mi][j], aH[mi], bL[ni][h], bL[ni][h+2]);
                        mma_bf16(acc[mi][j], aL[mi], bH[ni][h], bH[ni][h+2]);
                    }
        }
        __syncthreads();
    }

    #pragma unroll
    for (int mi = 0; mi < 2; mi++) {
        #pragma unroll
        for (int half = 0; half < 2; half++) {
            int gr = m0 + wm + mi*16 + (lane >> 2) + half*8;
            if (gr >= limit) continue;
            int crow = gather ? gather[gr] : gr;
            float rs = 1.f;
            if (EPI == 3) rs = rowScale[crow];
            #pragma unroll
            for (int j = 0; j < 8; j++) {
                int col = n0 + wn + j*8 + (lane & 3)*2;
                float vx = acc[mi][j][half*2 + 0];
                float vy = acc[mi][j][half*2 + 1];
                if (EPI >= 1) { vx += bias[col]; vy += bias[col+1]; }
                if (EPI == 2) { vx = fmaxf(vx, 0.f); vy = fmaxf(vy, 0.f); }
                if (EPI == 3) { vx *= rs; vy *= rs; }
                if (OBF == 0) {
                    *(float2*)(C + (size_t)crow * N + col) = make_float2(vx, vy);
                } else {
                    bf162 h, l; split2(vx, vy, h, l);
                    *(bf162*)(Chi + (size_t)crow * N + col) = h;
                    *(bf162*)(Clo + (size_t)crow * N + col) = l;
                }
            }
        }
    }
}

// ---------------- attention scores via HMMA (64x64 tile) ----------------
// mode 0: ac = A(qu)[bh] @ B(k)[bh]^T ; mode 1: bd = A(qv)[bh] @ B(r)[h]^T
__global__ __launch_bounds__(256)
void attn_sc(const bf16* __restrict__ Ah_, const bf16* __restrict__ Al_,
             const bf16* __restrict__ Bh_, const bf16* __restrict__ Bl_,
             float* __restrict__ out, int mode)
{
    int kt = blockIdx.x, qt = blockIdx.y, bh = blockIdx.z;
    if (mode == 0 && kt > qt) return;
    if (mode == 1 && (qt*64 + kt*64 + 126) < (Sc - 1)) return;

    __shared__ bf16 Ahs[64][72], Als[64][72];
    __shared__ bf16 Bhs[64][72], Bls[64][72];

    size_t aoff = ((size_t)bh*Sc + qt*64)*64;
    size_t boff = mode ? ((size_t)(bh & 15)*Sc + kt*64)*64 : ((size_t)bh*Sc + kt*64)*64;

    int tid = threadIdx.x, wid = tid >> 5, lane = tid & 31;
    #pragma unroll
    for (int l = 0; l < 2; l++) {
        int slot = tid + 256*l;
        int row = slot >> 3, seg = slot & 7;
        *(uint4*)&Ahs[row][seg*8] = *(const uint4*)(Ah_ + aoff + row*64 + seg*8);
        *(uint4*)&Als[row][seg*8] = *(const uint4*)(Al_ + aoff + row*64 + seg*8);
        *(uint4*)&Bhs[row][seg*8] = *(const uint4*)(Bh_ + boff + row*64 + seg*8);
        *(uint4*)&Bls[row][seg*8] = *(const uint4*)(Bl_ + boff + row*64 + seg*8);
    }
    __syncthreads();

    int wm = (wid & 3) * 16, wn = (wid >> 2) * 32;
    int t4 = lane >> 3;
    int rr = (lane & 7) + (t4 & 1) * 8;
    int cc = (t4 >> 1) * 8;
    uint32_t baAH = smem_u32(Ahs), baAL = smem_u32(Als);
    uint32_t baBH = smem_u32(Bhs), baBL = smem_u32(Bls);

    float acc[4][4];
    #pragma unroll
    for (int j = 0; j < 4; j++)
        #pragma unroll
        for (int q = 0; q < 4; q++) acc[j][q] = 0.f;

    #pragma unroll
    for (int k16 = 0; k16 < 64; k16 += 16) {
        uint32_t aH[4], aL[4];
        {
            uint32_t off = ((uint32_t)(wm + rr) * 72u + (uint32_t)(k16 + cc)) * 2u;
            ldm4(aH, baAH + off);
            ldm4(aL, baAL + off);
        }
        uint32_t bH[2][4], bL[2][4];
        #pragma unroll
        for (int ni = 0; ni < 2; ni++) {
            uint32_t off = ((uint32_t)(wn + ni*16 + rr) * 72u + (uint32_t)(k16 + cc)) * 2u;
            ldm4(bH[ni], baBH + off);
            ldm4(bL[ni], baBL + off);
        }
        #pragma unroll
        for (int ni = 0; ni < 2; ni++)
            #pragma unroll
            for (int h = 0; h < 2; h++) {
                int j = ni*2 + h;
                mma_bf16(acc[j], aH, bH[ni][h], bH[ni][h+2]);
                mma_bf16(acc[j], aH, bL[ni][h], bL[ni][h+2]);
                mma_bf16(acc[j], aL, bH[ni][h], bH[ni][h+2]);
            }
    }

    #pragma unroll
    for (int half = 0; half < 2; half++) {
        int q = qt*64 + wm + (lane >> 2) + half*8;
        #pragma unroll
        for (int j = 0; j < 4; j++) {
            int k = kt*64 + wn + j*8 + (lane & 3)*2;
            *(float2*)(out + ((size_t)bh*Sc + q)*Sc + k) =
                make_float2(acc[j][half*2], acc[j][half*2+1]);
        }
    }
}

// ---------------- rel_shift + causal softmax (in place on sc) ----------------
__global__ __launch_bounds__(256)
void softmax_k(float* __restrict__ sc, const float* __restrict__ bd)
{
    int q = blockIdx.x, bh = blockIdx.y;
    size_t base = ((size_t)bh*Sc + q)*Sc;
    int tid = threadIdx.x;
    __shared__ float red[256];

    float v[4];
    float mx = -1e30f;
    #pragma unroll
    for (int l = 0; l < 4; l++) {
        int k = tid + l*256;
        float val = -1e30f;
        if (k <= q) {
            int j = k - q + Sc - 1;
            val = (sc[base + k] + bd[base + j]) * 0.125f;
        }
        v[l] = val;
        mx = fmaxf(mx, val);
    }
    red[tid] = mx; __syncthreads();
    for (int s = 128; s > 0; s >>= 1) { if (tid < s) red[tid] = fmaxf(red[tid], red[tid+s]); __syncthreads(); }
    float m = red[0]; __syncthreads();

    float sum = 0.f;
    #pragma unroll
    for (int l = 0; l < 4; l++) {
        int k = tid + l*256;
        float e = (k <= q) ? expf(v[l] - m) : 0.f;
        v[l] = e; sum += e;
    }
    red[tid] = sum; __syncthreads();
    for (int s = 128; s > 0; s >>= 1) { if (tid < s) red[tid] += red[tid+s]; __syncthreads(); }
    float inv = 1.f / red[0];

    #pragma unroll
    for (int l = 0; l < 4; l++) {
        int k = tid + l*256;
        sc[base + k] = v[l] * inv;
    }
}

// ---------------- ctx = probs @ V via HMMA (64q x 64d tile) ----------------
__global__ __launch_bounds__(256)
void attn_av(const float* __restrict__ probs, const bf16* __restrict__ vth,
             const bf16* __restrict__ vtl, bf16* __restrict__ ctxh, bf16* __restrict__ ctxl)
{
    int qt = blockIdx.x, bh = blockIdx.y;
    int b = bh >> 4, h = bh & 15;
    int q0 = qt * 64;

    __shared__ bf16 Phs[64][72], Pls[64][72];
    __shared__ bf16 Vhs[64][72], Vls[64][72];

    int tid = threadIdx.x, wid = tid >> 5, lane = tid & 31;
    int wm = (wid & 3) * 16, wn = (wid >> 2) * 32;
    int t4 = lane >> 3;
    int rr = (lane & 7) + (t4 & 1) * 8;
    int cc = (t4 >> 1) * 8;
    uint32_t baPH = smem_u32(Phs), baPL = smem_u32(Pls);
    uint32_t baVH = smem_u32(Vhs), baVL = smem_u32(Vls);

    float acc[4][4];
    #pragma unroll
    for (int j = 0; j < 4; j++)
        #pragma unroll
        for (int q = 0; q < 4; q++) acc[j][q] = 0.f;

    int kmax = (qt + 1) * 64;
    for (int s0 = 0; s0 < kmax; s0 += 64) {
        __syncthreads();
        // probs tile: 64x64 fp32 -> split into smem
        #pragma unroll
        for (int l = 0; l < 4; l++) {
            int slot = tid + 256*l;
            int row = slot >> 4, seg = slot & 15;
            float4 p = *(const float4*)(probs + ((size_t)bh*Sc + q0 + row)*Sc + s0 + seg*4);
            bf162 h0, l0, h1, l1;
            split2(p.x, p.y, h0, l0);
            split2(p.z, p.w, h1, l1);
            *(bf162*)&Phs[row][seg*4]     = h0;
            *(bf162*)&Phs[row][seg*4 + 2] = h1;
            *(bf162*)&Pls[row][seg*4]     = l0;
            *(bf162*)&Pls[row][seg*4 + 2] = l1;
        }
        // V^T tile: [d rows][s cols]
        #pragma unroll
        for (int l = 0; l < 2; l++) {
            int slot = tid + 256*l;
            int row = slot >> 3, seg = slot & 7;
            size_t src = ((size_t)bh*64 + row)*Sc + s0 + seg*8;
            *(uint4*)&Vhs[row][seg*8] = *(const uint4*)(vth + src);
            *(uint4*)&Vls[row][seg*8] = *(const uint4*)(vtl + src);
        }
        __syncthreads();

        #pragma unroll
        for (int k16 = 0; k16 < 64; k16 += 16) {
            uint32_t aH[4], aL[4];
            {
                uint32_t off = ((uint32_t)(wm + rr) * 72u + (uint32_t)(k16 + cc)) * 2u;
                ldm4(aH, baPH + off);
                ldm4(aL, baPL + off);
            }
            uint32_t bH[2][4], bL[2][4];
            #pragma unroll
            for (int ni = 0; ni < 2; ni++) {
                uint32_t off = ((uint32_t)(wn + ni*16 + rr) * 72u + (uint32_t)(k16 + cc)) * 2u;
                ldm4(bH[ni], baVH + off);
                ldm4(bL[ni], baVL + off);
            }
            #pragma unroll
            for (int ni = 0; ni < 2; ni++)
                #pragma unroll
                for (int hb = 0; hb < 2; hb++) {
                    int j = ni*2 + hb;
                    mma_bf16(acc[j], aH, bH[ni][hb], bH[ni][hb+2]);
                    mma_bf16(acc[j], aH, bL[ni][hb], bL[ni][hb+2]);
                    mma_bf16(acc[j], aL, bH[ni][hb], bH[ni][hb+2]);
                }
        }
    }

    #pragma unroll
    for (int half = 0; half < 2; half++) {
        int tok = b*Sc + q0 + wm + (lane >> 2) + half*8;
        #pragma unroll
        for (int j = 0; j < 4; j++) {
            int col = h*64 + wn + j*8 + (lane & 3)*2;
            bf162 hh, ll;
            split2(acc[j][half*2], acc[j][half*2+1], hh, ll);
            *(bf162*)(ctxh + (size_t)tok*Dc + col) = hh;
            *(bf162*)(ctxl + (size_t)tok*Dc + col) = ll;
        }
    }
}

// ---------------- residual + layernorm (fp32 out + optional bf16 hi/lo) ----------------
template<int OBF>
__global__ __launch_bounds__(256)
void rln_k(const float* __restrict__ x, const float* __restrict__ y,
           const float* __restrict__ g, const float* __restrict__ bta,
           float* __restrict__ out, bf16* __restrict__ oh, bf16* __restrict__ ol)
{
    int row = blockIdx.x;
    int tid = threadIdx.x;
    __shared__ float red[256];
    float v[4];
    float s = 0.f, ss = 0.f;
    #pragma unroll
    for (int l = 0; l < 4; l++) {
        size_t idx = (size_t)row*Dc + tid + l*256;
        float val = x[idx] + y[idx];
        v[l] = val; s += val; ss += val*val;
    }
    red[tid] = s; __syncthreads();
    for (int st = 128; st > 0; st >>= 1) { if (tid < st) red[tid] += red[tid+st]; __syncthreads(); }
    float mean = red[0] * (1.f/Dc); __syncthreads();
    red[tid] = ss; __syncthreads();
    for (int st = 128; st > 0; st >>= 1) { if (tid < st) red[tid] += red[tid+st]; __syncthreads(); }
    float var = red[0] * (1.f/Dc) - mean*mean;
    float inv = rsqrtf(var + 1e-5f);
    #pragma unroll
    for (int l = 0; l < 4; l++) {
        int c = tid + l*256;
        float o = (v[l] - mean) * inv * g[c] + bta[c];
        out[(size_t)row*Dc + c] = o;
        if (OBF) {
            bf16 hh, ll; split1(o, hh, ll);
            oh[(size_t)row*Dc + c] = hh;
            ol[(size_t)row*Dc + c] = ll;
        }
    }
}

// ---------------- router ----------------
__global__ void zero_cnt(int* cnt) { if (threadIdx.x < NEc) cnt[threadIdx.x] = 0; }

__global__ __launch_bounds__(256)
void router_k(const float* __restrict__ h2, const float* __restrict__ Wg,
              float* __restrict__ gate, int* __restrict__ cnt, int* __restrict__ idxlist)
{
    int warp = (blockIdx.x * blockDim.x + threadIdx.x) >> 5;
    int lane = threadIdx.x & 31;
    if (warp >= Tc) return;
    const float* hrow = h2 + (size_t)warp * Dc;
    float logit[NEc];
    #pragma unroll
    for (int e = 0; e < NEc; e++) {
        float p = 0.f;
        for (int d = lane; d < Dc; d += 32) p += hrow[d] * Wg[d*NEc + e];
        #pragma unroll
        for (int off = 16; off > 0; off >>= 1) p += __shfl_xor_sync(0xFFFFFFFFu, p, off);
        logit[e] = p;
    }
    float m = logit[0]; int am = 0;
    #pragma unroll
    for (int e = 1; e < NEc; e++) if (logit[e] > m) { m = logit[e]; am = e; }
    float sum = 0.f;
    #pragma unroll
    for (int e = 0; e < NEc; e++) sum += expf(logit[e] - m);
    if (lane == 0) {
        gate[warp] = 1.f / sum;
        int pos = atomicAdd(&cnt[am], 1);
        idxlist[am*Tc + pos] = warp;
    }
}

// ---------------- launch ----------------
extern "C" void kernel_launch(void* const* d_in, const int* in_sizes, int n_in,
                              void* d_out, int out_size)
{
    const float* x    = (const float*)d_in[0];
    const float* Wqkv = (const float*)d_in[1];
    const float* Wo   = (const float*)d_in[2];
    const float* Wr   = (const float*)d_in[3];
    const float* u_b  = (const float*)d_in[4];
    const float* v_b  = (const float*)d_in[5];
    const float* ln1g = (const float*)d_in[6];
    const float* ln1b = (const float*)d_in[7];
    const float* Wff1 = (const float*)d_in[8];
    const float* bff1 = (const float*)d_in[9];
    const float* Wff2 = (const float*)d_in[10];
    const float* bff2 = (const float*)d_in[11];
    const float* ln2g = (const float*)d_in[12];
    const float* ln2b = (const float*)d_in[13];
    const float* Wg   = (const float*)d_in[14];
    const float* We1  = (const float*)d_in[15];
    const float* be1  = (const float*)d_in[16];
    const float* We2  = (const float*)d_in[17];
    const float* be2  = (const float*)d_in[18];
    const float* ln3g = (const float*)d_in[19];
    const float* ln3b = (const float*)d_in[20];
    const float* Wout = (const float*)d_in[21];
    float* out = (float*)d_out;

    float *qkv, *r, *sc, *bd, *ao, *ff, *h1, *h2, *h3, *moe, *gate;
    int *cnt, *idx;
    bf16 *whi, *wlo, *peh, *pel, *xh, *xl;
    bf16 *quh, *qul, *qvh, *qvl, *kh, *kl, *vth, *vtl, *rh, *rl;
    bf16 *ctxh, *ctxl, *h1h, *h1l, *h2h, *h2l, *h3h, *h3l, *ffhh, *ffhl;

    cudaGetSymbolAddress((void**)&qkv, g_qkv);
    cudaGetSymbolAddress((void**)&r,   g_r);
    cudaGetSymbolAddress((void**)&sc,  g_sc);
    cudaGetSymbolAddress((void**)&bd,  g_bd);
    cudaGetSymbolAddress((void**)&ao,  g_ao);
    cudaGetSymbolAddress((void**)&ff,  g_ff);
    cudaGetSymbolAddress((void**)&h1,  g_h1);
    cudaGetSymbolAddress((void**)&h2,  g_h2);
    cudaGetSymbolAddress((void**)&h3,  g_h3);
    cudaGetSymbolAddress((void**)&moe, g_moe);
    cudaGetSymbolAddress((void**)&gate,g_gate);
    cudaGetSymbolAddress((void**)&cnt, g_cnt);
    cudaGetSymbolAddress((void**)&idx, g_idx);
    cudaGetSymbolAddress((void**)&whi, g_whi);
    cudaGetSymbolAddress((void**)&wlo, g_wlo);
    cudaGetSymbolAddress((void**)&peh, g_peh);
    cudaGetSymbolAddress((void**)&pel, g_pel);
    cudaGetSymbolAddress((void**)&xh,  g_xh);
    cudaGetSymbolAddress((void**)&xl,  g_xl);
    cudaGetSymbolAddress((void**)&quh, g_quh);
    cudaGetSymbolAddress((void**)&qul, g_qul);
    cudaGetSymbolAddress((void**)&qvh, g_qvh);
    cudaGetSymbolAddress((void**)&qvl, g_qvl);
    cudaGetSymbolAddress((void**)&kh,  g_kh);
    cudaGetSymbolAddress((void**)&kl,  g_kl);
    cudaGetSymbolAddress((void**)&vth, g_vth);
    cudaGetSymbolAddress((void**)&vtl, g_vtl);
    cudaGetSymbolAddress((void**)&rh,  g_rh);
    cudaGetSymbolAddress((void**)&rl,  g_rl);
    cudaGetSymbolAddress((void**)&ctxh,g_ctxh);
    cudaGetSymbolAddress((void**)&ctxl,g_ctxl);
    cudaGetSymbolAddress((void**)&h1h, g_h1h);
    cudaGetSymbolAddress((void**)&h1l, g_h1l);
    cudaGetSymbolAddress((void**)&h2h, g_h2h);
    cudaGetSymbolAddress((void**)&h2l, g_h2l);
    cudaGetSymbolAddress((void**)&h3h, g_h3h);
    cudaGetSymbolAddress((void**)&h3l, g_h3l);
    cudaGetSymbolAddress((void**)&ffhh,g_ffhh);
    cudaGetSymbolAddress((void**)&ffhl,g_ffhl);

    // weight transpose + split
    wconv<<<dim3(3072/32, 1024/32), 256>>>(Wqkv, whi+OFF_QKV,  wlo+OFF_QKV,  1024, 3072);
    wconv<<<dim3(1024/32, 1024/32), 256>>>(Wr,   whi+OFF_WR,   wlo+OFF_WR,   1024, 1024);
    wconv<<<dim3(1024/32, 1024/32), 256>>>(Wo,   whi+OFF_WO,   wlo+OFF_WO,   1024, 1024);
    wconv<<<dim3(4096/32, 1024/32), 256>>>(Wff1, whi+OFF_FF1,  wlo+OFF_FF1,  1024, 4096);
    wconv<<<dim3(1024/32, 4096/32), 256>>>(Wff2, whi+OFF_FF2,  wlo+OFF_FF2,  4096, 1024);
    wconv<<<dim3(1024/32, 1024/32), 256>>>(Wout, whi+OFF_WOUT, wlo+OFF_WOUT, 1024, 1024);
    for (int e = 0; e < NEc; e++) {
        wconv<<<dim3(4096/32, 1024/32), 256>>>(We1 + (size_t)e*Dc*FFc,
            whi+OFF_WE1 + (size_t)e*FFc*Dc, wlo+OFF_WE1 + (size_t)e*FFc*Dc, 1024, 4096);
        wconv<<<dim3(1024/32, 4096/32), 256>>>(We2 + (size_t)e*FFc*Dc,
            whi+OFF_WE2 + (size_t)e*Dc*FFc, wlo+OFF_WE2 + (size_t)e*Dc*FFc, 4096, 1024);
    }

    pe_kernel<<<Sc, 256>>>(peh, pel);
    econv<<<Tc, 256>>>(x, xh, xl);

    // projections
    tgemm<0,0><<<dim3(3072/128, Tc/128), 256>>>(xh, xl, whi+OFF_QKV, wlo+OFF_QKV,
        qkv, nullptr, nullptr, Tc, 3072, 1024, nullptr, nullptr, nullptr, nullptr);
    tgemm<0,0><<<dim3(1024/128, Sc/128), 256>>>(peh, pel, whi+OFF_WR, wlo+OFF_WR,
        r, nullptr, nullptr, Sc, 1024, 1024, nullptr, nullptr, nullptr, nullptr);

    // attention prep
    qprep<<<Tc, 256>>>(qkv, u_b, v_b, quh, qul, qvh, qvl, kh, kl);
    vtprep<<<dim3(Sc/32, 2, BHc), 256>>>(qkv, vth, vtl);
    rprep<<<Sc, 256>>>(r, rh, rl);

    // attention
    attn_sc<<<dim3(16, 16, BHc), 256>>>(quh, qul, kh, kl, sc, 0);
    attn_sc<<<dim3(16, 16, BHc), 256>>>(qvh, qvl, rh, rl, bd, 1);
    softmax_k<<<dim3(Sc, BHc), 256>>>(sc, bd);
    attn_av<<<dim3(16, BHc), 256>>>(sc, vth, vtl, ctxh, ctxl);
    tgemm<0,0><<<dim3(1024/128, Tc/128), 256>>>(ctxh, ctxl, whi+OFF_WO, wlo+OFF_WO,
        ao, nullptr, nullptr, Tc, 1024, 1024, nullptr, nullptr, nullptr, nullptr);
    rln_k<1><<<Tc, 256>>>(x, ao, ln1g, ln1b, h1, h1h, h1l);

    // FFN
    tgemm<2,1><<<dim3(4096/128, Tc/128), 256>>>(h1h, h1l, whi+OFF_FF1, wlo+OFF_FF1,
        nullptr, ffhh, ffhl, Tc, 4096, 1024, bff1, nullptr, nullptr, nullptr);
    tgemm<1,0><<<dim3(1024/128, Tc/128), 256>>>(ffhh, ffhl, whi+OFF_FF2, wlo+OFF_FF2,
        ff, nullptr, nullptr, Tc, 1024, 4096, bff2, nullptr, nullptr, nullptr);
    rln_k<1><<<Tc, 256>>>(h1, ff, ln2g, ln2b, h2, h2h, h2l);

    // MoE
    zero_cnt<<<1, 32>>>(cnt);
    router_k<<<Tc/8, 256>>>(h2, Wg, gate, cnt, idx);
    for (int e = 0; e < NEc; e++) {
        tgemm<2,1><<<dim3(4096/128, Tc/128), 256>>>(
            h2h, h2l, whi+OFF_WE1 + (size_t)e*FFc*Dc, wlo+OFF_WE1 + (size_t)e*FFc*Dc,
            nullptr, ffhh, ffhl, Tc, 4096, 1024, be1 + (size_t)e*FFc, nullptr, idx + e*Tc, cnt + e);
        tgemm<3,0><<<dim3(1024/128, Tc/128), 256>>>(
            ffhh, ffhl, whi+OFF_WE2 + (size_t)e*Dc*FFc, wlo+OFF_WE2 + (size_t)e*Dc*FFc,
            moe, nullptr, nullptr, Tc, 1024, 4096, be2 + (size_t)e*Dc, gate, idx + e*Tc, cnt + e);
    }
    rln_k<1><<<Tc, 256>>>(h2, moe, ln3g, ln3b, h3, h3h, h3l);

    // output projection
    tgemm<0,0><<<dim3(1024/128, Tc/128), 256>>>(h3h, h3l, whi+OFF_WOUT, wlo+OFF_WOUT,
        out, nullptr, nullptr, Tc, 1024, 1024, nullptr, nullptr, nullptr, nullptr);
}

// round 5
// speedup vs baseline: 6.5846x; 1.4997x over previous
#include <cuda_runtime.h>
#include <cuda_bf16.h>
#include <math.h>
#include <stdint.h>

#define Bc 4
#define Sc 1024
#define Dc 1024
#define NHc 16
#define DHc 64
#define FFc 4096
#define NEc 8
#define Tc (Bc*Sc)
#define BHc (Bc*NHc)

typedef __nv_bfloat16 bf16;
typedef __nv_bfloat162 bf162;

// ---------------- fp32 scratch ----------------
__device__ float g_qkv[(size_t)Tc*3*Dc];
__device__ float g_r[Sc*Dc];
__device__ float g_sc[(size_t)BHc*Sc*Sc];
__device__ float g_bd[(size_t)BHc*Sc*Sc];
__device__ float g_ao[(size_t)Tc*Dc];
__device__ float g_ff[(size_t)Tc*Dc];
__device__ float g_h1[(size_t)Tc*Dc];
__device__ float g_h2[(size_t)Tc*Dc];
__device__ float g_h3[(size_t)Tc*Dc];
__device__ float g_moe[(size_t)Tc*Dc];
__device__ float g_gate[Tc];
__device__ int   g_cnt[NEc];
__device__ int   g_idx[NEc*Tc];

// ---------------- bf16 hi/lo scratch ----------------
__device__ bf16 g_peh[Sc*Dc],  g_pel[Sc*Dc];
__device__ bf16 g_xh[(size_t)Tc*Dc],  g_xl[(size_t)Tc*Dc];
__device__ bf16 g_quh[(size_t)Tc*Dc], g_qul[(size_t)Tc*Dc];
__device__ bf16 g_qvh[(size_t)Tc*Dc], g_qvl[(size_t)Tc*Dc];
__device__ bf16 g_kh[(size_t)Tc*Dc],  g_kl[(size_t)Tc*Dc];
__device__ bf16 g_vth[(size_t)Tc*Dc], g_vtl[(size_t)Tc*Dc];
__device__ bf16 g_rh[NHc*Sc*DHc],     g_rl[NHc*Sc*DHc];
__device__ bf16 g_ctxh[(size_t)Tc*Dc], g_ctxl[(size_t)Tc*Dc];
__device__ bf16 g_h1h[(size_t)Tc*Dc], g_h1l[(size_t)Tc*Dc];
__device__ bf16 g_h2h[(size_t)Tc*Dc], g_h2l[(size_t)Tc*Dc];
__device__ bf16 g_h3h[(size_t)Tc*Dc], g_h3l[(size_t)Tc*Dc];
__device__ bf16 g_ffhh[(size_t)Tc*FFc], g_ffhl[(size_t)Tc*FFc];

// transposed split-bf16 weights: [N,K] layout, hi + lo
#define OFF_QKV  0
#define OFF_WR   3145728
#define OFF_WO   4194304
#define OFF_FF1  5242880
#define OFF_FF2  9437184
#define OFF_WE1  13631488
#define OFF_WE2  47185920
#define OFF_WOUT 80740352
#define WTOT     81788928
__device__ bf16 g_whi[WTOT];
__device__ bf16 g_wlo[WTOT];

// ---------------- helpers ----------------
__device__ __forceinline__ uint32_t smem_u32(const void* p) {
    uint32_t a;
    asm("{ .reg .u64 t; cvta.to.shared.u64 t, %1; cvt.u32.u64 %0, t; }" : "=r"(a) : "l"(p));
    return a;
}
__device__ __forceinline__ void ldm4(uint32_t* r, uint32_t a) {
    asm volatile("ldmatrix.sync.aligned.m8n8.x4.shared.b16 {%0,%1,%2,%3}, [%4];"
        : "=r"(r[0]), "=r"(r[1]), "=r"(r[2]), "=r"(r[3]) : "r"(a));
}
__device__ __forceinline__ void mma_bf16(float* c, const uint32_t* a, uint32_t b0, uint32_t b1) {
    asm volatile("mma.sync.aligned.m16n8k16.row.col.f32.bf16.bf16.f32 "
        "{%0,%1,%2,%3}, {%4,%5,%6,%7}, {%8,%9}, {%0,%1,%2,%3};"
        : "+f"(c[0]), "+f"(c[1]), "+f"(c[2]), "+f"(c[3])
        : "r"(a[0]), "r"(a[1]), "r"(a[2]), "r"(a[3]), "r"(b0), "r"(b1));
}
__device__ __forceinline__ void split1(float v, bf16& h, bf16& l) {
    h = __float2bfloat16_rn(v);
    l = __float2bfloat16_rn(v - __bfloat162float(h));
}
__device__ __forceinline__ void split2(float x, float y, bf162& h, bf162& l) {
    h = __floats2bfloat162_rn(x, y);
    float2 hf = __bfloat1622float2(h);
    l = __floats2bfloat162_rn(x - hf.x, y - hf.y);
}

// ---------------- weight transpose + split: W[K,N] -> hi/lo [N,K] ----------------
__global__ __launch_bounds__(256)
void wconv(const float* __restrict__ W, bf16* __restrict__ hi,
           bf16* __restrict__ lo, int K, int N)
{
    __shared__ float t[32][33];
    int tx = threadIdx.x & 31, ty = threadIdx.x >> 5;
    int kb = blockIdx.y * 32, nb = blockIdx.x * 32;
    size_t eoffW = (size_t)blockIdx.z * K * N;
    #pragma unroll
    for (int j = 0; j < 4; j++)
        t[ty + j*8][tx] = W[eoffW + (size_t)(kb + ty + j*8) * N + nb + tx];
    __syncthreads();
    #pragma unroll
    for (int j = 0; j < 4; j++) {
        int n = nb + ty + j*8, k = kb + tx;
        float v = t[tx][ty + j*8];
        bf16 h, l; split1(v, h, l);
        hi[eoffW + (size_t)n*K + k] = h;
        lo[eoffW + (size_t)n*K + k] = l;
    }
}

// ---------------- elementwise fp32 -> bf16 hi/lo ----------------
__global__ __launch_bounds__(256)
void econv(const float* __restrict__ src, bf16* __restrict__ hi, bf16* __restrict__ lo)
{
    size_t i = (size_t)blockIdx.x * 1024 + threadIdx.x;
    #pragma unroll
    for (int l = 0; l < 4; l++) {
        float v = src[i + l*256];
        bf16 h, lo_;
        split1(v, h, lo_);
        hi[i + l*256] = h; lo[i + l*256] = lo_;
    }
}

// ---------------- positional embedding (bf16 hi/lo) ----------------
__global__ void pe_kernel(bf16* __restrict__ peh, bf16* __restrict__ pel) {
    int i = blockIdx.x;
    float pos = (float)(Sc - 1 - i);
    #pragma unroll
    for (int l = 0; l < 4; l++) {
        int c = threadIdx.x + l * 256;
        int j = (c < Dc/2) ? c : (c - Dc/2);
        float invf = expf(-logf(10000.f) * ((float)(2*j) / (float)Dc));
        float a = pos * invf;
        float v = (c < Dc/2) ? sinf(a) : cosf(a);
        bf16 h, lo; split1(v, h, lo);
        peh[(size_t)i*Dc + c] = h; pel[(size_t)i*Dc + c] = lo;
    }
}

// ---------------- attention operand prep ----------------
__global__ __launch_bounds__(256)
void qprep(const float* __restrict__ qkv, const float* __restrict__ ub, const float* __restrict__ vb,
           bf16* quh, bf16* qul, bf16* qvh, bf16* qvl, bf16* kh, bf16* kl)
{
    int tok = blockIdx.x;
    int b = tok >> 10, s = tok & 1023;
    #pragma unroll
    for (int l = 0; l < 4; l++) {
        int c = threadIdx.x + l*256;
        int h = c >> 6, d = c & 63;
        size_t src = (size_t)tok*3072 + c;
        float qf = qkv[src], kf = qkv[src + 1024];
        size_t dst = ((size_t)(b*NHc + h)*Sc + s)*64 + d;
        bf16 hh, ll;
        split1(qf + ub[c], hh, ll); quh[dst] = hh; qul[dst] = ll;
        split1(qf + vb[c], hh, ll); qvh[dst] = hh; qvl[dst] = ll;
        split1(kf, hh, ll);         kh[dst] = hh;  kl[dst] = ll;
    }
}
__global__ __launch_bounds__(256)
void vtprep(const float* __restrict__ qkv, bf16* vth, bf16* vtl)
{
    __shared__ float t[32][33];
    int tx = threadIdx.x & 31, ty = threadIdx.x >> 5;
    int s0 = blockIdx.x * 32, d0 = blockIdx.y * 32, bh = blockIdx.z;
    int b = bh >> 4, h = bh & 15;
    #pragma unroll
    for (int j = 0; j < 4; j++) {
        int sl = ty + j*8;
        t[sl][tx] = qkv[((size_t)(b*Sc + s0 + sl))*3072 + 2048 + h*64 + d0 + tx];
    }
    __syncthreads();
    #pragma unroll
    for (int j = 0; j < 4; j++) {
        int dl = ty + j*8;
        float v = t[tx][dl];
        bf16 hh, ll; split1(v, hh, ll);
        size_t dst = ((size_t)bh*64 + d0 + dl)*Sc + s0 + tx;
        vth[dst] = hh; vtl[dst] = ll;
    }
}
__global__ __launch_bounds__(256)
void rprep(const float* __restrict__ r, bf16* rh, bf16* rl)
{
    int s = blockIdx.x;
    #pragma unroll
    for (int l = 0; l < 4; l++) {
        int c = threadIdx.x + l*256;
        int h = c >> 6, d = c & 63;
        float v = r[(size_t)s*Dc + c];
        bf16 hh, ll; split1(v, hh, ll);
        size_t dst = ((size_t)h*Sc + s)*64 + d;
        rh[dst] = hh; rl[dst] = ll;
    }
}

// ---------------- HMMA split-bf16 GEMM: C[M,N] = A[M,K] @ B^T ----------------
// Expert batching: blockIdx.z = expert; B/bias advance by eStrideB/eStrideBias,
// gather/cnt indexed per expert. For dense GEMMs launch with gridDim.z=1, strides 0.
// EPI: 0=none 1=+bias 2=relu(+bias) 3=(+bias)*rowScale ; OBF: 0=fp32 C, 1=bf16 hi/lo C
template<int EPI, int OBF>
__global__ __launch_bounds__(256)
void tgemm(const bf16* __restrict__ Ahi, const bf16* __restrict__ Alo,
           const bf16* __restrict__ Bhi, const bf16* __restrict__ Blo,
           float* __restrict__ C, bf16* __restrict__ Chi, bf16* __restrict__ Clo,
           int M, int N, int K,
           const float* __restrict__ bias, const float* __restrict__ rowScale,
           const int* __restrict__ gatherBase, const int* __restrict__ cntBase,
           size_t eStrideB, int eStrideBias)
{
    __shared__ bf16 AsH[128][40];
    __shared__ bf16 AsL[128][40];
    __shared__ bf16 BsH[128][40];
    __shared__ bf16 BsL[128][40];

    int e = blockIdx.z;
    const int* gather = gatherBase ? gatherBase + e * Tc : nullptr;
    int limit = cntBase ? cntBase[e] : M;
    int m0 = blockIdx.y * 128;
    if (m0 >= limit) return;
    int n0 = blockIdx.x * 128;
    const bf16* BhiE = Bhi + (size_t)e * eStrideB;
    const bf16* BloE = Blo + (size_t)e * eStrideB;
    const float* biasE = (EPI >= 1) ? bias + (size_t)e * eStrideBias : bias;

    int tid = threadIdx.x, wid = tid >> 5, lane = tid & 31;
    int wm = (wid & 3) * 32, wn = (wid >> 2) * 64;

    const bf16 *aph[2], *apl[2], *bph[2], *bpl[2];
    int arow[2], aseg[2], brow[2], bseg[2];
    #pragma unroll
    for (int l = 0; l < 2; l++) {
        int slot = tid + 256*l;
        arow[l] = slot >> 2; aseg[l] = slot & 3;
        int gr = m0 + arow[l];
        aph[l] = nullptr; apl[l] = nullptr;
        if (gr < limit) {
            int sr = gather ? gather[gr] : gr;
            aph[l] = Ahi + (size_t)sr * K + aseg[l] * 8;
            apl[l] = Alo + (size_t)sr * K + aseg[l] * 8;
        }
        brow[l] = slot >> 2; bseg[l] = slot & 3;
        size_t off = (size_t)(n0 + brow[l]) * K + bseg[l] * 8;
        bph[l] = BhiE + off; bpl[l] = BloE + off;
    }

    int t4 = lane >> 3;
    int rr = (lane & 7) + (t4 & 1) * 8;
    int cc = (t4 >> 1) * 8;
    uint32_t baAH = smem_u32(AsH), baAL = smem_u32(AsL);
    uint32_t baBH = smem_u32(BsH), baBL = smem_u32(BsL);

    float acc[2][8][4];
    #pragma unroll
    for (int i = 0; i < 2; i++)
        #pragma unroll
        for (int j = 0; j < 8; j++)
            #pragma unroll
            for (int q = 0; q < 4; q++) acc[i][j][q] = 0.f;

    uint4 avh[2], avl[2], bvh[2], bvl[2];
    const uint4 z4 = make_uint4(0,0,0,0);
    int Kc = K >> 5;

    #pragma unroll
    for (int l = 0; l < 2; l++) {
        avh[l] = aph[l] ? *(const uint4*)(aph[l]) : z4;
        avl[l] = apl[l] ? *(const uint4*)(apl[l]) : z4;
        bvh[l] = *(const uint4*)(bph[l]);
        bvl[l] = *(const uint4*)(bpl[l]);
    }

    for (int c = 0; c < Kc; c++) {
        #pragma unroll
        for (int l = 0; l < 2; l++) {
            *(uint4*)&AsH[arow[l]][aseg[l]*8] = avh[l];
            *(uint4*)&AsL[arow[l]][aseg[l]*8] = avl[l];
            *(uint4*)&BsH[brow[l]][bseg[l]*8] = bvh[l];
            *(uint4*)&BsL[brow[l]][bseg[l]*8] = bvl[l];
        }
        __syncthreads();

        if (c + 1 < Kc) {
            int ko = (c + 1) * 32;
            #pragma unroll
            for (int l = 0; l < 2; l++) {
                avh[l] = aph[l] ? *(const uint4*)(aph[l] + ko) : z4;
                avl[l] = apl[l] ? *(const uint4*)(apl[l] + ko) : z4;
                bvh[l] = *(const uint4*)(bph[l] + ko);
                bvl[l] = *(const uint4*)(bpl[l] + ko);
            }
        }

        #pragma unroll
        for (int k16 = 0; k16 < 32; k16 += 16) {
            uint32_t aH[2][4], aL[2][4];
            #pragma unroll
            for (int mi = 0; mi < 2; mi++) {
                uint32_t off = ((uint32_t)(wm + mi*16 + rr) * 40u + (uint32_t)(k16 + cc)) * 2u;
                ldm4(aH[mi], baAH + off);
                ldm4(aL[mi], baAL + off);
            }
            uint32_t bH[4][4], bL[4][4];
            #pragma unroll
            for (int ni = 0; ni < 4; ni++) {
                uint32_t off = ((uint32_t)(wn + ni*16 + rr) * 40u + (uint32_t)(k16 + cc)) * 2u;
                ldm4(bH[ni], baBH + off);
                ldm4(bL[ni], baBL + off);
            }
            #pragma unroll
            for (int mi = 0; mi < 2; mi++)
                #pragma unroll
                for (int ni = 0; ni < 4; ni++)
                    #pragma unroll
                    for (int h = 0; h < 2; h++) {
                        int j = ni*2 + h;
                        mma_bf16(acc[mi][j], aH[mi], bH[ni][h], bH[ni][h+2]);
                        mma_bf16(acc[mi][j], aH[mi], bL[ni][h], bL[ni][h+2]);
                        mma_bf16(acc[mi][j], aL[mi], bH[ni][h], bH[ni][h+2]);
                    }
        }
        __syncthreads();
    }

    #pragma unroll
    for (int mi = 0; mi < 2; mi++) {
        #pragma unroll
        for (int half = 0; half < 2; half++) {
            int gr = m0 + wm + mi*16 + (lane >> 2) + half*8;
            if (gr >= limit) continue;
            int crow = gather ? gather[gr] : gr;
            float rs = 1.f;
            if (EPI == 3) rs = rowScale[crow];
            #pragma unroll
            for (int j = 0; j < 8; j++) {
                int col = n0 + wn + j*8 + (lane & 3)*2;
                float vx = acc[mi][j][half*2 + 0];
                float vy = acc[mi][j][half*2 + 1];
                if (EPI >= 1) { vx += biasE[col]; vy += biasE[col+1]; }
                if (EPI == 2) { vx = fmaxf(vx, 0.f); vy = fmaxf(vy, 0.f); }
                if (EPI == 3) { vx *= rs; vy *= rs; }
                if (OBF == 0) {
                    *(float2*)(C + (size_t)crow * N + col) = make_float2(vx, vy);
                } else {
                    bf162 h, l; split2(vx, vy, h, l);
                    *(bf162*)(Chi + (size_t)crow * N + col) = h;
                    *(bf162*)(Clo + (size_t)crow * N + col) = l;
                }
            }
        }
    }
}

// ---------------- attention scores via HMMA (64x64 tile) ----------------
__global__ __launch_bounds__(256)
void attn_sc(const bf16* __restrict__ Ah_, const bf16* __restrict__ Al_,
             const bf16* __restrict__ Bh_, const bf16* __restrict__ Bl_,
             float* __restrict__ out, int mode)
{
    int kt = blockIdx.x, qt = blockIdx.y, bh = blockIdx.z;
    if (mode == 0 && kt > qt) return;
    if (mode == 1 && (qt*64 + kt*64 + 126) < (Sc - 1)) return;

    __shared__ bf16 Ahs[64][72], Als[64][72];
    __shared__ bf16 Bhs[64][72], Bls[64][72];

    size_t aoff = ((size_t)bh*Sc + qt*64)*64;
    size_t boff = mode ? ((size_t)(bh & 15)*Sc + kt*64)*64 : ((size_t)bh*Sc + kt*64)*64;

    int tid = threadIdx.x, wid = tid >> 5, lane = tid & 31;
    #pragma unroll
    for (int l = 0; l < 2; l++) {
        int slot = tid + 256*l;
        int row = slot >> 3, seg = slot & 7;
        *(uint4*)&Ahs[row][seg*8] = *(const uint4*)(Ah_ + aoff + row*64 + seg*8);
        *(uint4*)&Als[row][seg*8] = *(const uint4*)(Al_ + aoff + row*64 + seg*8);
        *(uint4*)&Bhs[row][seg*8] = *(const uint4*)(Bh_ + boff + row*64 + seg*8);
        *(uint4*)&Bls[row][seg*8] = *(const uint4*)(Bl_ + boff + row*64 + seg*8);
    }
    __syncthreads();

    int wm = (wid & 3) * 16, wn = (wid >> 2) * 32;
    int t4 = lane >> 3;
    int rr = (lane & 7) + (t4 & 1) * 8;
    int cc = (t4 >> 1) * 8;
    uint32_t baAH = smem_u32(Ahs), baAL = smem_u32(Als);
    uint32_t baBH = smem_u32(Bhs), baBL = smem_u32(Bls);

    float acc[4][4];
    #pragma unroll
    for (int j = 0; j < 4; j++)
        #pragma unroll
        for (int q = 0; q < 4; q++) acc[j][q] = 0.f;

    #pragma unroll
    for (int k16 = 0; k16 < 64; k16 += 16) {
        uint32_t aH[4], aL[4];
        {
            uint32_t off = ((uint32_t)(wm + rr) * 72u + (uint32_t)(k16 + cc)) * 2u;
            ldm4(aH, baAH + off);
            ldm4(aL, baAL + off);
        }
        uint32_t bH[2][4], bL[2][4];
        #pragma unroll
        for (int ni = 0; ni < 2; ni++) {
            uint32_t off = ((uint32_t)(wn + ni*16 + rr) * 72u + (uint32_t)(k16 + cc)) * 2u;
            ldm4(bH[ni], baBH + off);
            ldm4(bL[ni], baBL + off);
        }
        #pragma unroll
        for (int ni = 0; ni < 2; ni++)
            #pragma unroll
            for (int h = 0; h < 2; h++) {
                int j = ni*2 + h;
                mma_bf16(acc[j], aH, bH[ni][h], bH[ni][h+2]);
                mma_bf16(acc[j], aH, bL[ni][h], bL[ni][h+2]);
                mma_bf16(acc[j], aL, bH[ni][h], bH[ni][h+2]);
            }
    }

    #pragma unroll
    for (int half = 0; half < 2; half++) {
        int q = qt*64 + wm + (lane >> 2) + half*8;
        #pragma unroll
        for (int j = 0; j < 4; j++) {
            int k = kt*64 + wn + j*8 + (lane & 3)*2;
            *(float2*)(out + ((size_t)bh*Sc + q)*Sc + k) =
                make_float2(acc[j][half*2], acc[j][half*2+1]);
        }
    }
}

// ---------------- rel_shift + causal softmax (in place on sc) ----------------
__global__ __launch_bounds__(256)
void softmax_k(float* __restrict__ sc, const float* __restrict__ bd)
{
    int q = blockIdx.x, bh = blockIdx.y;
    size_t base = ((size_t)bh*Sc + q)*Sc;
    int tid = threadIdx.x;
    __shared__ float red[256];

    float v[4];
    float mx = -1e30f;
    #pragma unroll
    for (int l = 0; l < 4; l++) {
        int k = tid + l*256;
        float val = -1e30f;
        if (k <= q) {
            int j = k - q + Sc - 1;
            val = (sc[base + k] + bd[base + j]) * 0.125f;
        }
        v[l] = val;
        mx = fmaxf(mx, val);
    }
    red[tid] = mx; __syncthreads();
    for (int s = 128; s > 0; s >>= 1) { if (tid < s) red[tid] = fmaxf(red[tid], red[tid+s]); __syncthreads(); }
    float m = red[0]; __syncthreads();

    float sum = 0.f;
    #pragma unroll
    for (int l = 0; l < 4; l++) {
        int k = tid + l*256;
        float e = (k <= q) ? expf(v[l] - m) : 0.f;
        v[l] = e; sum += e;
    }
    red[tid] = sum; __syncthreads();
    for (int s = 128; s > 0; s >>= 1) { if (tid < s) red[tid] += red[tid+s]; __syncthreads(); }
    float inv = 1.f / red[0];

    #pragma unroll
    for (int l = 0; l < 4; l++) {
        int k = tid + l*256;
        sc[base + k] = v[l] * inv;
    }
}

// ---------------- ctx = probs @ V via HMMA (64q x 64d tile) ----------------
__global__ __launch_bounds__(256)
void attn_av(const float* __restrict__ probs, const bf16* __restrict__ vth,
             const bf16* __restrict__ vtl, bf16* __restrict__ ctxh, bf16* __restrict__ ctxl)
{
    int qt = blockIdx.x, bh = blockIdx.y;
    int b = bh >> 4, h = bh & 15;
    int q0 = qt * 64;

    __shared__ bf16 Phs[64][72], Pls[64][72];
    __shared__ bf16 Vhs[64][72], Vls[64][72];

    int tid = threadIdx.x, wid = tid >> 5, lane = tid & 31;
    int wm = (wid & 3) * 16, wn = (wid >> 2) * 32;
    int t4 = lane >> 3;
    int rr = (lane & 7) + (t4 & 1) * 8;
    int cc = (t4 >> 1) * 8;
    uint32_t baPH = smem_u32(Phs), baPL = smem_u32(Pls);
    uint32_t baVH = smem_u32(Vhs), baVL = smem_u32(Vls);

    float acc[4][4];
    #pragma unroll
    for (int j = 0; j < 4; j++)
        #pragma unroll
        for (int q = 0; q < 4; q++) acc[j][q] = 0.f;

    int kmax = (qt + 1) * 64;
    for (int s0 = 0; s0 < kmax; s0 += 64) {
        __syncthreads();
        #pragma unroll
        for (int l = 0; l < 4; l++) {
            int slot = tid + 256*l;
            int row = slot >> 4, seg = slot & 15;
            float4 p = *(const float4*)(probs + ((size_t)bh*Sc + q0 + row)*Sc + s0 + seg*4);
            bf162 h0, l0, h1, l1;
            split2(p.x, p.y, h0, l0);
            split2(p.z, p.w, h1, l1);
            *(bf162*)&Phs[row][seg*4]     = h0;
            *(bf162*)&Phs[row][seg*4 + 2] = h1;
            *(bf162*)&Pls[row][seg*4]     = l0;
            *(bf162*)&Pls[row][seg*4 + 2] = l1;
        }
        #pragma unroll
        for (int l = 0; l < 2; l++) {
            int slot = tid + 256*l;
            int row = slot >> 3, seg = slot & 7;
            size_t src = ((size_t)bh*64 + row)*Sc + s0 + seg*8;
            *(uint4*)&Vhs[row][seg*8] = *(const uint4*)(vth + src);
            *(uint4*)&Vls[row][seg*8] = *(const uint4*)(vtl + src);
        }
        __syncthreads();

        #pragma unroll
        for (int k16 = 0; k16 < 64; k16 += 16) {
            uint32_t aH[4], aL[4];
            {
                uint32_t off = ((uint32_t)(wm + rr) * 72u + (uint32_t)(k16 + cc)) * 2u;
                ldm4(aH, baPH + off);
                ldm4(aL, baPL + off);
            }
            uint32_t bH[2][4], bL[2][4];
            #pragma unroll
            for (int ni = 0; ni < 2; ni++) {
                uint32_t off = ((uint32_t)(wn + ni*16 + rr) * 72u + (uint32_t)(k16 + cc)) * 2u;
                ldm4(bH[ni], baVH + off);
                ldm4(bL[ni], baVL + off);
            }
            #pragma unroll
            for (int ni = 0; ni < 2; ni++)
                #pragma unroll
                for (int hb = 0; hb < 2; hb++) {
                    int j = ni*2 + hb;
                    mma_bf16(acc[j], aH, bH[ni][hb], bH[ni][hb+2]);
                    mma_bf16(acc[j], aH, bL[ni][hb], bL[ni][hb+2]);
                    mma_bf16(acc[j], aL, bH[ni][hb], bH[ni][hb+2]);
                }
        }
    }

    #pragma unroll
    for (int half = 0; half < 2; half++) {
        int tok = b*Sc + q0 + wm + (lane >> 2) + half*8;
        #pragma unroll
        for (int j = 0; j < 4; j++) {
            int col = h*64 + wn + j*8 + (lane & 3)*2;
            bf162 hh, ll;
            split2(acc[j][half*2], acc[j][half*2+1], hh, ll);
            *(bf162*)(ctxh + (size_t)tok*Dc + col) = hh;
            *(bf162*)(ctxl + (size_t)tok*Dc + col) = ll;
        }
    }
}

// ---------------- residual + layernorm ----------------
template<int OBF>
__global__ __launch_bounds__(256)
void rln_k(const float* __restrict__ x, const float* __restrict__ y,
           const float* __restrict__ g, const float* __restrict__ bta,
           float* __restrict__ out, bf16* __restrict__ oh, bf16* __restrict__ ol)
{
    int row = blockIdx.x;
    int tid = threadIdx.x;
    __shared__ float red[256];
    float v[4];
    float s = 0.f, ss = 0.f;
    #pragma unroll
    for (int l = 0; l < 4; l++) {
        size_t idx = (size_t)row*Dc + tid + l*256;
        float val = x[idx] + y[idx];
        v[l] = val; s += val; ss += val*val;
    }
    red[tid] = s; __syncthreads();
    for (int st = 128; st > 0; st >>= 1) { if (tid < st) red[tid] += red[tid+st]; __syncthreads(); }
    float mean = red[0] * (1.f/Dc); __syncthreads();
    red[tid] = ss; __syncthreads();
    for (int st = 128; st > 0; st >>= 1) { if (tid < st) red[tid] += red[tid+st]; __syncthreads(); }
    float var = red[0] * (1.f/Dc) - mean*mean;
    float inv = rsqrtf(var + 1e-5f);
    #pragma unroll
    for (int l = 0; l < 4; l++) {
        int c = tid + l*256;
        float o = (v[l] - mean) * inv * g[c] + bta[c];
        out[(size_t)row*Dc + c] = o;
        if (OBF) {
            bf16 hh, ll; split1(o, hh, ll);
            oh[(size_t)row*Dc + c] = hh;
            ol[(size_t)row*Dc + c] = ll;
        }
    }
}

// ---------------- router ----------------
__global__ void zero_cnt(int* cnt) { if (threadIdx.x < NEc) cnt[threadIdx.x] = 0; }

__global__ __launch_bounds__(256)
void router_k(const float* __restrict__ h2, const float* __restrict__ Wg,
              float* __restrict__ gate, int* __restrict__ cnt, int* __restrict__ idxlist)
{
    int warp = (blockIdx.x * blockDim.x + threadIdx.x) >> 5;
    int lane = threadIdx.x & 31;
    if (warp >= Tc) return;
    const float* hrow = h2 + (size_t)warp * Dc;
    float logit[NEc];
    #pragma unroll
    for (int e = 0; e < NEc; e++) {
        float p = 0.f;
        for (int d = lane; d < Dc; d += 32) p += hrow[d] * Wg[d*NEc + e];
        #pragma unroll
        for (int off = 16; off > 0; off >>= 1) p += __shfl_xor_sync(0xFFFFFFFFu, p, off);
        logit[e] = p;
    }
    float m = logit[0]; int am = 0;
    #pragma unroll
    for (int e = 1; e < NEc; e++) if (logit[e] > m) { m = logit[e]; am = e; }
    float sum = 0.f;
    #pragma unroll
    for (int e = 0; e < NEc; e++) sum += expf(logit[e] - m);
    if (lane == 0) {
        gate[warp] = 1.f / sum;
        int pos = atomicAdd(&cnt[am], 1);
        idxlist[am*Tc + pos] = warp;
    }
}

// ---------------- launch ----------------
extern "C" void kernel_launch(void* const* d_in, const int* in_sizes, int n_in,
                              void* d_out, int out_size)
{
    const float* x    = (const float*)d_in[0];
    const float* Wqkv = (const float*)d_in[1];
    const float* Wo   = (const float*)d_in[2];
    const float* Wr   = (const float*)d_in[3];
    const float* u_b  = (const float*)d_in[4];
    const float* v_b  = (const float*)d_in[5];
    const float* ln1g = (const float*)d_in[6];
    const float* ln1b = (const float*)d_in[7];
    const float* Wff1 = (const float*)d_in[8];
    const float* bff1 = (const float*)d_in[9];
    const float* Wff2 = (const float*)d_in[10];
    const float* bff2 = (const float*)d_in[11];
    const float* ln2g = (const float*)d_in[12];
    const float* ln2b = (const float*)d_in[13];
    const float* Wg   = (const float*)d_in[14];
    const float* We1  = (const float*)d_in[15];
    const float* be1  = (const float*)d_in[16];
    const float* We2  = (const float*)d_in[17];
    const float* be2  = (const float*)d_in[18];
    const float* ln3g = (const float*)d_in[19];
    const float* ln3b = (const float*)d_in[20];
    const float* Wout = (const float*)d_in[21];
    float* out = (float*)d_out;

    float *qkv, *r, *sc, *bd, *ao, *ff, *h1, *h2, *h3, *moe, *gate;
    int *cnt, *idx;
    bf16 *whi, *wlo, *peh, *pel, *xh, *xl;
    bf16 *quh, *qul, *qvh, *qvl, *kh, *kl, *vth, *vtl, *rh, *rl;
    bf16 *ctxh, *ctxl, *h1h, *h1l, *h2h, *h2l, *h3h, *h3l, *ffhh, *ffhl;

    cudaGetSymbolAddress((void**)&qkv, g_qkv);
    cudaGetSymbolAddress((void**)&r,   g_r);
    cudaGetSymbolAddress((void**)&sc,  g_sc);
    cudaGetSymbolAddress((void**)&bd,  g_bd);
    cudaGetSymbolAddress((void**)&ao,  g_ao);
    cudaGetSymbolAddress((void**)&ff,  g_ff);
    cudaGetSymbolAddress((void**)&h1,  g_h1);
    cudaGetSymbolAddress((void**)&h2,  g_h2);
    cudaGetSymbolAddress((void**)&h3,  g_h3);
    cudaGetSymbolAddress((void**)&moe, g_moe);
    cudaGetSymbolAddress((void**)&gate,g_gate);
    cudaGetSymbolAddress((void**)&cnt, g_cnt);
    cudaGetSymbolAddress((void**)&idx, g_idx);
    cudaGetSymbolAddress((void**)&whi, g_whi);
    cudaGetSymbolAddress((void**)&wlo, g_wlo);
    cudaGetSymbolAddress((void**)&peh, g_peh);
    cudaGetSymbolAddress((void**)&pel, g_pel);
    cudaGetSymbolAddress((void**)&xh,  g_xh);
    cudaGetSymbolAddress((void**)&xl,  g_xl);
    cudaGetSymbolAddress((void**)&quh, g_quh);
    cudaGetSymbolAddress((void**)&qul, g_qul);
    cudaGetSymbolAddress((void**)&qvh, g_qvh);
    cudaGetSymbolAddress((void**)&qvl, g_qvl);
    cudaGetSymbolAddress((void**)&kh,  g_kh);
    cudaGetSymbolAddress((void**)&kl,  g_kl);
    cudaGetSymbolAddress((void**)&vth, g_vth);
    cudaGetSymbolAddress((void**)&vtl, g_vtl);
    cudaGetSymbolAddress((void**)&rh,  g_rh);
    cudaGetSymbolAddress((void**)&rl,  g_rl);
    cudaGetSymbolAddress((void**)&ctxh,g_ctxh);
    cudaGetSymbolAddress((void**)&ctxl,g_ctxl);
    cudaGetSymbolAddress((void**)&h1h, g_h1h);
    cudaGetSymbolAddress((void**)&h1l, g_h1l);
    cudaGetSymbolAddress((void**)&h2h, g_h2h);
    cudaGetSymbolAddress((void**)&h2l, g_h2l);
    cudaGetSymbolAddress((void**)&h3h, g_h3h);
    cudaGetSymbolAddress((void**)&h3l, g_h3l);
    cudaGetSymbolAddress((void**)&ffhh,g_ffhh);
    cudaGetSymbolAddress((void**)&ffhl,g_ffhl);

    // weight transpose + split (experts batched via blockIdx.z)
    wconv<<<dim3(3072/32, 1024/32), 256>>>(Wqkv, whi+OFF_QKV,  wlo+OFF_QKV,  1024, 3072);
    wconv<<<dim3(1024/32, 1024/32), 256>>>(Wr,   whi+OFF_WR,   wlo+OFF_WR,   1024, 1024);
    wconv<<<dim3(1024/32, 1024/32), 256>>>(Wo,   whi+OFF_WO,   wlo+OFF_WO,   1024, 1024);
    wconv<<<dim3(4096/32, 1024/32), 256>>>(Wff1, whi+OFF_FF1,  wlo+OFF_FF1,  1024, 4096);
    wconv<<<dim3(1024/32, 4096/32), 256>>>(Wff2, whi+OFF_FF2,  wlo+OFF_FF2,  4096, 1024);
    wconv<<<dim3(1024/32, 1024/32), 256>>>(Wout, whi+OFF_WOUT, wlo+OFF_WOUT, 1024, 1024);
    wconv<<<dim3(4096/32, 1024/32, NEc), 256>>>(We1, whi+OFF_WE1, wlo+OFF_WE1, 1024, 4096);
    wconv<<<dim3(1024/32, 4096/32, NEc), 256>>>(We2, whi+OFF_WE2, wlo+OFF_WE2, 4096, 1024);

    pe_kernel<<<Sc, 256>>>(peh, pel);
    econv<<<Tc, 256>>>(x, xh, xl);

    // projections
    tgemm<0,0><<<dim3(3072/128, Tc/128), 256>>>(xh, xl, whi+OFF_QKV, wlo+OFF_QKV,
        qkv, nullptr, nullptr, Tc, 3072, 1024, nullptr, nullptr, nullptr, nullptr, 0, 0);
    tgemm<0,0><<<dim3(1024/128, Sc/128), 256>>>(peh, pel, whi+OFF_WR, wlo+OFF_WR,
        r, nullptr, nullptr, Sc, 1024, 1024, nullptr, nullptr, nullptr, nullptr, 0, 0);

    // attention prep
    qprep<<<Tc, 256>>>(qkv, u_b, v_b, quh, qul, qvh, qvl, kh, kl);
    vtprep<<<dim3(Sc/32, 2, BHc), 256>>>(qkv, vth, vtl);
    rprep<<<Sc, 256>>>(r, rh, rl);

    // attention
    attn_sc<<<dim3(16, 16, BHc), 256>>>(quh, qul, kh, kl, sc, 0);
    attn_sc<<<dim3(16, 16, BHc), 256>>>(qvh, qvl, rh, rl, bd, 1);
    softmax_k<<<dim3(Sc, BHc), 256>>>(sc, bd);
    attn_av<<<dim3(16, BHc), 256>>>(sc, vth, vtl, ctxh, ctxl);
    tgemm<0,0><<<dim3(1024/128, Tc/128), 256>>>(ctxh, ctxl, whi+OFF_WO, wlo+OFF_WO,
        ao, nullptr, nullptr, Tc, 1024, 1024, nullptr, nullptr, nullptr, nullptr, 0, 0);
    rln_k<1><<<Tc, 256>>>(x, ao, ln1g, ln1b, h1, h1h, h1l);

    // FFN
    tgemm<2,1><<<dim3(4096/128, Tc/128), 256>>>(h1h, h1l, whi+OFF_FF1, wlo+OFF_FF1,
        nullptr, ffhh, ffhl, Tc, 4096, 1024, bff1, nullptr, nullptr, nullptr, 0, 0);
    tgemm<1,0><<<dim3(1024/128, Tc/128), 256>>>(ffhh, ffhl, whi+OFF_FF2, wlo+OFF_FF2,
        ff, nullptr, nullptr, Tc, 1024, 4096, bff2, nullptr, nullptr, nullptr, 0, 0);
    rln_k<1><<<Tc, 256>>>(h1, ff, ln2g, ln2b, h2, h2h, h2l);

    // MoE: all experts in two launches (blockIdx.z = expert)
    zero_cnt<<<1, 32>>>(cnt);
    router_k<<<Tc/8, 256>>>(h2, Wg, gate, cnt, idx);
    tgemm<2,1><<<dim3(4096/128, Tc/128, NEc), 256>>>(
        h2h, h2l, whi+OFF_WE1, wlo+OFF_WE1,
        nullptr, ffhh, ffhl, Tc, 4096, 1024, be1, nullptr, idx, cnt,
        (size_t)FFc*Dc, FFc);
    tgemm<3,0><<<dim3(1024/128, Tc/128, NEc), 256>>>(
        ffhh, ffhl, whi+OFF_WE2, wlo+OFF_WE2,
        moe, nullptr, nullptr, Tc, 1024, 4096, be2, gate, idx, cnt,
        (size_t)Dc*FFc, Dc);
    rln_k<1><<<Tc, 256>>>(h2, moe, ln3g, ln3b, h3, h3h, h3l);

    // output projection
    tgemm<0,0><<<dim3(1024/128, Tc/128), 256>>>(h3h, h3l, whi+OFF_WOUT, wlo+OFF_WOUT,
        out, nullptr, nullptr, Tc, 1024, 1024, nullptr, nullptr, nullptr, nullptr, 0, 0);
}

// round 6
// speedup vs baseline: 6.9923x; 1.0619x over previous
#include <cuda_runtime.h>
#include <cuda_bf16.h>
#include <math.h>
#include <stdint.h>

#define Bc 4
#define Sc 1024
#define Dc 1024
#define NHc 16
#define DHc 64
#define FFc 4096
#define NEc 8
#define Tc (Bc*Sc)
#define BHc (Bc*NHc)

typedef __nv_bfloat16 bf16;
typedef __nv_bfloat162 bf162;

// ---------------- fp32 scratch ----------------
__device__ float g_qkv[(size_t)Tc*3*Dc];
__device__ float g_r[Sc*Dc];
__device__ float g_sc[(size_t)BHc*Sc*Sc];
__device__ float g_bd[(size_t)BHc*Sc*Sc];
__device__ float g_ao[(size_t)Tc*Dc];
__device__ float g_ff[(size_t)Tc*Dc];
__device__ float g_h1[(size_t)Tc*Dc];
__device__ float g_h2[(size_t)Tc*Dc];
__device__ float g_h3[(size_t)Tc*Dc];
__device__ float g_moe[(size_t)Tc*Dc];
__device__ float g_gate[Tc];
__device__ int   g_cnt[NEc];
__device__ int   g_idx[NEc*Tc];

// ---------------- bf16 hi/lo scratch ----------------
__device__ bf16 g_peh[Sc*Dc],  g_pel[Sc*Dc];
__device__ bf16 g_xh[(size_t)Tc*Dc],  g_xl[(size_t)Tc*Dc];
__device__ bf16 g_quh[(size_t)Tc*Dc], g_qul[(size_t)Tc*Dc];
__device__ bf16 g_qvh[(size_t)Tc*Dc], g_qvl[(size_t)Tc*Dc];
__device__ bf16 g_kh[(size_t)Tc*Dc],  g_kl[(size_t)Tc*Dc];
__device__ bf16 g_vth[(size_t)Tc*Dc], g_vtl[(size_t)Tc*Dc];
__device__ bf16 g_rh[NHc*Sc*DHc],     g_rl[NHc*Sc*DHc];
__device__ bf16 g_ctxh[(size_t)Tc*Dc], g_ctxl[(size_t)Tc*Dc];
__device__ bf16 g_h1h[(size_t)Tc*Dc], g_h1l[(size_t)Tc*Dc];
__device__ bf16 g_h2h[(size_t)Tc*Dc], g_h2l[(size_t)Tc*Dc];
__device__ bf16 g_h3h[(size_t)Tc*Dc], g_h3l[(size_t)Tc*Dc];
__device__ bf16 g_ffhh[(size_t)Tc*FFc], g_ffhl[(size_t)Tc*FFc];

// transposed split-bf16 weights: [N,K] layout, hi + lo
#define OFF_QKV  0
#define OFF_WR   3145728
#define OFF_WO   4194304
#define OFF_FF1  5242880
#define OFF_FF2  9437184
#define OFF_WE1  13631488
#define OFF_WE2  47185920
#define OFF_WOUT 80740352
#define WTOT     81788928
__device__ bf16 g_whi[WTOT];
__device__ bf16 g_wlo[WTOT];

// ---------------- helpers ----------------
__device__ __forceinline__ uint32_t smem_u32(const void* p) {
    uint32_t a;
    asm("{ .reg .u64 t; cvta.to.shared.u64 t, %1; cvt.u32.u64 %0, t; }" : "=r"(a) : "l"(p));
    return a;
}
__device__ __forceinline__ void ldm4(uint32_t* r, uint32_t a) {
    asm volatile("ldmatrix.sync.aligned.m8n8.x4.shared.b16 {%0,%1,%2,%3}, [%4];"
        : "=r"(r[0]), "=r"(r[1]), "=r"(r[2]), "=r"(r[3]) : "r"(a));
}
__device__ __forceinline__ void mma_bf16(float* c, const uint32_t* a, uint32_t b0, uint32_t b1) {
    asm volatile("mma.sync.aligned.m16n8k16.row.col.f32.bf16.bf16.f32 "
        "{%0,%1,%2,%3}, {%4,%5,%6,%7}, {%8,%9}, {%0,%1,%2,%3};"
        : "+f"(c[0]), "+f"(c[1]), "+f"(c[2]), "+f"(c[3])
        : "r"(a[0]), "r"(a[1]), "r"(a[2]), "r"(a[3]), "r"(b0), "r"(b1));
}
__device__ __forceinline__ void split1(float v, bf16& h, bf16& l) {
    h = __float2bfloat16_rn(v);
    l = __float2bfloat16_rn(v - __bfloat162float(h));
}
__device__ __forceinline__ void split2(float x, float y, bf162& h, bf162& l) {
    h = __floats2bfloat162_rn(x, y);
    float2 hf = __bfloat1622float2(h);
    l = __floats2bfloat162_rn(x - hf.x, y - hf.y);
}
#define CPA16(dst, src, sz) \
    asm volatile("cp.async.cg.shared.global [%0], [%1], 16, %2;" :: "r"(dst), "l"(src), "r"(sz))
#define CPC()  asm volatile("cp.async.commit_group;" ::: "memory")
#define CPW1() asm volatile("cp.async.wait_group 1;" ::: "memory")
#define CPW0() asm volatile("cp.async.wait_group 0;" ::: "memory")

// ---------------- weight transpose + split: W[K,N] -> hi/lo [N,K] ----------------
__global__ __launch_bounds__(256)
void wconv(const float* __restrict__ W, bf16* __restrict__ hi,
           bf16* __restrict__ lo, int K, int N)
{
    __shared__ float t[32][33];
    int tx = threadIdx.x & 31, ty = threadIdx.x >> 5;
    int kb = blockIdx.y * 32, nb = blockIdx.x * 32;
    size_t eoffW = (size_t)blockIdx.z * K * N;
    #pragma unroll
    for (int j = 0; j < 4; j++)
        t[ty + j*8][tx] = W[eoffW + (size_t)(kb + ty + j*8) * N + nb + tx];
    __syncthreads();
    #pragma unroll
    for (int j = 0; j < 4; j++) {
        int n = nb + ty + j*8, k = kb + tx;
        float v = t[tx][ty + j*8];
        bf16 h, l; split1(v, h, l);
        hi[eoffW + (size_t)n*K + k] = h;
        lo[eoffW + (size_t)n*K + k] = l;
    }
}

// ---------------- elementwise fp32 -> bf16 hi/lo ----------------
__global__ __launch_bounds__(256)
void econv(const float* __restrict__ src, bf16* __restrict__ hi, bf16* __restrict__ lo)
{
    size_t i = (size_t)blockIdx.x * 1024 + threadIdx.x;
    #pragma unroll
    for (int l = 0; l < 4; l++) {
        float v = src[i + l*256];
        bf16 h, lo_;
        split1(v, h, lo_);
        hi[i + l*256] = h; lo[i + l*256] = lo_;
    }
}

// ---------------- positional embedding (bf16 hi/lo) ----------------
__global__ void pe_kernel(bf16* __restrict__ peh, bf16* __restrict__ pel) {
    int i = blockIdx.x;
    float pos = (float)(Sc - 1 - i);
    #pragma unroll
    for (int l = 0; l < 4; l++) {
        int c = threadIdx.x + l * 256;
        int j = (c < Dc/2) ? c : (c - Dc/2);
        float invf = expf(-logf(10000.f) * ((float)(2*j) / (float)Dc));
        float a = pos * invf;
        float v = (c < Dc/2) ? sinf(a) : cosf(a);
        bf16 h, lo; split1(v, h, lo);
        peh[(size_t)i*Dc + c] = h; pel[(size_t)i*Dc + c] = lo;
    }
}

// ---------------- attention operand prep (q-side pre-scaled by 0.125) ----------------
__global__ __launch_bounds__(256)
void qprep(const float* __restrict__ qkv, const float* __restrict__ ub, const float* __restrict__ vb,
           bf16* quh, bf16* qul, bf16* qvh, bf16* qvl, bf16* kh, bf16* kl)
{
    int tok = blockIdx.x;
    int b = tok >> 10, s = tok & 1023;
    #pragma unroll
    for (int l = 0; l < 4; l++) {
        int c = threadIdx.x + l*256;
        int h = c >> 6, d = c & 63;
        size_t src = (size_t)tok*3072 + c;
        float qf = qkv[src], kf = qkv[src + 1024];
        size_t dst = ((size_t)(b*NHc + h)*Sc + s)*64 + d;
        bf16 hh, ll;
        split1((qf + ub[c]) * 0.125f, hh, ll); quh[dst] = hh; qul[dst] = ll;
        split1((qf + vb[c]) * 0.125f, hh, ll); qvh[dst] = hh; qvl[dst] = ll;
        split1(kf, hh, ll);                   kh[dst] = hh;  kl[dst] = ll;
    }
}
__global__ __launch_bounds__(256)
void vtprep(const float* __restrict__ qkv, bf16* vth, bf16* vtl)
{
    __shared__ float t[32][33];
    int tx = threadIdx.x & 31, ty = threadIdx.x >> 5;
    int s0 = blockIdx.x * 32, d0 = blockIdx.y * 32, bh = blockIdx.z;
    int b = bh >> 4, h = bh & 15;
    #pragma unroll
    for (int j = 0; j < 4; j++) {
        int sl = ty + j*8;
        t[sl][tx] = qkv[((size_t)(b*Sc + s0 + sl))*3072 + 2048 + h*64 + d0 + tx];
    }
    __syncthreads();
    #pragma unroll
    for (int j = 0; j < 4; j++) {
        int dl = ty + j*8;
        float v = t[tx][dl];
        bf16 hh, ll; split1(v, hh, ll);
        size_t dst = ((size_t)bh*64 + d0 + dl)*Sc + s0 + tx;
        vth[dst] = hh; vtl[dst] = ll;
    }
}
__global__ __launch_bounds__(256)
void rprep(const float* __restrict__ r, bf16* rh, bf16* rl)
{
    int s = blockIdx.x;
    #pragma unroll
    for (int l = 0; l < 4; l++) {
        int c = threadIdx.x + l*256;
        int h = c >> 6, d = c & 63;
        float v = r[(size_t)s*Dc + c];
        bf16 hh, ll; split1(v, hh, ll);
        size_t dst = ((size_t)h*Sc + s)*64 + d;
        rh[dst] = hh; rl[dst] = ll;
    }
}

// ---------------- HMMA split-bf16 GEMM with cp.async double buffering ----------------
// C[M,N] = A[M,K] @ B^T. blockIdx.z = expert (dense: gridDim.z=1, strides 0).
// Dynamic smem: 2 stages x [AH | AL | BH | BL], each operand 128x40 bf16 (10240 B).
// EPI: 0=none 1=+bias 2=relu(+bias) 3=(+bias)*rowScale ; OBF: 0=fp32 C, 1=bf16 hi/lo C
#define STG_BYTES 40960
#define OPD_BYTES 10240
#define TG_SMEM   (2*STG_BYTES)

template<int EPI, int OBF>
__global__ __launch_bounds__(256, 2)
void tgemm(const bf16* __restrict__ Ahi, const bf16* __restrict__ Alo,
           const bf16* __restrict__ Bhi, const bf16* __restrict__ Blo,
           float* __restrict__ C, bf16* __restrict__ Chi, bf16* __restrict__ Clo,
           int M, int N, int K,
           const float* __restrict__ bias, const float* __restrict__ rowScale,
           const int* __restrict__ gatherBase, const int* __restrict__ cntBase,
           size_t eStrideB, int eStrideBias)
{
    extern __shared__ char sm[];

    int e = blockIdx.z;
    const int* gather = gatherBase ? gatherBase + e * Tc : nullptr;
    int limit = cntBase ? cntBase[e] : M;
    int m0 = blockIdx.y * 128;
    if (m0 >= limit) return;
    int n0 = blockIdx.x * 128;
    const bf16* BhiE = Bhi + (size_t)e * eStrideB;
    const bf16* BloE = Blo + (size_t)e * eStrideB;
    const float* biasE = (EPI >= 1) ? bias + (size_t)e * eStrideBias : bias;

    int tid = threadIdx.x, wid = tid >> 5, lane = tid & 31;
    int wm = (wid & 3) * 32, wn = (wid >> 2) * 64;
    uint32_t sbase = smem_u32(sm);

    // per-thread cp.async lines: 2 per operand-half (128 rows x 4 segs of 16B)
    const bf16 *aph[2], *apl[2], *bph[2], *bpl[2];
    uint32_t soff[2], asz[2];
    #pragma unroll
    for (int l = 0; l < 2; l++) {
        int slot = tid + 256*l;
        int row = slot >> 2, seg = slot & 3;
        soff[l] = (uint32_t)(row * 80 + seg * 16);
        int gr = m0 + row;
        if (gr < limit) {
            int sr = gather ? gather[gr] : gr;
            aph[l] = Ahi + (size_t)sr * K + seg * 8;
            apl[l] = Alo + (size_t)sr * K + seg * 8;
            asz[l] = 16;
        } else {
            aph[l] = Ahi; apl[l] = Alo; asz[l] = 0;   // zero-fill
        }
        size_t off = (size_t)(n0 + row) * K + seg * 8;
        bph[l] = BhiE + off; bpl[l] = BloE + off;
    }

    int t4 = lane >> 3;
    int rr = (lane & 7) + (t4 & 1) * 8;
    int cc = (t4 >> 1) * 8;

    float acc[2][8][4];
    #pragma unroll
    for (int i = 0; i < 2; i++)
        #pragma unroll
        for (int j = 0; j < 8; j++)
            #pragma unroll
            for (int q = 0; q < 4; q++) acc[i][j][q] = 0.f;

    int Kc = K >> 5;

    // prologue: issue stages 0 and 1
    #pragma unroll
    for (int s = 0; s < 2; s++) {
        if (s < Kc) {
            uint32_t b = sbase + s * STG_BYTES;
            int ko = s * 32;
            #pragma unroll
            for (int l = 0; l < 2; l++) {
                CPA16(b + soff[l],               aph[l] + ko, asz[l]);
                CPA16(b + OPD_BYTES + soff[l],   apl[l] + ko, asz[l]);
                CPA16(b + 2*OPD_BYTES + soff[l], bph[l] + ko, 16u);
                CPA16(b + 3*OPD_BYTES + soff[l], bpl[l] + ko, 16u);
            }
            CPC();
        }
    }

    for (int c = 0; c < Kc; c++) {
        if (c + 1 < Kc) { CPW1(); } else { CPW0(); }
        __syncthreads();

        uint32_t sb = sbase + (uint32_t)(c & 1) * STG_BYTES;
        uint32_t baAH = sb, baAL = sb + OPD_BYTES;
        uint32_t baBH = sb + 2*OPD_BYTES, baBL = sb + 3*OPD_BYTES;

        #pragma unroll
        for (int k16 = 0; k16 < 32; k16 += 16) {
            uint32_t aH[2][4], aL[2][4];
            #pragma unroll
            for (int mi = 0; mi < 2; mi++) {
                uint32_t off = ((uint32_t)(wm + mi*16 + rr) * 40u + (uint32_t)(k16 + cc)) * 2u;
                ldm4(aH[mi], baAH + off);
                ldm4(aL[mi], baAL + off);
            }
            uint32_t bH[4][4], bL[4][4];
            #pragma unroll
            for (int ni = 0; ni < 4; ni++) {
                uint32_t off = ((uint32_t)(wn + ni*16 + rr) * 40u + (uint32_t)(k16 + cc)) * 2u;
                ldm4(bH[ni], baBH + off);
                ldm4(bL[ni], baBL + off);
            }
            #pragma unroll
            for (int mi = 0; mi < 2; mi++)
                #pragma unroll
                for (int ni = 0; ni < 4; ni++)
                    #pragma unroll
                    for (int h = 0; h < 2; h++) {
                        int j = ni*2 + h;
                        mma_bf16(acc[mi][j], aH[mi], bH[ni][h], bH[ni][h+2]);
                        mma_bf16(acc[mi][j], aH[mi], bL[ni][h], bL[ni][h+2]);
                        mma_bf16(acc[mi][j], aL[mi], bH[ni][h], bH[ni][h+2]);
                    }
        }
        __syncthreads();

        if (c + 2 < Kc) {
            uint32_t b = sbase + (uint32_t)(c & 1) * STG_BYTES;
            int ko = (c + 2) * 32;
            #pragma unroll
            for (int l = 0; l < 2; l++) {
                CPA16(b + soff[l],               aph[l] + ko, asz[l]);
                CPA16(b + OPD_BYTES + soff[l],   apl[l] + ko, asz[l]);
                CPA16(b + 2*OPD_BYTES + soff[l], bph[l] + ko, 16u);
                CPA16(b + 3*OPD_BYTES + soff[l], bpl[l] + ko, 16u);
            }
            CPC();
        }
    }

    #pragma unroll
    for (int mi = 0; mi < 2; mi++) {
        #pragma unroll
        for (int half = 0; half < 2; half++) {
            int gr = m0 + wm + mi*16 + (lane >> 2) + half*8;
            if (gr >= limit) continue;
            int crow = gather ? gather[gr] : gr;
            float rs = 1.f;
            if (EPI == 3) rs = rowScale[crow];
            #pragma unroll
            for (int j = 0; j < 8; j++) {
                int col = n0 + wn + j*8 + (lane & 3)*2;
                float vx = acc[mi][j][half*2 + 0];
                float vy = acc[mi][j][half*2 + 1];
                if (EPI >= 1) { vx += biasE[col]; vy += biasE[col+1]; }
                if (EPI == 2) { vx = fmaxf(vx, 0.f); vy = fmaxf(vy, 0.f); }
                if (EPI == 3) { vx *= rs; vy *= rs; }
                if (OBF == 0) {
                    *(float2*)(C + (size_t)crow * N + col) = make_float2(vx, vy);
                } else {
                    bf162 h, l; split2(vx, vy, h, l);
                    *(bf162*)(Chi + (size_t)crow * N + col) = h;
                    *(bf162*)(Clo + (size_t)crow * N + col) = l;
                }
            }
        }
    }
}

// ---------------- attention scores via HMMA (64x64 tile) ----------------
__global__ __launch_bounds__(256)
void attn_sc(const bf16* __restrict__ Ah_, const bf16* __restrict__ Al_,
             const bf16* __restrict__ Bh_, const bf16* __restrict__ Bl_,
             float* __restrict__ out, int mode)
{
    int kt = blockIdx.x, qt = blockIdx.y, bh = blockIdx.z;
    if (mode == 0 && kt > qt) return;
    if (mode == 1 && (qt*64 + kt*64 + 126) < (Sc - 1)) return;

    __shared__ bf16 Ahs[64][72], Als[64][72];
    __shared__ bf16 Bhs[64][72], Bls[64][72];

    size_t aoff = ((size_t)bh*Sc + qt*64)*64;
    size_t boff = mode ? ((size_t)(bh & 15)*Sc + kt*64)*64 : ((size_t)bh*Sc + kt*64)*64;

    int tid = threadIdx.x, wid = tid >> 5, lane = tid & 31;
    #pragma unroll
    for (int l = 0; l < 2; l++) {
        int slot = tid + 256*l;
        int row = slot >> 3, seg = slot & 7;
        *(uint4*)&Ahs[row][seg*8] = *(const uint4*)(Ah_ + aoff + row*64 + seg*8);
        *(uint4*)&Als[row][seg*8] = *(const uint4*)(Al_ + aoff + row*64 + seg*8);
        *(uint4*)&Bhs[row][seg*8] = *(const uint4*)(Bh_ + boff + row*64 + seg*8);
        *(uint4*)&Bls[row][seg*8] = *(const uint4*)(Bl_ + boff + row*64 + seg*8);
    }
    __syncthreads();

    int wm = (wid & 3) * 16, wn = (wid >> 2) * 32;
    int t4 = lane >> 3;
    int rr = (lane & 7) + (t4 & 1) * 8;
    int cc = (t4 >> 1) * 8;
    uint32_t baAH = smem_u32(Ahs), baAL = smem_u32(Als);
    uint32_t baBH = smem_u32(Bhs), baBL = smem_u32(Bls);

    float acc[4][4];
    #pragma unroll
    for (int j = 0; j < 4; j++)
        #pragma unroll
        for (int q = 0; q < 4; q++) acc[j][q] = 0.f;

    #pragma unroll
    for (int k16 = 0; k16 < 64; k16 += 16) {
        uint32_t aH[4], aL[4];
        {
            uint32_t off = ((uint32_t)(wm + rr) * 72u + (uint32_t)(k16 + cc)) * 2u;
            ldm4(aH, baAH + off);
            ldm4(aL, baAL + off);
        }
        uint32_t bH[2][4], bL[2][4];
        #pragma unroll
        for (int ni = 0; ni < 2; ni++) {
            uint32_t off = ((uint32_t)(wn + ni*16 + rr) * 72u + (uint32_t)(k16 + cc)) * 2u;
            ldm4(bH[ni], baBH + off);
            ldm4(bL[ni], baBL + off);
        }
        #pragma unroll
        for (int ni = 0; ni < 2; ni++)
            #pragma unroll
            for (int h = 0; h < 2; h++) {
                int j = ni*2 + h;
                mma_bf16(acc[j], aH, bH[ni][h], bH[ni][h+2]);
                mma_bf16(acc[j], aH, bL[ni][h], bL[ni][h+2]);
                mma_bf16(acc[j], aL, bH[ni][h], bH[ni][h+2]);
            }
    }

    #pragma unroll
    for (int half = 0; half < 2; half++) {
        int q = qt*64 + wm + (lane >> 2) + half*8;
        #pragma unroll
        for (int j = 0; j < 4; j++) {
            int k = kt*64 + wn + j*8 + (lane & 3)*2;
            *(float2*)(out + ((size_t)bh*Sc + q)*Sc + k) =
                make_float2(acc[j][half*2], acc[j][half*2+1]);
        }
    }
}

// ---------------- rel_shift + causal softmax (in place on sc; inputs pre-scaled) ----------------
__global__ __launch_bounds__(256)
void softmax_k(float* __restrict__ sc, const float* __restrict__ bd)
{
    int q = blockIdx.x, bh = blockIdx.y;
    size_t base = ((size_t)bh*Sc + q)*Sc;
    int tid = threadIdx.x;
    __shared__ float red[256];

    float v[4];
    float mx = -1e30f;
    #pragma unroll
    for (int l = 0; l < 4; l++) {
        int k = tid + l*256;
        float val = -1e30f;
        if (k <= q) {
            int j = k - q + Sc - 1;
            val = sc[base + k] + bd[base + j];
        }
        v[l] = val;
        mx = fmaxf(mx, val);
    }
    red[tid] = mx; __syncthreads();
    for (int s = 128; s > 0; s >>= 1) { if (tid < s) red[tid] = fmaxf(red[tid], red[tid+s]); __syncthreads(); }
    float m = red[0]; __syncthreads();

    float sum = 0.f;
    #pragma unroll
    for (int l = 0; l < 4; l++) {
        int k = tid + l*256;
        float e = (k <= q) ? expf(v[l] - m) : 0.f;
        v[l] = e; sum += e;
    }
    red[tid] = sum; __syncthreads();
    for (int s = 128; s > 0; s >>= 1) { if (tid < s) red[tid] += red[tid+s]; __syncthreads(); }
    float inv = 1.f / red[0];

    #pragma unroll
    for (int l = 0; l < 4; l++) {
        int k = tid + l*256;
        sc[base + k] = v[l] * inv;
    }
}

// ---------------- ctx = probs @ V via HMMA (64q x 64d tile) ----------------
__global__ __launch_bounds__(256)
void attn_av(const float* __restrict__ probs, const bf16* __restrict__ vth,
             const bf16* __restrict__ vtl, bf16* __restrict__ ctxh, bf16* __restrict__ ctxl)
{
    int qt = blockIdx.x, bh = blockIdx.y;
    int b = bh >> 4, h = bh & 15;
    int q0 = qt * 64;

    __shared__ bf16 Phs[64][72], Pls[64][72];
    __shared__ bf16 Vhs[64][72], Vls[64][72];

    int tid = threadIdx.x, wid = tid >> 5, lane = tid & 31;
    int wm = (wid & 3) * 16, wn = (wid >> 2) * 32;
    int t4 = lane >> 3;
    int rr = (lane & 7) + (t4 & 1) * 8;
    int cc = (t4 >> 1) * 8;
    uint32_t baPH = smem_u32(Phs), baPL = smem_u32(Pls);
    uint32_t baVH = smem_u32(Vhs), baVL = smem_u32(Vls);

    float acc[4][4];
    #pragma unroll
    for (int j = 0; j < 4; j++)
        #pragma unroll
        for (int q = 0; q < 4; q++) acc[j][q] = 0.f;

    int kmax = (qt + 1) * 64;
    for (int s0 = 0; s0 < kmax; s0 += 64) {
        __syncthreads();
        #pragma unroll
        for (int l = 0; l < 4; l++) {
            int slot = tid + 256*l;
            int row = slot >> 4, seg = slot & 15;
            float4 p = *(const float4*)(probs + ((size_t)bh*Sc + q0 + row)*Sc + s0 + seg*4);
            bf162 h0, l0, h1, l1;
            split2(p.x, p.y, h0, l0);
            split2(p.z, p.w, h1, l1);
            *(bf162*)&Phs[row][seg*4]     = h0;
            *(bf162*)&Phs[row][seg*4 + 2] = h1;
            *(bf162*)&Pls[row][seg*4]     = l0;
            *(bf162*)&Pls[row][seg*4 + 2] = l1;
        }
        #pragma unroll
        for (int l = 0; l < 2; l++) {
            int slot = tid + 256*l;
            int row = slot >> 3, seg = slot & 7;
            size_t src = ((size_t)bh*64 + row)*Sc + s0 + seg*8;
            *(uint4*)&Vhs[row][seg*8] = *(const uint4*)(vth + src);
            *(uint4*)&Vls[row][seg*8] = *(const uint4*)(vtl + src);
        }
        __syncthreads();

        #pragma unroll
        for (int k16 = 0; k16 < 64; k16 += 16) {
            uint32_t aH[4], aL[4];
            {
                uint32_t off = ((uint32_t)(wm + rr) * 72u + (uint32_t)(k16 + cc)) * 2u;
                ldm4(aH, baPH + off);
                ldm4(aL, baPL + off);
            }
            uint32_t bH[2][4], bL[2][4];
            #pragma unroll
            for (int ni = 0; ni < 2; ni++) {
                uint32_t off = ((uint32_t)(wn + ni*16 + rr) * 72u + (uint32_t)(k16 + cc)) * 2u;
                ldm4(bH[ni], baVH + off);
                ldm4(bL[ni], baVL + off);
            }
            #pragma unroll
            for (int ni = 0; ni < 2; ni++)
                #pragma unroll
                for (int hb = 0; hb < 2; hb++) {
                    int j = ni*2 + hb;
                    mma_bf16(acc[j], aH, bH[ni][hb], bH[ni][hb+2]);
                    mma_bf16(acc[j], aH, bL[ni][hb], bL[ni][hb+2]);
                    mma_bf16(acc[j], aL, bH[ni][hb], bH[ni][hb+2]);
                }
        }
    }

    #pragma unroll
    for (int half = 0; half < 2; half++) {
        int tok = b*Sc + q0 + wm + (lane >> 2) + half*8;
        #pragma unroll
        for (int j = 0; j < 4; j++) {
            int col = h*64 + wn + j*8 + (lane & 3)*2;
            bf162 hh, ll;
            split2(acc[j][half*2], acc[j][half*2+1], hh, ll);
            *(bf162*)(ctxh + (size_t)tok*Dc + col) = hh;
            *(bf162*)(ctxl + (size_t)tok*Dc + col) = ll;
        }
    }
}

// ---------------- residual + layernorm ----------------
template<int OBF>
__global__ __launch_bounds__(256)
void rln_k(const float* __restrict__ x, const float* __restrict__ y,
           const float* __restrict__ g, const float* __restrict__ bta,
           float* __restrict__ out, bf16* __restrict__ oh, bf16* __restrict__ ol)
{
    int row = blockIdx.x;
    int tid = threadIdx.x;
    __shared__ float red[256];
    float v[4];
    float s = 0.f, ss = 0.f;
    #pragma unroll
    for (int l = 0; l < 4; l++) {
        size_t idx = (size_t)row*Dc + tid + l*256;
        float val = x[idx] + y[idx];
        v[l] = val; s += val; ss += val*val;
    }
    red[tid] = s; __syncthreads();
    for (int st = 128; st > 0; st >>= 1) { if (tid < st) red[tid] += red[tid+st]; __syncthreads(); }
    float mean = red[0] * (1.f/Dc); __syncthreads();
    red[tid] = ss; __syncthreads();
    for (int st = 128; st > 0; st >>= 1) { if (tid < st) red[tid] += red[tid+st]; __syncthreads(); }
    float var = red[0] * (1.f/Dc) - mean*mean;
    float inv = rsqrtf(var + 1e-5f);
    #pragma unroll
    for (int l = 0; l < 4; l++) {
        int c = tid + l*256;
        float o = (v[l] - mean) * inv * g[c] + bta[c];
        out[(size_t)row*Dc + c] = o;
        if (OBF) {
            bf16 hh, ll; split1(o, hh, ll);
            oh[(size_t)row*Dc + c] = hh;
            ol[(size_t)row*Dc + c] = ll;
        }
    }
}

// ---------------- router ----------------
__global__ void zero_cnt(int* cnt) { if (threadIdx.x < NEc) cnt[threadIdx.x] = 0; }

__global__ __launch_bounds__(256)
void router_k(const float* __restrict__ h2, const float* __restrict__ Wg,
              float* __restrict__ gate, int* __restrict__ cnt, int* __restrict__ idxlist)
{
    int warp = (blockIdx.x * blockDim.x + threadIdx.x) >> 5;
    int lane = threadIdx.x & 31;
    if (warp >= Tc) return;
    const float* hrow = h2 + (size_t)warp * Dc;
    float logit[NEc];
    #pragma unroll
    for (int e = 0; e < NEc; e++) {
        float p = 0.f;
        for (int d = lane; d < Dc; d += 32) p += hrow[d] * Wg[d*NEc + e];
        #pragma unroll
        for (int off = 16; off > 0; off >>= 1) p += __shfl_xor_sync(0xFFFFFFFFu, p, off);
        logit[e] = p;
    }
    float m = logit[0]; int am = 0;
    #pragma unroll
    for (int e = 1; e < NEc; e++) if (logit[e] > m) { m = logit[e]; am = e; }
    float sum = 0.f;
    #pragma unroll
    for (int e = 0; e < NEc; e++) sum += expf(logit[e] - m);
    if (lane == 0) {
        gate[warp] = 1.f / sum;
        int pos = atomicAdd(&cnt[am], 1);
        idxlist[am*Tc + pos] = warp;
    }
}

// ---------------- launch ----------------
extern "C" void kernel_launch(void* const* d_in, const int* in_sizes, int n_in,
                              void* d_out, int out_size)
{
    const float* x    = (const float*)d_in[0];
    const float* Wqkv = (const float*)d_in[1];
    const float* Wo   = (const float*)d_in[2];
    const float* Wr   = (const float*)d_in[3];
    const float* u_b  = (const float*)d_in[4];
    const float* v_b  = (const float*)d_in[5];
    const float* ln1g = (const float*)d_in[6];
    const float* ln1b = (const float*)d_in[7];
    const float* Wff1 = (const float*)d_in[8];
    const float* bff1 = (const float*)d_in[9];
    const float* Wff2 = (const float*)d_in[10];
    const float* bff2 = (const float*)d_in[11];
    const float* ln2g = (const float*)d_in[12];
    const float* ln2b = (const float*)d_in[13];
    const float* Wg   = (const float*)d_in[14];
    const float* We1  = (const float*)d_in[15];
    const float* be1  = (const float*)d_in[16];
    const float* We2  = (const float*)d_in[17];
    const float* be2  = (const float*)d_in[18];
    const float* ln3g = (const float*)d_in[19];
    const float* ln3b = (const float*)d_in[20];
    const float* Wout = (const float*)d_in[21];
    float* out = (float*)d_out;

    static int smemSet = 0;
    if (!smemSet) {
        cudaFuncSetAttribute(tgemm<0,0>, cudaFuncAttributeMaxDynamicSharedMemorySize, TG_SMEM);
        cudaFuncSetAttribute(tgemm<1,0>, cudaFuncAttributeMaxDynamicSharedMemorySize, TG_SMEM);
        cudaFuncSetAttribute(tgemm<2,1>, cudaFuncAttributeMaxDynamicSharedMemorySize, TG_SMEM);
        cudaFuncSetAttribute(tgemm<3,0>, cudaFuncAttributeMaxDynamicSharedMemorySize, TG_SMEM);
        smemSet = 1;
    }

    float *qkv, *r, *sc, *bd, *ao, *ff, *h1, *h2, *h3, *moe, *gate;
    int *cnt, *idx;
    bf16 *whi, *wlo, *peh, *pel, *xh, *xl;
    bf16 *quh, *qul, *qvh, *qvl, *kh, *kl, *vth, *vtl, *rh, *rl;
    bf16 *ctxh, *ctxl, *h1h, *h1l, *h2h, *h2l, *h3h, *h3l, *ffhh, *ffhl;

    cudaGetSymbolAddress((void**)&qkv, g_qkv);
    cudaGetSymbolAddress((void**)&r,   g_r);
    cudaGetSymbolAddress((void**)&sc,  g_sc);
    cudaGetSymbolAddress((void**)&bd,  g_bd);
    cudaGetSymbolAddress((void**)&ao,  g_ao);
    cudaGetSymbolAddress((void**)&ff,  g_ff);
    cudaGetSymbolAddress((void**)&h1,  g_h1);
    cudaGetSymbolAddress((void**)&h2,  g_h2);
    cudaGetSymbolAddress((void**)&h3,  g_h3);
    cudaGetSymbolAddress((void**)&moe, g_moe);
    cudaGetSymbolAddress((void**)&gate,g_gate);
    cudaGetSymbolAddress((void**)&cnt, g_cnt);
    cudaGetSymbolAddress((void**)&idx, g_idx);
    cudaGetSymbolAddress((void**)&whi, g_whi);
    cudaGetSymbolAddress((void**)&wlo, g_wlo);
    cudaGetSymbolAddress((void**)&peh, g_peh);
    cudaGetSymbolAddress((void**)&pel, g_pel);
    cudaGetSymbolAddress((void**)&xh,  g_xh);
    cudaGetSymbolAddress((void**)&xl,  g_xl);
    cudaGetSymbolAddress((void**)&quh, g_quh);
    cudaGetSymbolAddress((void**)&qul, g_qul);
    cudaGetSymbolAddress((void**)&qvh, g_qvh);
    cudaGetSymbolAddress((void**)&qvl, g_qvl);
    cudaGetSymbolAddress((void**)&kh,  g_kh);
    cudaGetSymbolAddress((void**)&kl,  g_kl);
    cudaGetSymbolAddress((void**)&vth, g_vth);
    cudaGetSymbolAddress((void**)&vtl, g_vtl);
    cudaGetSymbolAddress((void**)&rh,  g_rh);
    cudaGetSymbolAddress((void**)&rl,  g_rl);
    cudaGetSymbolAddress((void**)&ctxh,g_ctxh);
    cudaGetSymbolAddress((void**)&ctxl,g_ctxl);
    cudaGetSymbolAddress((void**)&h1h, g_h1h);
    cudaGetSymbolAddress((void**)&h1l, g_h1l);
    cudaGetSymbolAddress((void**)&h2h, g_h2h);
    cudaGetSymbolAddress((void**)&h2l, g_h2l);
    cudaGetSymbolAddress((void**)&h3h, g_h3h);
    cudaGetSymbolAddress((void**)&h3l, g_h3l);
    cudaGetSymbolAddress((void**)&ffhh,g_ffhh);
    cudaGetSymbolAddress((void**)&ffhl,g_ffhl);

    // weight transpose + split (experts batched via blockIdx.z)
    wconv<<<dim3(3072/32, 1024/32), 256>>>(Wqkv, whi+OFF_QKV,  wlo+OFF_QKV,  1024, 3072);
    wconv<<<dim3(1024/32, 1024/32), 256>>>(Wr,   whi+OFF_WR,   wlo+OFF_WR,   1024, 1024);
    wconv<<<dim3(1024/32, 1024/32), 256>>>(Wo,   whi+OFF_WO,   wlo+OFF_WO,   1024, 1024);
    wconv<<<dim3(4096/32, 1024/32), 256>>>(Wff1, whi+OFF_FF1,  wlo+OFF_FF1,  1024, 4096);
    wconv<<<dim3(1024/32, 4096/32), 256>>>(Wff2, whi+OFF_FF2,  wlo+OFF_FF2,  4096, 1024);
    wconv<<<dim3(1024/32, 1024/32), 256>>>(Wout, whi+OFF_WOUT, wlo+OFF_WOUT, 1024, 1024);
    wconv<<<dim3(4096/32, 1024/32, NEc), 256>>>(We1, whi+OFF_WE1, wlo+OFF_WE1, 1024, 4096);
    wconv<<<dim3(1024/32, 4096/32, NEc), 256>>>(We2, whi+OFF_WE2, wlo+OFF_WE2, 4096, 1024);

    pe_kernel<<<Sc, 256>>>(peh, pel);
    econv<<<Tc, 256>>>(x, xh, xl);

    // projections
    tgemm<0,0><<<dim3(3072/128, Tc/128), 256, TG_SMEM>>>(xh, xl, whi+OFF_QKV, wlo+OFF_QKV,
        qkv, nullptr, nullptr, Tc, 3072, 1024, nullptr, nullptr, nullptr, nullptr, 0, 0);
    tgemm<0,0><<<dim3(1024/128, Sc/128), 256, TG_SMEM>>>(peh, pel, whi+OFF_WR, wlo+OFF_WR,
        r, nullptr, nullptr, Sc, 1024, 1024, nullptr, nullptr, nullptr, nullptr, 0, 0);

    // attention prep
    qprep<<<Tc, 256>>>(qkv, u_b, v_b, quh, qul, qvh, qvl, kh, kl);
    vtprep<<<dim3(Sc/32, 2, BHc), 256>>>(qkv, vth, vtl);
    rprep<<<Sc, 256>>>(r, rh, rl);

    // attention
    attn_sc<<<dim3(16, 16, BHc), 256>>>(quh, qul, kh, kl, sc, 0);
    attn_sc<<<dim3(16, 16, BHc), 256>>>(qvh, qvl, rh, rl, bd, 1);
    softmax_k<<<dim3(Sc, BHc), 256>>>(sc, bd);
    attn_av<<<dim3(16, BHc), 256>>>(sc, vth, vtl, ctxh, ctxl);
    tgemm<0,0><<<dim3(1024/128, Tc/128), 256, TG_SMEM>>>(ctxh, ctxl, whi+OFF_WO, wlo+OFF_WO,
        ao, nullptr, nullptr, Tc, 1024, 1024, nullptr, nullptr, nullptr, nullptr, 0, 0);
    rln_k<1><<<Tc, 256>>>(x, ao, ln1g, ln1b, h1, h1h, h1l);

    // FFN
    tgemm<2,1><<<dim3(4096/128, Tc/128), 256, TG_SMEM>>>(h1h, h1l, whi+OFF_FF1, wlo+OFF_FF1,
        nullptr, ffhh, ffhl, Tc, 4096, 1024, bff1, nullptr, nullptr, nullptr, 0, 0);
    tgemm<1,0><<<dim3(1024/128, Tc/128), 256, TG_SMEM>>>(ffhh, ffhl, whi+OFF_FF2, wlo+OFF_FF2,
        ff, nullptr, nullptr, Tc, 1024, 4096, bff2, nullptr, nullptr, nullptr, 0, 0);
    rln_k<1><<<Tc, 256>>>(h1, ff, ln2g, ln2b, h2, h2h, h2l);

    // MoE: all experts in two launches (blockIdx.z = expert)
    zero_cnt<<<1, 32>>>(cnt);
    router_k<<<Tc/8, 256>>>(h2, Wg, gate, cnt, idx);
    tgemm<2,1><<<dim3(4096/128, Tc/128, NEc), 256, TG_SMEM>>>(
        h2h, h2l, whi+OFF_WE1, wlo+OFF_WE1,
        nullptr, ffhh, ffhl, Tc, 4096, 1024, be1, nullptr, idx, cnt,
        (size_t)FFc*Dc, FFc);
    tgemm<3,0><<<dim3(1024/128, Tc/128, NEc), 256, TG_SMEM>>>(
        ffhh, ffhl, whi+OFF_WE2, wlo+OFF_WE2,
        moe, nullptr, nullptr, Tc, 1024, 4096, be2, gate, idx, cnt,
        (size_t)Dc*FFc, Dc);
    rln_k<1><<<Tc, 256>>>(h2, moe, ln3g, ln3b, h3, h3h, h3l);

    // output projection
    tgemm<0,0><<<dim3(1024/128, Tc/128), 256, TG_SMEM>>>(h3h, h3l, whi+OFF_WOUT, wlo+OFF_WOUT,
        out, nullptr, nullptr, Tc, 1024, 1024, nullptr, nullptr, nullptr, nullptr, 0, 0);
}

// round 8
// speedup vs baseline: 7.0542x; 1.0088x over previous
#include <cuda_runtime.h>
#include <cuda_bf16.h>
#include <math.h>
#include <stdint.h>

#define Bc 4
#define Sc 1024
#define Dc 1024
#define NHc 16
#define DHc 64
#define FFc 4096
#define NEc 8
#define Tc (Bc*Sc)
#define BHc (Bc*NHc)

typedef __nv_bfloat16 bf16;
typedef __nv_bfloat162 bf162;

// ---------------- fp32 scratch ----------------
__device__ float g_qkv[(size_t)Tc*3*Dc];
__device__ float g_r[Sc*Dc];
__device__ float g_sc[(size_t)BHc*Sc*Sc];
__device__ float g_bd[(size_t)BHc*Sc*Sc];
__device__ float g_ao[(size_t)Tc*Dc];
__device__ float g_ff[(size_t)Tc*Dc];
__device__ float g_h1[(size_t)Tc*Dc];
__device__ float g_h2[(size_t)Tc*Dc];
__device__ float g_h3[(size_t)Tc*Dc];
__device__ float g_moe[(size_t)Tc*Dc];
__device__ float g_gate[Tc];
__device__ int   g_cnt[NEc];
__device__ int   g_idx[NEc*Tc];

// ---------------- bf16 hi/lo scratch ----------------
__device__ bf16 g_peh[Sc*Dc],  g_pel[Sc*Dc];
__device__ bf16 g_xh[(size_t)Tc*Dc],  g_xl[(size_t)Tc*Dc];
__device__ bf16 g_quh[(size_t)Tc*Dc], g_qul[(size_t)Tc*Dc];
__device__ bf16 g_qvh[(size_t)Tc*Dc], g_qvl[(size_t)Tc*Dc];
__device__ bf16 g_kh[(size_t)Tc*Dc],  g_kl[(size_t)Tc*Dc];
__device__ bf16 g_vth[(size_t)Tc*Dc], g_vtl[(size_t)Tc*Dc];
__device__ bf16 g_rh[NHc*Sc*DHc],     g_rl[NHc*Sc*DHc];
__device__ bf16 g_ctxh[(size_t)Tc*Dc], g_ctxl[(size_t)Tc*Dc];
__device__ bf16 g_h1h[(size_t)Tc*Dc], g_h1l[(size_t)Tc*Dc];
__device__ bf16 g_h2h[(size_t)Tc*Dc], g_h2l[(size_t)Tc*Dc];
__device__ bf16 g_h3h[(size_t)Tc*Dc], g_h3l[(size_t)Tc*Dc];
__device__ bf16 g_ffhh[(size_t)Tc*FFc], g_ffhl[(size_t)Tc*FFc];

// transposed split-bf16 weights: [N,K] layout, hi + lo
#define OFF_QKV  0
#define OFF_WR   3145728
#define OFF_WO   4194304
#define OFF_FF1  5242880
#define OFF_FF2  9437184
#define OFF_WE1  13631488
#define OFF_WE2  47185920
#define OFF_WOUT 80740352
#define WTOT     81788928
__device__ bf16 g_whi[WTOT];
__device__ bf16 g_wlo[WTOT];

// ---------------- helpers ----------------
__device__ __forceinline__ uint32_t smem_u32(const void* p) {
    uint32_t a;
    asm("{ .reg .u64 t; cvta.to.shared.u64 t, %1; cvt.u32.u64 %0, t; }" : "=r"(a) : "l"(p));
    return a;
}
__device__ __forceinline__ void ldm4(uint32_t* r, uint32_t a) {
    asm volatile("ldmatrix.sync.aligned.m8n8.x4.shared.b16 {%0,%1,%2,%3}, [%4];"
        : "=r"(r[0]), "=r"(r[1]), "=r"(r[2]), "=r"(r[3]) : "r"(a));
}
__device__ __forceinline__ void mma_bf16(float* c, const uint32_t* a, uint32_t b0, uint32_t b1) {
    asm volatile("mma.sync.aligned.m16n8k16.row.col.f32.bf16.bf16.f32 "
        "{%0,%1,%2,%3}, {%4,%5,%6,%7}, {%8,%9}, {%0,%1,%2,%3};"
        : "+f"(c[0]), "+f"(c[1]), "+f"(c[2]), "+f"(c[3])
        : "r"(a[0]), "r"(a[1]), "r"(a[2]), "r"(a[3]), "r"(b0), "r"(b1));
}
__device__ __forceinline__ void split1(float v, bf16& h, bf16& l) {
    h = __float2bfloat16_rn(v);
    l = __float2bfloat16_rn(v - __bfloat162float(h));
}
__device__ __forceinline__ void split2(float x, float y, bf162& h, bf162& l) {
    h = __floats2bfloat162_rn(x, y);
    float2 hf = __bfloat1622float2(h);
    l = __floats2bfloat162_rn(x - hf.x, y - hf.y);
}
#define CPA16(dst, src, sz) \
    asm volatile("cp.async.cg.shared.global [%0], [%1], 16, %2;" :: "r"(dst), "l"(src), "r"(sz))
#define CPC()  asm volatile("cp.async.commit_group;" ::: "memory")
#define CPW1() asm volatile("cp.async.wait_group 1;" ::: "memory")
#define CPW0() asm volatile("cp.async.wait_group 0;" ::: "memory")

// ---------------- weight transpose + split: W[K,N] -> hi/lo [N,K] ----------------
// 64x64 tile; smem-transposed; vectorized bf162 stores (full 128B lines per warp).
// Row pad = 66 floats so float2 reads at even element offsets stay 8B-aligned.
__global__ __launch_bounds__(256)
void wconv(const float* __restrict__ W, bf16* __restrict__ hi,
           bf16* __restrict__ lo, int K, int N)
{
    __shared__ float t[64][66];
    int tid = threadIdx.x;
    int nb = blockIdx.x * 64, kb = blockIdx.y * 64;
    size_t eoff = (size_t)blockIdx.z * K * N;

    int j  = tid & 63;       // n within tile
    int r0 = tid >> 6;       // 0..3
    #pragma unroll
    for (int l = 0; l < 16; l++) {
        int i = r0 + l * 4;  // k within tile
        t[j][i] = W[eoff + (size_t)(kb + i) * N + nb + j];
    }
    __syncthreads();

    int lane = tid & 31, w = tid >> 5;
    #pragma unroll
    for (int l = 0; l < 8; l++) {
        int n = w + l * 8;
        float2 v = *(float2*)&t[n][2 * lane];
        bf162 h, lo2; split2(v.x, v.y, h, lo2);
        size_t dst = eoff + (size_t)(nb + n) * K + kb + 2 * lane;
        *(bf162*)(hi + dst) = h;
        *(bf162*)(lo + dst) = lo2;
    }
}

// ---------------- elementwise fp32 -> bf16 hi/lo ----------------
__global__ __launch_bounds__(256)
void econv(const float* __restrict__ src, bf16* __restrict__ hi, bf16* __restrict__ lo)
{
    size_t i = (size_t)blockIdx.x * 1024 + threadIdx.x;
    #pragma unroll
    for (int l = 0; l < 4; l++) {
        float v = src[i + l*256];
        bf16 h, lo_;
        split1(v, h, lo_);
        hi[i + l*256] = h; lo[i + l*256] = lo_;
    }
}

// ---------------- positional embedding (bf16 hi/lo) ----------------
__global__ void pe_kernel(bf16* __restrict__ peh, bf16* __restrict__ pel) {
    int i = blockIdx.x;
    float pos = (float)(Sc - 1 - i);
    #pragma unroll
    for (int l = 0; l < 4; l++) {
        int c = threadIdx.x + l * 256;
        int j = (c < Dc/2) ? c : (c - Dc/2);
        float invf = expf(-logf(10000.f) * ((float)(2*j) / (float)Dc));
        float a = pos * invf;
        float v = (c < Dc/2) ? sinf(a) : cosf(a);
        bf16 h, lo; split1(v, h, lo);
        peh[(size_t)i*Dc + c] = h; pel[(size_t)i*Dc + c] = lo;
    }
}

// ---------------- attention operand prep (q-side pre-scaled by 0.125) ----------------
__global__ __launch_bounds__(256)
void qprep(const float* __restrict__ qkv, const float* __restrict__ ub, const float* __restrict__ vb,
           bf16* quh, bf16* qul, bf16* qvh, bf16* qvl, bf16* kh, bf16* kl)
{
    int tok = blockIdx.x;
    int b = tok >> 10, s = tok & 1023;
    #pragma unroll
    for (int l = 0; l < 4; l++) {
        int c = threadIdx.x + l*256;
        int h = c >> 6, d = c & 63;
        size_t src = (size_t)tok*3072 + c;
        float qf = qkv[src], kf = qkv[src + 1024];
        size_t dst = ((size_t)(b*NHc + h)*Sc + s)*64 + d;
        bf16 hh, ll;
        split1((qf + ub[c]) * 0.125f, hh, ll); quh[dst] = hh; qul[dst] = ll;
        split1((qf + vb[c]) * 0.125f, hh, ll); qvh[dst] = hh; qvl[dst] = ll;
        split1(kf, hh, ll);                   kh[dst] = hh;  kl[dst] = ll;
    }
}
__global__ __launch_bounds__(256)
void vtprep(const float* __restrict__ qkv, bf16* vth, bf16* vtl)
{
    __shared__ float t[32][33];
    int tx = threadIdx.x & 31, ty = threadIdx.x >> 5;
    int s0 = blockIdx.x * 32, d0 = blockIdx.y * 32, bh = blockIdx.z;
    int b = bh >> 4, h = bh & 15;
    #pragma unroll
    for (int j = 0; j < 4; j++) {
        int sl = ty + j*8;
        t[sl][tx] = qkv[((size_t)(b*Sc + s0 + sl))*3072 + 2048 + h*64 + d0 + tx];
    }
    __syncthreads();
    #pragma unroll
    for (int j = 0; j < 4; j++) {
        int dl = ty + j*8;
        float v = t[tx][dl];
        bf16 hh, ll; split1(v, hh, ll);
        size_t dst = ((size_t)bh*64 + d0 + dl)*Sc + s0 + tx;
        vth[dst] = hh; vtl[dst] = ll;
    }
}
__global__ __launch_bounds__(256)
void rprep(const float* __restrict__ r, bf16* rh, bf16* rl)
{
    int s = blockIdx.x;
    #pragma unroll
    for (int l = 0; l < 4; l++) {
        int c = threadIdx.x + l*256;
        int h = c >> 6, d = c & 63;
        float v = r[(size_t)s*Dc + c];
        bf16 hh, ll; split1(v, hh, ll);
        size_t dst = ((size_t)h*Sc + s)*64 + d;
        rh[dst] = hh; rl[dst] = ll;
    }
}

// ---------------- HMMA split-bf16 GEMM with cp.async double buffering ----------------
#define STG_BYTES 40960
#define OPD_BYTES 10240
#define TG_SMEM   (2*STG_BYTES)

template<int EPI, int OBF>
__global__ __launch_bounds__(256, 2)
void tgemm(const bf16* __restrict__ Ahi, const bf16* __restrict__ Alo,
           const bf16* __restrict__ Bhi, const bf16* __restrict__ Blo,
           float* __restrict__ C, bf16* __restrict__ Chi, bf16* __restrict__ Clo,
           int M, int N, int K,
           const float* __restrict__ bias, const float* __restrict__ rowScale,
           const int* __restrict__ gatherBase, const int* __restrict__ cntBase,
           size_t eStrideB, int eStrideBias)
{
    extern __shared__ char sm[];

    int e = blockIdx.z;
    const int* gather = gatherBase ? gatherBase + e * Tc : nullptr;
    int limit = cntBase ? cntBase[e] : M;
    int m0 = blockIdx.y * 128;
    if (m0 >= limit) return;
    int n0 = blockIdx.x * 128;
    const bf16* BhiE = Bhi + (size_t)e * eStrideB;
    const bf16* BloE = Blo + (size_t)e * eStrideB;
    const float* biasE = (EPI >= 1) ? bias + (size_t)e * eStrideBias : bias;

    int tid = threadIdx.x, wid = tid >> 5, lane = tid & 31;
    int wm = (wid & 3) * 32, wn = (wid >> 2) * 64;
    uint32_t sbase = smem_u32(sm);

    const bf16 *aph[2], *apl[2], *bph[2], *bpl[2];
    uint32_t soff[2], asz[2];
    #pragma unroll
    for (int l = 0; l < 2; l++) {
        int slot = tid + 256*l;
        int row = slot >> 2, seg = slot & 3;
        soff[l] = (uint32_t)(row * 80 + seg * 16);
        int gr = m0 + row;
        if (gr < limit) {
            int sr = gather ? gather[gr] : gr;
            aph[l] = Ahi + (size_t)sr * K + seg * 8;
            apl[l] = Alo + (size_t)sr * K + seg * 8;
            asz[l] = 16;
        } else {
            aph[l] = Ahi; apl[l] = Alo; asz[l] = 0;
        }
        size_t off = (size_t)(n0 + row) * K + seg * 8;
        bph[l] = BhiE + off; bpl[l] = BloE + off;
    }

    int t4 = lane >> 3;
    int rr = (lane & 7) + (t4 & 1) * 8;
    int cc = (t4 >> 1) * 8;

    float acc[2][8][4];
    #pragma unroll
    for (int i = 0; i < 2; i++)
        #pragma unroll
        for (int j = 0; j < 8; j++)
            #pragma unroll
            for (int q = 0; q < 4; q++) acc[i][j][q] = 0.f;

    int Kc = K >> 5;

    #pragma unroll
    for (int s = 0; s < 2; s++) {
        if (s < Kc) {
            uint32_t b = sbase + s * STG_BYTES;
            int ko = s * 32;
            #pragma unroll
            for (int l = 0; l < 2; l++) {
                CPA16(b + soff[l],               aph[l] + ko, asz[l]);
                CPA16(b + OPD_BYTES + soff[l],   apl[l] + ko, asz[l]);
                CPA16(b + 2*OPD_BYTES + soff[l], bph[l] + ko, 16u);
                CPA16(b + 3*OPD_BYTES + soff[l], bpl[l] + ko, 16u);
            }
            CPC();
        }
    }

    for (int c = 0; c < Kc; c++) {
        if (c + 1 < Kc) { CPW1(); } else { CPW0(); }
        __syncthreads();

        uint32_t sb = sbase + (uint32_t)(c & 1) * STG_BYTES;
        uint32_t baAH = sb, baAL = sb + OPD_BYTES;
        uint32_t baBH = sb + 2*OPD_BYTES, baBL = sb + 3*OPD_BYTES;

        #pragma unroll
        for (int k16 = 0; k16 < 32; k16 += 16) {
            uint32_t aH[2][4], aL[2][4];
            #pragma unroll
            for (int mi = 0; mi < 2; mi++) {
                uint32_t off = ((uint32_t)(wm + mi*16 + rr) * 40u + (uint32_t)(k16 + cc)) * 2u;
                ldm4(aH[mi], baAH + off);
                ldm4(aL[mi], baAL + off);
            }
            uint32_t bH[4][4], bL[4][4];
            #pragma unroll
            for (int ni = 0; ni < 4; ni++) {
                uint32_t off = ((uint32_t)(wn + ni*16 + rr) * 40u + (uint32_t)(k16 + cc)) * 2u;
                ldm4(bH[ni], baBH + off);
                ldm4(bL[ni], baBL + off);
            }
            #pragma unroll
            for (int mi = 0; mi < 2; mi++)
                #pragma unroll
                for (int ni = 0; ni < 4; ni++)
                    #pragma unroll
                    for (int h = 0; h < 2; h++) {
                        int j = ni*2 + h;
                        mma_bf16(acc[mi][j], aH[mi], bH[ni][h], bH[ni][h+2]);
                        mma_bf16(acc[mi][j], aH[mi], bL[ni][h], bL[ni][h+2]);
                        mma_bf16(acc[mi][j], aL[mi], bH[ni][h], bH[ni][h+2]);
                    }
        }
        __syncthreads();

        if (c + 2 < Kc) {
            uint32_t b = sbase + (uint32_t)(c & 1) * STG_BYTES;
            int ko = (c + 2) * 32;
            #pragma unroll
            for (int l = 0; l < 2; l++) {
                CPA16(b + soff[l],               aph[l] + ko, asz[l]);
                CPA16(b + OPD_BYTES + soff[l],   apl[l] + ko, asz[l]);
                CPA16(b + 2*OPD_BYTES + soff[l], bph[l] + ko, 16u);
                CPA16(b + 3*OPD_BYTES + soff[l], bpl[l] + ko, 16u);
            }
            CPC();
        }
    }

    #pragma unroll
    for (int mi = 0; mi < 2; mi++) {
        #pragma unroll
        for (int half = 0; half < 2; half++) {
            int gr = m0 + wm + mi*16 + (lane >> 2) + half*8;
            if (gr >= limit) continue;
            int crow = gather ? gather[gr] : gr;
            float rs = 1.f;
            if (EPI == 3) rs = rowScale[crow];
            #pragma unroll
            for (int j = 0; j < 8; j++) {
                int col = n0 + wn + j*8 + (lane & 3)*2;
                float vx = acc[mi][j][half*2 + 0];
                float vy = acc[mi][j][half*2 + 1];
                if (EPI >= 1) { vx += biasE[col]; vy += biasE[col+1]; }
                if (EPI == 2) { vx = fmaxf(vx, 0.f); vy = fmaxf(vy, 0.f); }
                if (EPI == 3) { vx *= rs; vy *= rs; }
                if (OBF == 0) {
                    *(float2*)(C + (size_t)crow * N + col) = make_float2(vx, vy);
                } else {
                    bf162 h, l; split2(vx, vy, h, l);
                    *(bf162*)(Chi + (size_t)crow * N + col) = h;
                    *(bf162*)(Clo + (size_t)crow * N + col) = l;
                }
            }
        }
    }
}

// ---------------- attention scores via HMMA (64x64 tile) ----------------
__global__ __launch_bounds__(256)
void attn_sc(const bf16* __restrict__ Ah_, const bf16* __restrict__ Al_,
             const bf16* __restrict__ Bh_, const bf16* __restrict__ Bl_,
             float* __restrict__ out, int mode)
{
    int kt = blockIdx.x, qt = blockIdx.y, bh = blockIdx.z;
    if (mode == 0 && kt > qt) return;
    if (mode == 1 && (qt*64 + kt*64 + 126) < (Sc - 1)) return;

    __shared__ bf16 Ahs[64][72], Als[64][72];
    __shared__ bf16 Bhs[64][72], Bls[64][72];

    size_t aoff = ((size_t)bh*Sc + qt*64)*64;
    size_t boff = mode ? ((size_t)(bh & 15)*Sc + kt*64)*64 : ((size_t)bh*Sc + kt*64)*64;

    int tid = threadIdx.x, wid = tid >> 5, lane = tid & 31;
    #pragma unroll
    for (int l = 0; l < 2; l++) {
        int slot = tid + 256*l;
        int row = slot >> 3, seg = slot & 7;
        *(uint4*)&Ahs[row][seg*8] = *(const uint4*)(Ah_ + aoff + row*64 + seg*8);
        *(uint4*)&Als[row][seg*8] = *(const uint4*)(Al_ + aoff + row*64 + seg*8);
        *(uint4*)&Bhs[row][seg*8] = *(const uint4*)(Bh_ + boff + row*64 + seg*8);
        *(uint4*)&Bls[row][seg*8] = *(const uint4*)(Bl_ + boff + row*64 + seg*8);
    }
    __syncthreads();

    int wm = (wid & 3) * 16, wn = (wid >> 2) * 32;
    int t4 = lane >> 3;
    int rr = (lane & 7) + (t4 & 1) * 8;
    int cc = (t4 >> 1) * 8;
    uint32_t baAH = smem_u32(Ahs), baAL = smem_u32(Als);
    uint32_t baBH = smem_u32(Bhs), baBL = smem_u32(Bls);

    float acc[4][4];
    #pragma unroll
    for (int j = 0; j < 4; j++)
        #pragma unroll
        for (int q = 0; q < 4; q++) acc[j][q] = 0.f;

    #pragma unroll
    for (int k16 = 0; k16 < 64; k16 += 16) {
        uint32_t aH[4], aL[4];
        {
            uint32_t off = ((uint32_t)(wm + rr) * 72u + (uint32_t)(k16 + cc)) * 2u;
            ldm4(aH, baAH + off);
            ldm4(aL, baAL + off);
        }
        uint32_t bH[2][4], bL[2][4];
        #pragma unroll
        for (int ni = 0; ni < 2; ni++) {
            uint32_t off = ((uint32_t)(wn + ni*16 + rr) * 72u + (uint32_t)(k16 + cc)) * 2u;
            ldm4(bH[ni], baBH + off);
            ldm4(bL[ni], baBL + off);
        }
        #pragma unroll
        for (int ni = 0; ni < 2; ni++)
            #pragma unroll
            for (int h = 0; h < 2; h++) {
                int j = ni*2 + h;
                mma_bf16(acc[j], aH, bH[ni][h], bH[ni][h+2]);
                mma_bf16(acc[j], aH, bL[ni][h], bL[ni][h+2]);
                mma_bf16(acc[j], aL, bH[ni][h], bH[ni][h+2]);
            }
    }

    #pragma unroll
    for (int half = 0; half < 2; half++) {
        int q = qt*64 + wm + (lane >> 2) + half*8;
        #pragma unroll
        for (int j = 0; j < 4; j++) {
            int k = kt*64 + wn + j*8 + (lane & 3)*2;
            *(float2*)(out + ((size_t)bh*Sc + q)*Sc + k) =
                make_float2(acc[j][half*2], acc[j][half*2+1]);
        }
    }
}

// ---------------- rel_shift + causal softmax (in place on sc; inputs pre-scaled) ----------------
__global__ __launch_bounds__(256)
void softmax_k(float* __restrict__ sc, const float* __restrict__ bd)
{
    int q = blockIdx.x, bh = blockIdx.y;
    size_t base = ((size_t)bh*Sc + q)*Sc;
    int tid = threadIdx.x;
    __shared__ float red[256];

    float v[4];
    float mx = -1e30f;
    #pragma unroll
    for (int l = 0; l < 4; l++) {
        int k = tid + l*256;
        float val = -1e30f;
        if (k <= q) {
            int j = k - q + Sc - 1;
            val = sc[base + k] + bd[base + j];
        }
        v[l] = val;
        mx = fmaxf(mx, val);
    }
    red[tid] = mx; __syncthreads();
    for (int s = 128; s > 0; s >>= 1) { if (tid < s) red[tid] = fmaxf(red[tid], red[tid+s]); __syncthreads(); }
    float m = red[0]; __syncthreads();

    float sum = 0.f;
    #pragma unroll
    for (int l = 0; l < 4; l++) {
        int k = tid + l*256;
        float e = (k <= q) ? expf(v[l] - m) : 0.f;
        v[l] = e; sum += e;
    }
    red[tid] = sum; __syncthreads();
    for (int s = 128; s > 0; s >>= 1) { if (tid < s) red[tid] += red[tid+s]; __syncthreads(); }
    float inv = 1.f / red[0];

    // only columns below the q-tile boundary are ever read by attn_av
    int kend = ((q >> 6) + 1) << 6;
    #pragma unroll
    for (int l = 0; l < 4; l++) {
        int k = tid + l*256;
        if (k < kend) sc[base + k] = v[l] * inv;
    }
}

// ---------------- ctx = probs @ V via HMMA (64q x 64d tile) ----------------
__global__ __launch_bounds__(256)
void attn_av(const float* __restrict__ probs, const bf16* __restrict__ vth,
             const bf16* __restrict__ vtl, bf16* __restrict__ ctxh, bf16* __restrict__ ctxl)
{
    int qt = blockIdx.x, bh = blockIdx.y;
    int b = bh >> 4, h = bh & 15;
    int q0 = qt * 64;

    __shared__ bf16 Phs[64][72], Pls[64][72];
    __shared__ bf16 Vhs[64][72], Vls[64][72];

    int tid = threadIdx.x, wid = tid >> 5, lane = tid & 31;
    int wm = (wid & 3) * 16, wn = (wid >> 2) * 32;
    int t4 = lane >> 3;
    int rr = (lane & 7) + (t4 & 1) * 8;
    int cc = (t4 >> 1) * 8;
    uint32_t baPH = smem_u32(Phs), baPL = smem_u32(Pls);
    uint32_t baVH = smem_u32(Vhs), baVL = smem_u32(Vls);

    float acc[4][4];
    #pragma unroll
    for (int j = 0; j < 4; j++)
        #pragma unroll
        for (int q = 0; q < 4; q++) acc[j][q] = 0.f;

    int kmax = (qt + 1) * 64;
    for (int s0 = 0; s0 < kmax; s0 += 64) {
        __syncthreads();
        #pragma unroll
        for (int l = 0; l < 4; l++) {
            int slot = tid + 256*l;
            int row = slot >> 4, seg = slot & 15;
            float4 p = *(const float4*)(probs + ((size_t)bh*Sc + q0 + row)*Sc + s0 + seg*4);
            bf162 h0, l0, h1, l1;
            split2(p.x, p.y, h0, l0);
            split2(p.z, p.w, h1, l1);
            *(bf162*)&Phs[row][seg*4]     = h0;
            *(bf162*)&Phs[row][seg*4 + 2] = h1;
            *(bf162*)&Pls[row][seg*4]     = l0;
            *(bf162*)&Pls[row][seg*4 + 2] = l1;
        }
        #pragma unroll
        for (int l = 0; l < 2; l++) {
            int slot = tid + 256*l;
            int row = slot >> 3, seg = slot & 7;
            size_t src = ((size_t)bh*64 + row)*Sc + s0 + seg*8;
            *(uint4*)&Vhs[row][seg*8] = *(const uint4*)(vth + src);
            *(uint4*)&Vls[row][seg*8] = *(const uint4*)(vtl + src);
        }
        __syncthreads();

        #pragma unroll
        for (int k16 = 0; k16 < 64; k16 += 16) {
            uint32_t aH[4], aL[4];
            {
                uint32_t off = ((uint32_t)(wm + rr) * 72u + (uint32_t)(k16 + cc)) * 2u;
                ldm4(aH, baPH + off);
                ldm4(aL, baPL + off);
            }
            uint32_t bH[2][4], bL[2][4];
            #pragma unroll
            for (int ni = 0; ni < 2; ni++) {
                uint32_t off = ((uint32_t)(wn + ni*16 + rr) * 72u + (uint32_t)(k16 + cc)) * 2u;
                ldm4(bH[ni], baVH + off);
                ldm4(bL[ni], baVL + off);
            }
            #pragma unroll
            for (int ni = 0; ni < 2; ni++)
                #pragma unroll
                for (int hb = 0; hb < 2; hb++) {
                    int j = ni*2 + hb;
                    mma_bf16(acc[j], aH, bH[ni][hb], bH[ni][hb+2]);
                    mma_bf16(acc[j], aH, bL[ni][hb], bL[ni][hb+2]);
                    mma_bf16(acc[j], aL, bH[ni][hb], bH[ni][hb+2]);
                }
        }
    }

    #pragma unroll
    for (int half = 0; half < 2; half++) {
        int tok = b*Sc + q0 + wm + (lane >> 2) + half*8;
        #pragma unroll
        for (int j = 0; j < 4; j++) {
            int col = h*64 + wn + j*8 + (lane & 3)*2;
            bf162 hh, ll;
            split2(acc[j][half*2], acc[j][half*2+1], hh, ll);
            *(bf162*)(ctxh + (size_t)tok*Dc + col) = hh;
            *(bf162*)(ctxl + (size_t)tok*Dc + col) = ll;
        }
    }
}

// ---------------- residual + layernorm ----------------
template<int OBF>
__global__ __launch_bounds__(256)
void rln_k(const float* __restrict__ x, const float* __restrict__ y,
           const float* __restrict__ g, const float* __restrict__ bta,
           float* __restrict__ out, bf16* __restrict__ oh, bf16* __restrict__ ol)
{
    int row = blockIdx.x;
    int tid = threadIdx.x;
    __shared__ float red[256];
    float v[4];
    float s = 0.f, ss = 0.f;
    #pragma unroll
    for (int l = 0; l < 4; l++) {
        size_t idx = (size_t)row*Dc + tid + l*256;
        float val = x[idx] + y[idx];
        v[l] = val; s += val; ss += val*val;
    }
    red[tid] = s; __syncthreads();
    for (int st = 128; st > 0; st >>= 1) { if (tid < st) red[tid] += red[tid+st]; __syncthreads(); }
    float mean = red[0] * (1.f/Dc); __syncthreads();
    red[tid] = ss; __syncthreads();
    for (int st = 128; st > 0; st >>= 1) { if (tid < st) red[tid] += red[tid+st]; __syncthreads(); }
    float var = red[0] * (1.f/Dc) - mean*mean;
    float inv = rsqrtf(var + 1e-5f);
    #pragma unroll
    for (int l = 0; l < 4; l++) {
        int c = tid + l*256;
        float o = (v[l] - mean) * inv * g[c] + bta[c];
        out[(size_t)row*Dc + c] = o;
        if (OBF) {
            bf16 hh, ll; split1(o, hh, ll);
            oh[(size_t)row*Dc + c] = hh;
            ol[(size_t)row*Dc + c] = ll;
        }
    }
}

// ---------------- router ----------------
__global__ void zero_cnt(int* cnt) { if (threadIdx.x < NEc) cnt[threadIdx.x] = 0; }

__global__ __launch_bounds__(256)
void router_k(const float* __restrict__ h2, const float* __restrict__ Wg,
              float* __restrict__ gate, int* __restrict__ cnt, int* __restrict__ idxlist)
{
    int warp = (blockIdx.x * blockDim.x + threadIdx.x) >> 5;
    int lane = threadIdx.x & 31;
    if (warp >= Tc) return;
    const float* hrow = h2 + (size_t)warp * Dc;
    float logit[NEc];
    #pragma unroll
    for (int e = 0; e < NEc; e++) {
        float p = 0.f;
        for (int d = lane; d < Dc; d += 32) p += hrow[d] * Wg[d*NEc + e];
        #pragma unroll
        for (int off = 16; off > 0; off >>= 1) p += __shfl_xor_sync(0xFFFFFFFFu, p, off);
        logit[e] = p;
    }
    float m = logit[0]; int am = 0;
    #pragma unroll
    for (int e = 1; e < NEc; e++) if (logit[e] > m) { m = logit[e]; am = e; }
    float sum = 0.f;
    #pragma unroll
    for (int e = 0; e < NEc; e++) sum += expf(logit[e] - m);
    if (lane == 0) {
        gate[warp] = 1.f / sum;
        int pos = atomicAdd(&cnt[am], 1);
        idxlist[am*Tc + pos] = warp;
    }
}

// ---------------- launch ----------------
extern "C" void kernel_launch(void* const* d_in, const int* in_sizes, int n_in,
                              void* d_out, int out_size)
{
    const float* x    = (const float*)d_in[0];
    const float* Wqkv = (const float*)d_in[1];
    const float* Wo   = (const float*)d_in[2];
    const float* Wr   = (const float*)d_in[3];
    const float* u_b  = (const float*)d_in[4];
    const float* v_b  = (const float*)d_in[5];
    const float* ln1g = (const float*)d_in[6];
    const float* ln1b = (const float*)d_in[7];
    const float* Wff1 = (const float*)d_in[8];
    const float* bff1 = (const float*)d_in[9];
    const float* Wff2 = (const float*)d_in[10];
    const float* bff2 = (const float*)d_in[11];
    const float* ln2g = (const float*)d_in[12];
    const float* ln2b = (const float*)d_in[13];
    const float* Wg   = (const float*)d_in[14];
    const float* We1  = (const float*)d_in[15];
    const float* be1  = (const float*)d_in[16];
    const float* We2  = (const float*)d_in[17];
    const float* be2  = (const float*)d_in[18];
    const float* ln3g = (const float*)d_in[19];
    const float* ln3b = (const float*)d_in[20];
    const float* Wout = (const float*)d_in[21];
    float* out = (float*)d_out;

    static int smemSet = 0;
    if (!smemSet) {
        cudaFuncSetAttribute(tgemm<0,0>, cudaFuncAttributeMaxDynamicSharedMemorySize, TG_SMEM);
        cudaFuncSetAttribute(tgemm<1,0>, cudaFuncAttributeMaxDynamicSharedMemorySize, TG_SMEM);
        cudaFuncSetAttribute(tgemm<2,1>, cudaFuncAttributeMaxDynamicSharedMemorySize, TG_SMEM);
        cudaFuncSetAttribute(tgemm<3,0>, cudaFuncAttributeMaxDynamicSharedMemorySize, TG_SMEM);
        smemSet = 1;
    }

    float *qkv, *r, *sc, *bd, *ao, *ff, *h1, *h2, *h3, *moe, *gate;
    int *cnt, *idx;
    bf16 *whi, *wlo, *peh, *pel, *xh, *xl;
    bf16 *quh, *qul, *qvh, *qvl, *kh, *kl, *vth, *vtl, *rh, *rl;
    bf16 *ctxh, *ctxl, *h1h, *h1l, *h2h, *h2l, *h3h, *h3l, *ffhh, *ffhl;

    cudaGetSymbolAddress((void**)&qkv, g_qkv);
    cudaGetSymbolAddress((void**)&r,   g_r);
    cudaGetSymbolAddress((void**)&sc,  g_sc);
    cudaGetSymbolAddress((void**)&bd,  g_bd);
    cudaGetSymbolAddress((void**)&ao,  g_ao);
    cudaGetSymbolAddress((void**)&ff,  g_ff);
    cudaGetSymbolAddress((void**)&h1,  g_h1);
    cudaGetSymbolAddress((void**)&h2,  g_h2);
    cudaGetSymbolAddress((void**)&h3,  g_h3);
    cudaGetSymbolAddress((void**)&moe, g_moe);
    cudaGetSymbolAddress((void**)&gate,g_gate);
    cudaGetSymbolAddress((void**)&cnt, g_cnt);
    cudaGetSymbolAddress((void**)&idx, g_idx);
    cudaGetSymbolAddress((void**)&whi, g_whi);
    cudaGetSymbolAddress((void**)&wlo, g_wlo);
    cudaGetSymbolAddress((void**)&peh, g_peh);
    cudaGetSymbolAddress((void**)&pel, g_pel);
    cudaGetSymbolAddress((void**)&xh,  g_xh);
    cudaGetSymbolAddress((void**)&xl,  g_xl);
    cudaGetSymbolAddress((void**)&quh, g_quh);
    cudaGetSymbolAddress((void**)&qul, g_qul);
    cudaGetSymbolAddress((void**)&qvh, g_qvh);
    cudaGetSymbolAddress((void**)&qvl, g_qvl);
    cudaGetSymbolAddress((void**)&kh,  g_kh);
    cudaGetSymbolAddress((void**)&kl,  g_kl);
    cudaGetSymbolAddress((void**)&vth, g_vth);
    cudaGetSymbolAddress((void**)&vtl, g_vtl);
    cudaGetSymbolAddress((void**)&rh,  g_rh);
    cudaGetSymbolAddress((void**)&rl,  g_rl);
    cudaGetSymbolAddress((void**)&ctxh,g_ctxh);
    cudaGetSymbolAddress((void**)&ctxl,g_ctxl);
    cudaGetSymbolAddress((void**)&h1h, g_h1h);
    cudaGetSymbolAddress((void**)&h1l, g_h1l);
    cudaGetSymbolAddress((void**)&h2h, g_h2h);
    cudaGetSymbolAddress((void**)&h2l, g_h2l);
    cudaGetSymbolAddress((void**)&h3h, g_h3h);
    cudaGetSymbolAddress((void**)&h3l, g_h3l);
    cudaGetSymbolAddress((void**)&ffhh,g_ffhh);
    cudaGetSymbolAddress((void**)&ffhl,g_ffhl);

    // weight transpose + split (64x64 tiles; experts batched via blockIdx.z)
    wconv<<<dim3(3072/64, 1024/64), 256>>>(Wqkv, whi+OFF_QKV,  wlo+OFF_QKV,  1024, 3072);
    wconv<<<dim3(1024/64, 1024/64), 256>>>(Wr,   whi+OFF_WR,   wlo+OFF_WR,   1024, 1024);
    wconv<<<dim3(1024/64, 1024/64), 256>>>(Wo,   whi+OFF_WO,   wlo+OFF_WO,   1024, 1024);
    wconv<<<dim3(4096/64, 1024/64), 256>>>(Wff1, whi+OFF_FF1,  wlo+OFF_FF1,  1024, 4096);
    wconv<<<dim3(1024/64, 4096/64), 256>>>(Wff2, whi+OFF_FF2,  wlo+OFF_FF2,  4096, 1024);
    wconv<<<dim3(1024/64, 1024/64), 256>>>(Wout, whi+OFF_WOUT, wlo+OFF_WOUT, 1024, 1024);
    wconv<<<dim3(4096/64, 1024/64, NEc), 256>>>(We1, whi+OFF_WE1, wlo+OFF_WE1, 1024, 4096);
    wconv<<<dim3(1024/64, 4096/64, NEc), 256>>>(We2, whi+OFF_WE2, wlo+OFF_WE2, 4096, 1024);

    pe_kernel<<<Sc, 256>>>(peh, pel);
    econv<<<Tc, 256>>>(x, xh, xl);

    // projections
    tgemm<0,0><<<dim3(3072/128, Tc/128), 256, TG_SMEM>>>(xh, xl, whi+OFF_QKV, wlo+OFF_QKV,
        qkv, nullptr, nullptr, Tc, 3072, 1024, nullptr, nullptr, nullptr, nullptr, 0, 0);
    tgemm<0,0><<<dim3(1024/128, Sc/128), 256, TG_SMEM>>>(peh, pel, whi+OFF_WR, wlo+OFF_WR,
        r, nullptr, nullptr, Sc, 1024, 1024, nullptr, nullptr, nullptr, nullptr, 0, 0);

    // attention prep
    qprep<<<Tc, 256>>>(qkv, u_b, v_b, quh, qul, qvh, qvl, kh, kl);
    vtprep<<<dim3(Sc/32, 2, BHc), 256>>>(qkv, vth, vtl);
    rprep<<<Sc, 256>>>(r, rh, rl);

    // attention
    attn_sc<<<dim3(16, 16, BHc), 256>>>(quh, qul, kh, kl, sc, 0);
    attn_sc<<<dim3(16, 16, BHc), 256>>>(qvh, qvl, rh, rl, bd, 1);
    softmax_k<<<dim3(Sc, BHc), 256>>>(sc, bd);
    attn_av<<<dim3(16, BHc), 256>>>(sc, vth, vtl, ctxh, ctxl);
    tgemm<0,0><<<dim3(1024/128, Tc/128), 256, TG_SMEM>>>(ctxh, ctxl, whi+OFF_WO, wlo+OFF_WO,
        ao, nullptr, nullptr, Tc, 1024, 1024, nullptr, nullptr, nullptr, nullptr, 0, 0);
    rln_k<1><<<Tc, 256>>>(x, ao, ln1g, ln1b, h1, h1h, h1l);

    // FFN
    tgemm<2,1><<<dim3(4096/128, Tc/128), 256, TG_SMEM>>>(h1h, h1l, whi+OFF_FF1, wlo+OFF_FF1,
        nullptr, ffhh, ffhl, Tc, 4096, 1024, bff1, nullptr, nullptr, nullptr, 0, 0);
    tgemm<1,0><<<dim3(1024/128, Tc/128), 256, TG_SMEM>>>(ffhh, ffhl, whi+OFF_FF2, wlo+OFF_FF2,
        ff, nullptr, nullptr, Tc, 1024, 4096, bff2, nullptr, nullptr, nullptr, 0, 0);
    rln_k<1><<<Tc, 256>>>(h1, ff, ln2g, ln2b, h2, h2h, h2l);

    // MoE: all experts in two launches (blockIdx.z = expert)
    zero_cnt<<<1, 32>>>(cnt);
    router_k<<<Tc/8, 256>>>(h2, Wg, gate, cnt, idx);
    tgemm<2,1><<<dim3(4096/128, Tc/128, NEc), 256, TG_SMEM>>>(
        h2h, h2l, whi+OFF_WE1, wlo+OFF_WE1,
        nullptr, ffhh, ffhl, Tc, 4096, 1024, be1, nullptr, idx, cnt,
        (size_t)FFc*Dc, FFc);
    tgemm<3,0><<<dim3(1024/128, Tc/128, NEc), 256, TG_SMEM>>>(
        ffhh, ffhl, whi+OFF_WE2, wlo+OFF_WE2,
        moe, nullptr, nullptr, Tc, 1024, 4096, be2, gate, idx, cnt,
        (size_t)Dc*FFc, Dc);
    rln_k<1><<<Tc, 256>>>(h2, moe, ln3g, ln3b, h3, h3h, h3l);

    // output projection
    tgemm<0,0><<<dim3(1024/128, Tc/128), 256, TG_SMEM>>>(h3h, h3l, whi+OFF_WOUT, wlo+OFF_WOUT,
        out, nullptr, nullptr, Tc, 1024, 1024, nullptr, nullptr, nullptr, nullptr, 0, 0);
}

// round 12
// speedup vs baseline: 7.4182x; 1.0516x over previous
#include <cuda_runtime.h>
#include <cuda_bf16.h>
#include <math.h>
#include <stdint.h>

#define Bc 4
#define Sc 1024
#define Dc 1024
#define NHc 16
#define DHc 64
#define FFc 4096
#define NEc 8
#define Tc (Bc*Sc)
#define BHc (Bc*NHc)

typedef __nv_bfloat16 bf16;
typedef __nv_bfloat162 bf162;

// ---------------- fp32 scratch ----------------
__device__ float g_qkv[(size_t)Tc*3*Dc];
__device__ float g_r[Sc*Dc];
__device__ float g_ao[(size_t)Tc*Dc];
__device__ float g_ff[(size_t)Tc*Dc];
__device__ float g_h1[(size_t)Tc*Dc];
__device__ float g_h2[(size_t)Tc*Dc];
__device__ float g_h3[(size_t)Tc*Dc];
__device__ float g_moe[(size_t)Tc*Dc];
__device__ float g_gate[Tc];
__device__ int   g_cnt[NEc];
__device__ int   g_idx[NEc*Tc];

// ---------------- bf16 hi/lo scratch ----------------
__device__ bf16 g_peh[Sc*Dc],  g_pel[Sc*Dc];
__device__ bf16 g_xh[(size_t)Tc*Dc],  g_xl[(size_t)Tc*Dc];
__device__ bf16 g_quh[(size_t)Tc*Dc], g_qul[(size_t)Tc*Dc];
__device__ bf16 g_qvh[(size_t)Tc*Dc], g_qvl[(size_t)Tc*Dc];
__device__ bf16 g_kh[(size_t)Tc*Dc],  g_kl[(size_t)Tc*Dc];
__device__ bf16 g_vth[(size_t)Tc*Dc], g_vtl[(size_t)Tc*Dc];
__device__ bf16 g_rh[NHc*Sc*DHc],     g_rl[NHc*Sc*DHc];
__device__ bf16 g_ctxh[(size_t)Tc*Dc], g_ctxl[(size_t)Tc*Dc];
__device__ bf16 g_h1h[(size_t)Tc*Dc], g_h1l[(size_t)Tc*Dc];
__device__ bf16 g_h2h[(size_t)Tc*Dc], g_h2l[(size_t)Tc*Dc];
__device__ bf16 g_h3h[(size_t)Tc*Dc], g_h3l[(size_t)Tc*Dc];
__device__ bf16 g_ffhh[(size_t)Tc*FFc], g_ffhl[(size_t)Tc*FFc];

// transposed split-bf16 weights: [N,K] layout, hi + lo
#define OFF_QKV  0
#define OFF_WR   3145728
#define OFF_WO   4194304
#define OFF_FF1  5242880
#define OFF_FF2  9437184
#define OFF_WE1  13631488
#define OFF_WE2  47185920
#define OFF_WOUT 80740352
#define WTOT     81788928
__device__ bf16 g_whi[WTOT];
__device__ bf16 g_wlo[WTOT];

// ---------------- helpers ----------------
__device__ __forceinline__ uint32_t smem_u32(const void* p) {
    uint32_t a;
    asm("{ .reg .u64 t; cvta.to.shared.u64 t, %1; cvt.u32.u64 %0, t; }" : "=r"(a) : "l"(p));
    return a;
}
__device__ __forceinline__ void ldm4(uint32_t* r, uint32_t a) {
    asm volatile("ldmatrix.sync.aligned.m8n8.x4.shared.b16 {%0,%1,%2,%3}, [%4];"
        : "=r"(r[0]), "=r"(r[1]), "=r"(r[2]), "=r"(r[3]) : "r"(a));
}
__device__ __forceinline__ void mma_bf16(float* c, const uint32_t* a, uint32_t b0, uint32_t b1) {
    asm volatile("mma.sync.aligned.m16n8k16.row.col.f32.bf16.bf16.f32 "
        "{%0,%1,%2,%3}, {%4,%5,%6,%7}, {%8,%9}, {%0,%1,%2,%3};"
        : "+f"(c[0]), "+f"(c[1]), "+f"(c[2]), "+f"(c[3])
        : "r"(a[0]), "r"(a[1]), "r"(a[2]), "r"(a[3]), "r"(b0), "r"(b1));
}
__device__ __forceinline__ void split1(float v, bf16& h, bf16& l) {
    h = __float2bfloat16_rn(v);
    l = __float2bfloat16_rn(v - __bfloat162float(h));
}
__device__ __forceinline__ void split2(float x, float y, bf162& h, bf162& l) {
    h = __floats2bfloat162_rn(x, y);
    float2 hf = __bfloat1622float2(h);
    l = __floats2bfloat162_rn(x - hf.x, y - hf.y);
}
#define CPA16(dst, src, sz) \
    asm volatile("cp.async.cg.shared.global [%0], [%1], 16, %2;" :: "r"(dst), "l"(src), "r"(sz))
#define CPC()  asm volatile("cp.async.commit_group;" ::: "memory")
#define CPW1() asm volatile("cp.async.wait_group 1;" ::: "memory")
#define CPW0() asm volatile("cp.async.wait_group 0;" ::: "memory")

// ---------------- weight transpose + split: W[K,N] -> hi/lo [N,K] ----------------
__global__ __launch_bounds__(256)
void wconv(const float* __restrict__ W, bf16* __restrict__ hi,
           bf16* __restrict__ lo, int K, int N)
{
    __shared__ float t[64][66];
    int tid = threadIdx.x;
    int nb = blockIdx.x * 64, kb = blockIdx.y * 64;
    size_t eoff = (size_t)blockIdx.z * K * N;

    int j  = tid & 63;
    int r0 = tid >> 6;
    #pragma unroll
    for (int l = 0; l < 16; l++) {
        int i = r0 + l * 4;
        t[j][i] = W[eoff + (size_t)(kb + i) * N + nb + j];
    }
    __syncthreads();

    int lane = tid & 31, w = tid >> 5;
    #pragma unroll
    for (int l = 0; l < 8; l++) {
        int n = w + l * 8;
        float2 v = *(float2*)&t[n][2 * lane];
        bf162 h, lo2; split2(v.x, v.y, h, lo2);
        size_t dst = eoff + (size_t)(nb + n) * K + kb + 2 * lane;
        *(bf162*)(hi + dst) = h;
        *(bf162*)(lo + dst) = lo2;
    }
}

// ---------------- elementwise fp32 -> bf16 hi/lo ----------------
__global__ __launch_bounds__(256)
void econv(const float* __restrict__ src, bf16* __restrict__ hi, bf16* __restrict__ lo)
{
    size_t i = (size_t)blockIdx.x * 1024 + threadIdx.x;
    #pragma unroll
    for (int l = 0; l < 4; l++) {
        float v = src[i + l*256];
        bf16 h, lo_;
        split1(v, h, lo_);
        hi[i + l*256] = h; lo[i + l*256] = lo_;
    }
}

// ---------------- positional embedding (bf16 hi/lo) ----------------
__global__ void pe_kernel(bf16* __restrict__ peh, bf16* __restrict__ pel) {
    int i = blockIdx.x;
    float pos = (float)(Sc - 1 - i);
    #pragma unroll
    for (int l = 0; l < 4; l++) {
        int c = threadIdx.x + l * 256;
        int j = (c < Dc/2) ? c : (c - Dc/2);
        float invf = expf(-logf(10000.f) * ((float)(2*j) / (float)Dc));
        float a = pos * invf;
        float v = (c < Dc/2) ? sinf(a) : cosf(a);
        bf16 h, lo; split1(v, h, lo);
        peh[(size_t)i*Dc + c] = h; pel[(size_t)i*Dc + c] = lo;
    }
}

// ---------------- attention operand prep (q-side pre-scaled by 0.125) ----------------
__global__ __launch_bounds__(256)
void qprep(const float* __restrict__ qkv, const float* __restrict__ ub, const float* __restrict__ vb,
           bf16* quh, bf16* qul, bf16* qvh, bf16* qvl, bf16* kh, bf16* kl)
{
    int tok = blockIdx.x;
    int b = tok >> 10, s = tok & 1023;
    #pragma unroll
    for (int l = 0; l < 4; l++) {
        int c = threadIdx.x + l*256;
        int h = c >> 6, d = c & 63;
        size_t src = (size_t)tok*3072 + c;
        float qf = qkv[src], kf = qkv[src + 1024];
        size_t dst = ((size_t)(b*NHc + h)*Sc + s)*64 + d;
        bf16 hh, ll;
        split1((qf + ub[c]) * 0.125f, hh, ll); quh[dst] = hh; qul[dst] = ll;
        split1((qf + vb[c]) * 0.125f, hh, ll); qvh[dst] = hh; qvl[dst] = ll;
        split1(kf, hh, ll);                   kh[dst] = hh;  kl[dst] = ll;
    }
}
__global__ __launch_bounds__(256)
void vtprep(const float* __restrict__ qkv, bf16* vth, bf16* vtl)
{
    __shared__ float t[32][33];
    int tx = threadIdx.x & 31, ty = threadIdx.x >> 5;
    int s0 = blockIdx.x * 32, d0 = blockIdx.y * 32, bh = blockIdx.z;
    int b = bh >> 4, h = bh & 15;
    #pragma unroll
    for (int j = 0; j < 4; j++) {
        int sl = ty + j*8;
        t[sl][tx] = qkv[((size_t)(b*Sc + s0 + sl))*3072 + 2048 + h*64 + d0 + tx];
    }
    __syncthreads();
    #pragma unroll
    for (int j = 0; j < 4; j++) {
        int dl = ty + j*8;
        float v = t[tx][dl];
        bf16 hh, ll; split1(v, hh, ll);
        size_t dst = ((size_t)bh*64 + d0 + dl)*Sc + s0 + tx;
        vth[dst] = hh; vtl[dst] = ll;
    }
}
__global__ __launch_bounds__(256)
void rprep(const float* __restrict__ r, bf16* rh, bf16* rl)
{
    int s = blockIdx.x;
    #pragma unroll
    for (int l = 0; l < 4; l++) {
        int c = threadIdx.x + l*256;
        int h = c >> 6, d = c & 63;
        float v = r[(size_t)s*Dc + c];
        bf16 hh, ll; split1(v, hh, ll);
        size_t dst = ((size_t)h*Sc + s)*64 + d;
        rh[dst] = hh; rl[dst] = ll;
    }
}

// ---------------- HMMA split-bf16 GEMM with cp.async double buffering ----------------
#define STG_BYTES 40960
#define OPD_BYTES 10240
#define TG_SMEM   (2*STG_BYTES)

template<int EPI, int OBF>
__global__ __launch_bounds__(256, 2)
void tgemm(const bf16* __restrict__ Ahi, const bf16* __restrict__ Alo,
           const bf16* __restrict__ Bhi, const bf16* __restrict__ Blo,
           float* __restrict__ C, bf16* __restrict__ Chi, bf16* __restrict__ Clo,
           int M, int N, int K,
           const float* __restrict__ bias, const float* __restrict__ rowScale,
           const int* __restrict__ gatherBase, const int* __restrict__ cntBase,
           size_t eStrideB, int eStrideBias)
{
    extern __shared__ char sm[];

    int e = blockIdx.z;
    const int* gather = gatherBase ? gatherBase + e * Tc : nullptr;
    int limit = cntBase ? cntBase[e] : M;
    int m0 = blockIdx.y * 128;
    if (m0 >= limit) return;
    int n0 = blockIdx.x * 128;
    const bf16* BhiE = Bhi + (size_t)e * eStrideB;
    const bf16* BloE = Blo + (size_t)e * eStrideB;
    const float* biasE = (EPI >= 1) ? bias + (size_t)e * eStrideBias : bias;

    int tid = threadIdx.x, wid = tid >> 5, lane = tid & 31;
    int wm = (wid & 3) * 32, wn = (wid >> 2) * 64;
    uint32_t sbase = smem_u32(sm);

    const bf16 *aph[2], *apl[2], *bph[2], *bpl[2];
    uint32_t soff[2], asz[2];
    #pragma unroll
    for (int l = 0; l < 2; l++) {
        int slot = tid + 256*l;
        int row = slot >> 2, seg = slot & 3;
        soff[l] = (uint32_t)(row * 80 + seg * 16);
        int gr = m0 + row;
        if (gr < limit) {
            int sr = gather ? gather[gr] : gr;
            aph[l] = Ahi + (size_t)sr * K + seg * 8;
            apl[l] = Alo + (size_t)sr * K + seg * 8;
            asz[l] = 16;
        } else {
            aph[l] = Ahi; apl[l] = Alo; asz[l] = 0;
        }
        size_t off = (size_t)(n0 + row) * K + seg * 8;
        bph[l] = BhiE + off; bpl[l] = BloE + off;
    }

    int t4 = lane >> 3;
    int rr = (lane & 7) + (t4 & 1) * 8;
    int cc = (t4 >> 1) * 8;

    float acc[2][8][4];
    #pragma unroll
    for (int i = 0; i < 2; i++)
        #pragma unroll
        for (int j = 0; j < 8; j++)
            #pragma unroll
            for (int q = 0; q < 4; q++) acc[i][j][q] = 0.f;

    int Kc = K >> 5;

    #pragma unroll
    for (int s = 0; s < 2; s++) {
        if (s < Kc) {
            uint32_t b = sbase + s * STG_BYTES;
            int ko = s * 32;
            #pragma unroll
            for (int l = 0; l < 2; l++) {
                CPA16(b + soff[l],               aph[l] + ko, asz[l]);
                CPA16(b + OPD_BYTES + soff[l],   apl[l] + ko, asz[l]);
                CPA16(b + 2*OPD_BYTES + soff[l], bph[l] + ko, 16u);
                CPA16(b + 3*OPD_BYTES + soff[l], bpl[l] + ko, 16u);
            }
            CPC();
        }
    }

    for (int c = 0; c < Kc; c++) {
        if (c + 1 < Kc) { CPW1(); } else { CPW0(); }
        __syncthreads();

        uint32_t sb = sbase + (uint32_t)(c & 1) * STG_BYTES;
        uint32_t baAH = sb, baAL = sb + OPD_BYTES;
        uint32_t baBH = sb + 2*OPD_BYTES, baBL = sb + 3*OPD_BYTES;

        #pragma unroll
        for (int k16 = 0; k16 < 32; k16 += 16) {
            uint32_t aH[2][4], aL[2][4];
            #pragma unroll
            for (int mi = 0; mi < 2; mi++) {
                uint32_t off = ((uint32_t)(wm + mi*16 + rr) * 40u + (uint32_t)(k16 + cc)) * 2u;
                ldm4(aH[mi], baAH + off);
                ldm4(aL[mi], baAL + off);
            }
            uint32_t bH[4][4], bL[4][4];
            #pragma unroll
            for (int ni = 0; ni < 4; ni++) {
                uint32_t off = ((uint32_t)(wn + ni*16 + rr) * 40u + (uint32_t)(k16 + cc)) * 2u;
                ldm4(bH[ni], baBH + off);
                ldm4(bL[ni], baBL + off);
            }
            #pragma unroll
            for (int mi = 0; mi < 2; mi++)
                #pragma unroll
                for (int ni = 0; ni < 4; ni++)
                    #pragma unroll
                    for (int h = 0; h < 2; h++) {
                        int j = ni*2 + h;
                        mma_bf16(acc[mi][j], aH[mi], bH[ni][h], bH[ni][h+2]);
                        mma_bf16(acc[mi][j], aH[mi], bL[ni][h], bL[ni][h+2]);
                        mma_bf16(acc[mi][j], aL[mi], bH[ni][h], bH[ni][h+2]);
                    }
        }
        __syncthreads();

        if (c + 2 < Kc) {
            uint32_t b = sbase + (uint32_t)(c & 1) * STG_BYTES;
            int ko = (c + 2) * 32;
            #pragma unroll
            for (int l = 0; l < 2; l++) {
                CPA16(b + soff[l],               aph[l] + ko, asz[l]);
                CPA16(b + OPD_BYTES + soff[l],   apl[l] + ko, asz[l]);
                CPA16(b + 2*OPD_BYTES + soff[l], bph[l] + ko, 16u);
                CPA16(b + 3*OPD_BYTES + soff[l], bpl[l] + ko, 16u);
            }
            CPC();
        }
    }

    #pragma unroll
    for (int mi = 0; mi < 2; mi++) {
        #pragma unroll
        for (int half = 0; half < 2; half++) {
            int gr = m0 + wm + mi*16 + (lane >> 2) + half*8;
            if (gr >= limit) continue;
            int crow = gather ? gather[gr] : gr;
            float rs = 1.f;
            if (EPI == 3) rs = rowScale[crow];
            #pragma unroll
            for (int j = 0; j < 8; j++) {
                int col = n0 + wn + j*8 + (lane & 3)*2;
                float vx = acc[mi][j][half*2 + 0];
                float vy = acc[mi][j][half*2 + 1];
                if (EPI >= 1) { vx += biasE[col]; vy += biasE[col+1]; }
                if (EPI == 2) { vx = fmaxf(vx, 0.f); vy = fmaxf(vy, 0.f); }
                if (EPI == 3) { vx *= rs; vy *= rs; }
                if (OBF == 0) {
                    *(float2*)(C + (size_t)crow * N + col) = make_float2(vx, vy);
                } else {
                    bf162 h, l; split2(vx, vy, h, l);
                    *(bf162*)(Chi + (size_t)crow * N + col) = h;
                    *(bf162*)(Clo + (size_t)crow * N + col) = l;
                }
            }
        }
    }
}

// ---------------- fused TXL attention: ac + rel-shift bd + online softmax + PV ----------------
#define FA_QUH 0
#define FA_QUL 9216
#define FA_QVH 18432
#define FA_QVL 27648
#define FA_KH  36864
#define FA_KL  46080
#define FA_RH  55296
#define FA_RL  73728
#define FA_VH  92160
#define FA_VL  101376
#define FA_PH  110592
#define FA_PL  119808
#define FA_BD  129024
#define FA_RED (FA_BD + 33792)          // [0,512): row max buf; [512,1024): row sum buf
#define FA_SMEM (FA_RED + 1024)

__global__ __launch_bounds__(256, 1)
void fattn(const bf16* __restrict__ quh, const bf16* __restrict__ qul,
           const bf16* __restrict__ qvh, const bf16* __restrict__ qvl,
           const bf16* __restrict__ kh,  const bf16* __restrict__ kl,
           const bf16* __restrict__ rhp, const bf16* __restrict__ rlp,
           const bf16* __restrict__ vth, const bf16* __restrict__ vtl,
           bf16* __restrict__ ctxh, bf16* __restrict__ ctxl)
{
    extern __shared__ char sm[];
    int qt = 15 - blockIdx.x;
    int bh = blockIdx.y;
    int b = bh >> 4, h = bh & 15;
    int q0 = qt * 64;
    uint32_t sb = smem_u32(sm);
    int tid = threadIdx.x, wid = tid >> 5, lane = tid & 31;
    int wm = (wid & 3) * 16, wn = (wid >> 2) * 32;
    int wcol = wid >> 2;               // warp-column: 0 or 1 (32 score cols each)
    int t4l = lane >> 3;
    int rr = (lane & 7) + (t4l & 1) * 8;
    int cc = (t4l >> 1) * 8;
    int qrow = (lane >> 2);
    int kc0 = (lane & 3) * 2;

    #pragma unroll
    for (int i = 0; i < 2; i++) {
        int slot = tid + 256*i;
        int row = slot >> 3, seg = slot & 7;
        size_t g = ((size_t)bh*Sc + q0 + row)*64 + seg*8;
        *(uint4*)(sm + FA_QUH + row*144 + seg*16) = *(const uint4*)(quh + g);
        *(uint4*)(sm + FA_QUL + row*144 + seg*16) = *(const uint4*)(qul + g);
        *(uint4*)(sm + FA_QVH + row*144 + seg*16) = *(const uint4*)(qvh + g);
        *(uint4*)(sm + FA_QVL + row*144 + seg*16) = *(const uint4*)(qvl + g);
    }

    float mrow[2] = {-1e30f, -1e30f}, lrow[2] = {0.f, 0.f};
    float oacc[4][4];
    #pragma unroll
    for (int j = 0; j < 4; j++)
        #pragma unroll
        for (int q = 0; q < 4; q++) oacc[j][q] = 0.f;

    for (int kt = 0; kt <= qt; kt++) {
        int k0 = kt * 64;
        int t0 = kt - qt + 15;
        __syncthreads();

        #pragma unroll
        for (int i = 0; i < 2; i++) {
            int slot = tid + 256*i;
            int row = slot >> 3, seg = slot & 7;
            size_t gk = ((size_t)bh*Sc + k0 + row)*64 + seg*8;
            *(uint4*)(sm + FA_KH + row*144 + seg*16) = *(const uint4*)(kh + gk);
            *(uint4*)(sm + FA_KL + row*144 + seg*16) = *(const uint4*)(kl + gk);
            size_t gv = ((size_t)bh*64 + row)*Sc + k0 + seg*8;
            *(uint4*)(sm + FA_VH + row*144 + seg*16) = *(const uint4*)(vth + gv);
            *(uint4*)(sm + FA_VL + row*144 + seg*16) = *(const uint4*)(vtl + gv);
        }
        int tfrom = (kt == 0) ? t0 : t0 + 1;
        for (int t = tfrom; t <= t0 + 1 && t <= 15; t++) {
            int hoff = (t & 1) * 64;
            #pragma unroll
            for (int i = 0; i < 2; i++) {
                int slot = tid + 256*i;
                int row = slot >> 3, seg = slot & 7;
                size_t gr = ((size_t)h*Sc + t*64 + row)*64 + seg*8;
                *(uint4*)(sm + FA_RH + (hoff + row)*144 + seg*16) = *(const uint4*)(rhp + gr);
                *(uint4*)(sm + FA_RL + (hoff + row)*144 + seg*16) = *(const uint4*)(rlp + gr);
            }
        }
        __syncthreads();

        // bd MMAs for new j-tiles -> BD ring
        for (int t = tfrom; t <= t0 + 1 && t <= 15; t++) {
            int hoff = (t & 1) * 64;
            float bacc[4][4];
            #pragma unroll
            for (int j = 0; j < 4; j++)
                #pragma unroll
                for (int q = 0; q < 4; q++) bacc[j][q] = 0.f;
            #pragma unroll
            for (int k16 = 0; k16 < 64; k16 += 16) {
                uint32_t aH[4], aL[4];
                uint32_t offA = ((uint32_t)(wm + rr) * 72u + (uint32_t)(k16 + cc)) * 2u;
                ldm4(aH, sb + FA_QVH + offA);
                ldm4(aL, sb + FA_QVL + offA);
                uint32_t bH[2][4], bL[2][4];
                #pragma unroll
                for (int ni = 0; ni < 2; ni++) {
                    uint32_t offB = ((uint32_t)(hoff + wn + ni*16 + rr) * 72u + (uint32_t)(k16 + cc)) * 2u;
                    ldm4(bH[ni], sb + FA_RH + offB);
                    ldm4(bL[ni], sb + FA_RL + offB);
                }
                #pragma unroll
                for (int ni = 0; ni < 2; ni++)
                    #pragma unroll
                    for (int hb = 0; hb < 2; hb++) {
                        int j = ni*2 + hb;
                        mma_bf16(bacc[j], aH, bH[ni][hb], bH[ni][hb+2]);
                        mma_bf16(bacc[j], aH, bL[ni][hb], bL[ni][hb+2]);
                        mma_bf16(bacc[j], aL, bH[ni][hb], bH[ni][hb+2]);
                    }
            }
            #pragma unroll
            for (int half = 0; half < 2; half++) {
                int row = wm + qrow + half*8;
                #pragma unroll
                for (int j = 0; j < 4; j++) {
                    int col = hoff + wn + j*8 + kc0;
                    *(float2*)(sm + FA_BD + row*528 + col*4) =
                        make_float2(bacc[j][half*2], bacc[j][half*2+1]);
                }
            }
        }

        // ac MMAs
        float s[4][4];
        #pragma unroll
        for (int j = 0; j < 4; j++)
            #pragma unroll
            for (int q = 0; q < 4; q++) s[j][q] = 0.f;
        #pragma unroll
        for (int k16 = 0; k16 < 64; k16 += 16) {
            uint32_t aH[4], aL[4];
            uint32_t offA = ((uint32_t)(wm + rr) * 72u + (uint32_t)(k16 + cc)) * 2u;
            ldm4(aH, sb + FA_QUH + offA);
            ldm4(aL, sb + FA_QUL + offA);
            uint32_t bH[2][4], bL[2][4];
            #pragma unroll
            for (int ni = 0; ni < 2; ni++) {
                uint32_t offB = ((uint32_t)(wn + ni*16 + rr) * 72u + (uint32_t)(k16 + cc)) * 2u;
                ldm4(bH[ni], sb + FA_KH + offB);
                ldm4(bL[ni], sb + FA_KL + offB);
            }
            #pragma unroll
            for (int ni = 0; ni < 2; ni++)
                #pragma unroll
                for (int hb = 0; hb < 2; hb++) {
                    int j = ni*2 + hb;
                    mma_bf16(s[j], aH, bH[ni][hb], bH[ni][hb+2]);
                    mma_bf16(s[j], aH, bL[ni][hb], bL[ni][hb+2]);
                    mma_bf16(s[j], aL, bH[ni][hb], bH[ni][hb+2]);
                }
        }
        __syncthreads();   // BD writes visible

        // ---- online softmax with cross-warp row statistics ----
        bool diag = (kt == qt);
        int ringbase = (t0 & 1) * 64;
        float mt2[2], sc2[2], rs2[2];

        // phase 1: add bd, mask, per-warp row max -> smem
        #pragma unroll
        for (int half = 0; half < 2; half++) {
            int row = wm + qrow + half*8;
            float mt = -1e30f;
            #pragma unroll
            for (int j = 0; j < 4; j++) {
                #pragma unroll
                for (int c2 = 0; c2 < 2; c2++) {
                    int colk = wn + j*8 + kc0 + c2;
                    int jcol = colk - row + 63;
                    int phys = (ringbase + jcol) & 127;
                    float val = s[j][half*2 + c2] +
                        *(const float*)(sm + FA_BD + row*528 + phys*4);
                    if (diag && colk > row) val = -1e30f;
                    s[j][half*2 + c2] = val;
                    mt = fmaxf(mt, val);
                }
            }
            mt = fmaxf(mt, __shfl_xor_sync(0xFFFFFFFFu, mt, 1));
            mt = fmaxf(mt, __shfl_xor_sync(0xFFFFFFFFu, mt, 2));
            mt2[half] = mt;
            if ((lane & 3) == 0)
                *(float*)(sm + FA_RED + (wcol*64 + row)*4) = mt;
        }
        __syncthreads();

        // phase 2: combined max, exponentiate, partial sums -> smem, write P
        #pragma unroll
        for (int half = 0; half < 2; half++) {
            int row = wm + qrow + half*8;
            float other = *(const float*)(sm + FA_RED + ((1-wcol)*64 + row)*4);
            float mnew = fmaxf(mrow[half], fmaxf(mt2[half], other));
            float scale = __expf(mrow[half] - mnew);
            sc2[half] = scale;
            float rs = 0.f;
            #pragma unroll
            for (int j = 0; j < 4; j++) {
                #pragma unroll
                for (int c2 = 0; c2 < 2; c2++) {
                    float p = __expf(s[j][half*2 + c2] - mnew);
                    s[j][half*2 + c2] = p;
                    rs += p;
                }
            }
            rs += __shfl_xor_sync(0xFFFFFFFFu, rs, 1);
            rs += __shfl_xor_sync(0xFFFFFFFFu, rs, 2);
            rs2[half] = rs;
            if ((lane & 3) == 0)
                *(float*)(sm + FA_RED + 512 + (wcol*64 + row)*4) = rs;
            mrow[half] = mnew;
            #pragma unroll
            for (int j = 0; j < 4; j++) {
                oacc[j][half*2 + 0] *= scale;
                oacc[j][half*2 + 1] *= scale;
            }
            #pragma unroll
            for (int j = 0; j < 4; j++) {
                int col = wn + j*8 + kc0;
                bf162 hh, ll;
                split2(s[j][half*2], s[j][half*2+1], hh, ll);
                *(bf162*)(sm + FA_PH + row*144 + col*2) = hh;
                *(bf162*)(sm + FA_PL + row*144 + col*2) = ll;
            }
        }
        __syncthreads();   // P + row sums visible

        // phase 3: combine row sums
        #pragma unroll
        for (int half = 0; half < 2; half++) {
            int row = wm + qrow + half*8;
            float other = *(const float*)(sm + FA_RED + 512 + ((1-wcol)*64 + row)*4);
            lrow[half] = lrow[half] * sc2[half] + rs2[half] + other;
        }

        // PV MMAs
        #pragma unroll
        for (int k16 = 0; k16 < 64; k16 += 16) {
            uint32_t aH[4], aL[4];
            uint32_t offA = ((uint32_t)(wm + rr) * 72u + (uint32_t)(k16 + cc)) * 2u;
            ldm4(aH, sb + FA_PH + offA);
            ldm4(aL, sb + FA_PL + offA);
            uint32_t bH[2][4], bL[2][4];
            #pragma unroll
            for (int ni = 0; ni < 2; ni++) {
                uint32_t offB = ((uint32_t)(wn + ni*16 + rr) * 72u + (uint32_t)(k16 + cc)) * 2u;
                ldm4(bH[ni], sb + FA_VH + offB);
                ldm4(bL[ni], sb + FA_VL + offB);
            }
            #pragma unroll
            for (int ni = 0; ni < 2; ni++)
                #pragma unroll
                for (int hb = 0; hb < 2; hb++) {
                    int j = ni*2 + hb;
                    mma_bf16(oacc[j], aH, bH[ni][hb], bH[ni][hb+2]);
                    mma_bf16(oacc[j], aH, bL[ni][hb], bL[ni][hb+2]);
                    mma_bf16(oacc[j], aL, bH[ni][hb], bH[ni][hb+2]);
                }
        }
    }

    #pragma unroll
    for (int half = 0; half < 2; half++) {
        int row = wm + qrow + half*8;
        int tok = b*Sc + q0 + row;
        float inv = 1.f / lrow[half];
        #pragma unroll
        for (int j = 0; j < 4; j++) {
            int col = h*64 + wn + j*8 + kc0;
            bf162 hh, ll;
            split2(oacc[j][half*2] * inv, oacc[j][half*2+1] * inv, hh, ll);
            *(bf162*)(ctxh + (size_t)tok*Dc + col) = hh;
            *(bf162*)(ctxl + (size_t)tok*Dc + col) = ll;
        }
    }
}

// ---------------- residual + layernorm ----------------
template<int OBF>
__global__ __launch_bounds__(256)
void rln_k(const float* __restrict__ x, const float* __restrict__ y,
           const float* __restrict__ g, const float* __restrict__ bta,
           float* __restrict__ out, bf16* __restrict__ oh, bf16* __restrict__ ol)
{
    int row = blockIdx.x;
    int tid = threadIdx.x;
    __shared__ float red[256];
    float v[4];
    float s = 0.f, ss = 0.f;
    #pragma unroll
    for (int l = 0; l < 4; l++) {
        size_t idx = (size_t)row*Dc + tid + l*256;
        float val = x[idx] + y[idx];
        v[l] = val; s += val; ss += val*val;
    }
    red[tid] = s; __syncthreads();
    for (int st = 128; st > 0; st >>= 1) { if (tid < st) red[tid] += red[tid+st]; __syncthreads(); }
    float mean = red[0] * (1.f/Dc); __syncthreads();
    red[tid] = ss; __syncthreads();
    for (int st = 128; st > 0; st >>= 1) { if (tid < st) red[tid] += red[tid+st]; __syncthreads(); }
    float var = red[0] * (1.f/Dc) - mean*mean;
    float inv = rsqrtf(var + 1e-5f);
    #pragma unroll
    for (int l = 0; l < 4; l++) {
        int c = tid + l*256;
        float o = (v[l] - mean) * inv * g[c] + bta[c];
        out[(size_t)row*Dc + c] = o;
        if (OBF) {
            bf16 hh, ll; split1(o, hh, ll);
            oh[(size_t)row*Dc + c] = hh;
            ol[(size_t)row*Dc + c] = ll;
        }
    }
}

// ---------------- router ----------------
__global__ void zero_cnt(int* cnt) { if (threadIdx.x < NEc) cnt[threadIdx.x] = 0; }

__global__ __launch_bounds__(256)
void router_k(const float* __restrict__ h2, const float* __restrict__ Wg,
              float* __restrict__ gate, int* __restrict__ cnt, int* __restrict__ idxlist)
{
    int warp = (blockIdx.x * blockDim.x + threadIdx.x) >> 5;
    int lane = threadIdx.x & 31;
    if (warp >= Tc) return;
    const float* hrow = h2 + (size_t)warp * Dc;
    float logit[NEc];
    #pragma unroll
    for (int e = 0; e < NEc; e++) {
        float p = 0.f;
        for (int d = lane; d < Dc; d += 32) p += hrow[d] * Wg[d*NEc + e];
        #pragma unroll
        for (int off = 16; off > 0; off >>= 1) p += __shfl_xor_sync(0xFFFFFFFFu, p, off);
        logit[e] = p;
    }
    float m = logit[0]; int am = 0;
    #pragma unroll
    for (int e = 1; e < NEc; e++) if (logit[e] > m) { m = logit[e]; am = e; }
    float sum = 0.f;
    #pragma unroll
    for (int e = 0; e < NEc; e++) sum += expf(logit[e] - m);
    if (lane == 0) {
        gate[warp] = 1.f / sum;
        int pos = atomicAdd(&cnt[am], 1);
        idxlist[am*Tc + pos] = warp;
    }
}

// ---------------- launch ----------------
extern "C" void kernel_launch(void* const* d_in, const int* in_sizes, int n_in,
                              void* d_out, int out_size)
{
    const float* x    = (const float*)d_in[0];
    const float* Wqkv = (const float*)d_in[1];
    const float* Wo   = (const float*)d_in[2];
    const float* Wr   = (const float*)d_in[3];
    const float* u_b  = (const float*)d_in[4];
    const float* v_b  = (const float*)d_in[5];
    const float* ln1g = (const float*)d_in[6];
    const float* ln1b = (const float*)d_in[7];
    const float* Wff1 = (const float*)d_in[8];
    const float* bff1 = (const float*)d_in[9];
    const float* Wff2 = (const float*)d_in[10];
    const float* bff2 = (const float*)d_in[11];
    const float* ln2g = (const float*)d_in[12];
    const float* ln2b = (const float*)d_in[13];
    const float* Wg   = (const float*)d_in[14];
    const float* We1  = (const float*)d_in[15];
    const float* be1  = (const float*)d_in[16];
    const float* We2  = (const float*)d_in[17];
    const float* be2  = (const float*)d_in[18];
    const float* ln3g = (const float*)d_in[19];
    const float* ln3b = (const float*)d_in[20];
    const float* Wout = (const float*)d_in[21];
    float* out = (float*)d_out;

    static int smemSet = 0;
    if (!smemSet) {
        cudaFuncSetAttribute(tgemm<0,0>, cudaFuncAttributeMaxDynamicSharedMemorySize, TG_SMEM);
        cudaFuncSetAttribute(tgemm<1,0>, cudaFuncAttributeMaxDynamicSharedMemorySize, TG_SMEM);
        cudaFuncSetAttribute(tgemm<2,1>, cudaFuncAttributeMaxDynamicSharedMemorySize, TG_SMEM);
        cudaFuncSetAttribute(tgemm<3,0>, cudaFuncAttributeMaxDynamicSharedMemorySize, TG_SMEM);
        cudaFuncSetAttribute(fattn,      cudaFuncAttributeMaxDynamicSharedMemorySize, FA_SMEM);
        smemSet = 1;
    }

    float *qkv, *r, *ao, *ff, *h1, *h2, *h3, *moe, *gate;
    int *cnt, *idx;
    bf16 *whi, *wlo, *peh, *pel, *xh, *xl;
    bf16 *quh, *qul, *qvh, *qvl, *kh, *kl, *vth, *vtl, *rh, *rl;
    bf16 *ctxh, *ctxl, *h1h, *h1l, *h2h, *h2l, *h3h, *h3l, *ffhh, *ffhl;

    cudaGetSymbolAddress((void**)&qkv, g_qkv);
    cudaGetSymbolAddress((void**)&r,   g_r);
    cudaGetSymbolAddress((void**)&ao,  g_ao);
    cudaGetSymbolAddress((void**)&ff,  g_ff);
    cudaGetSymbolAddress((void**)&h1,  g_h1);
    cudaGetSymbolAddress((void**)&h2,  g_h2);
    cudaGetSymbolAddress((void**)&h3,  g_h3);
    cudaGetSymbolAddress((void**)&moe, g_moe);
    cudaGetSymbolAddress((void**)&gate,g_gate);
    cudaGetSymbolAddress((void**)&cnt, g_cnt);
    cudaGetSymbolAddress((void**)&idx, g_idx);
    cudaGetSymbolAddress((void**)&whi, g_whi);
    cudaGetSymbolAddress((void**)&wlo, g_wlo);
    cudaGetSymbolAddress((void**)&peh, g_peh);
    cudaGetSymbolAddress((void**)&pel, g_pel);
    cudaGetSymbolAddress((void**)&xh,  g_xh);
    cudaGetSymbolAddress((void**)&xl,  g_xl);
    cudaGetSymbolAddress((void**)&quh, g_quh);
    cudaGetSymbolAddress((void**)&qul, g_qul);
    cudaGetSymbolAddress((void**)&qvh, g_qvh);
    cudaGetSymbolAddress((void**)&qvl, g_qvl);
    cudaGetSymbolAddress((void**)&kh,  g_kh);
    cudaGetSymbolAddress((void**)&kl,  g_kl);
    cudaGetSymbolAddress((void**)&vth, g_vth);
    cudaGetSymbolAddress((void**)&vtl, g_vtl);
    cudaGetSymbolAddress((void**)&rh,  g_rh);
    cudaGetSymbolAddress((void**)&rl,  g_rl);
    cudaGetSymbolAddress((void**)&ctxh,g_ctxh);
    cudaGetSymbolAddress((void**)&ctxl,g_ctxl);
    cudaGetSymbolAddress((void**)&h1h, g_h1h);
    cudaGetSymbolAddress((void**)&h1l, g_h1l);
    cudaGetSymbolAddress((void**)&h2h, g_h2h);
    cudaGetSymbolAddress((void**)&h2l, g_h2l);
    cudaGetSymbolAddress((void**)&h3h, g_h3h);
    cudaGetSymbolAddress((void**)&h3l, g_h3l);
    cudaGetSymbolAddress((void**)&ffhh,g_ffhh);
    cudaGetSymbolAddress((void**)&ffhl,g_ffhl);

    // weight transpose + split
    wconv<<<dim3(3072/64, 1024/64), 256>>>(Wqkv, whi+OFF_QKV,  wlo+OFF_QKV,  1024, 3072);
    wconv<<<dim3(1024/64, 1024/64), 256>>>(Wr,   whi+OFF_WR,   wlo+OFF_WR,   1024, 1024);
    wconv<<<dim3(1024/64, 1024/64), 256>>>(Wo,   whi+OFF_WO,   wlo+OFF_WO,   1024, 1024);
    wconv<<<dim3(4096/64, 1024/64), 256>>>(Wff1, whi+OFF_FF1,  wlo+OFF_FF1,  1024, 4096);
    wconv<<<dim3(1024/64, 4096/64), 256>>>(Wff2, whi+OFF_FF2,  wlo+OFF_FF2,  4096, 1024);
    wconv<<<dim3(1024/64, 1024/64), 256>>>(Wout, whi+OFF_WOUT, wlo+OFF_WOUT, 1024, 1024);
    wconv<<<dim3(4096/64, 1024/64, NEc), 256>>>(We1, whi+OFF_WE1, wlo+OFF_WE1, 1024, 4096);
    wconv<<<dim3(1024/64, 4096/64, NEc), 256>>>(We2, whi+OFF_WE2, wlo+OFF_WE2, 4096, 1024);

    pe_kernel<<<Sc, 256>>>(peh, pel);
    econv<<<Tc, 256>>>(x, xh, xl);

    // projections
    tgemm<0,0><<<dim3(3072/128, Tc/128), 256, TG_SMEM>>>(xh, xl, whi+OFF_QKV, wlo+OFF_QKV,
        qkv, nullptr, nullptr, Tc, 3072, 1024, nullptr, nullptr, nullptr, nullptr, 0, 0);
    tgemm<0,0><<<dim3(1024/128, Sc/128), 256, TG_SMEM>>>(peh, pel, whi+OFF_WR, wlo+OFF_WR,
        r, nullptr, nullptr, Sc, 1024, 1024, nullptr, nullptr, nullptr, nullptr, 0, 0);

    // attention prep
    qprep<<<Tc, 256>>>(qkv, u_b, v_b, quh, qul, qvh, qvl, kh, kl);
    vtprep<<<dim3(Sc/32, 2, BHc), 256>>>(qkv, vth, vtl);
    rprep<<<Sc, 256>>>(r, rh, rl);

    // fused attention
    fattn<<<dim3(16, BHc), 256, FA_SMEM>>>(quh, qul, qvh, qvl, kh, kl, rh, rl,
                                           vth, vtl, ctxh, ctxl);
    tgemm<0,0><<<dim3(1024/128, Tc/128), 256, TG_SMEM>>>(ctxh, ctxl, whi+OFF_WO, wlo+OFF_WO,
        ao, nullptr, nullptr, Tc, 1024, 1024, nullptr, nullptr, nullptr, nullptr, 0, 0);
    rln_k<1><<<Tc, 256>>>(x, ao, ln1g, ln1b, h1, h1h, h1l);

    // FFN
    tgemm<2,1><<<dim3(4096/128, Tc/128), 256, TG_SMEM>>>(h1h, h1l, whi+OFF_FF1, wlo+OFF_FF1,
        nullptr, ffhh, ffhl, Tc, 4096, 1024, bff1, nullptr, nullptr, nullptr, 0, 0);
    tgemm<1,0><<<dim3(1024/128, Tc/128), 256, TG_SMEM>>>(ffhh, ffhl, whi+OFF_FF2, wlo+OFF_FF2,
        ff, nullptr, nullptr, Tc, 1024, 4096, bff2, nullptr, nullptr, nullptr, 0, 0);
    rln_k<1><<<Tc, 256>>>(h1, ff, ln2g, ln2b, h2, h2h, h2l);

    // MoE
    zero_cnt<<<1, 32>>>(cnt);
    router_k<<<Tc/8, 256>>>(h2, Wg, gate, cnt, idx);
    tgemm<2,1><<<dim3(4096/128, Tc/128, NEc), 256, TG_SMEM>>>(
        h2h, h2l, whi+OFF_WE1, wlo+OFF_WE1,
        nullptr, ffhh, ffhl, Tc, 4096, 1024, be1, nullptr, idx, cnt,
        (size_t)FFc*Dc, FFc);
    tgemm<3,0><<<dim3(1024/128, Tc/128, NEc), 256, TG_SMEM>>>(
        ffhh, ffhl, whi+OFF_WE2, wlo+OFF_WE2,
        moe, nullptr, nullptr, Tc, 1024, 4096, be2, gate, idx, cnt,
        (size_t)Dc*FFc, Dc);
    rln_k<1><<<Tc, 256>>>(h2, moe, ln3g, ln3b, h3, h3h, h3l);

    // output projection
    tgemm<0,0><<<dim3(1024/128, Tc/128), 256, TG_SMEM>>>(h3h, h3l, whi+OFF_WOUT, wlo+OFF_WOUT,
        out, nullptr, nullptr, Tc, 1024, 1024, nullptr, nullptr, nullptr, nullptr, 0, 0);
}